// round 8
// baseline (speedup 1.0000x reference)
#include <cuda_runtime.h>
#include <cuda_fp16.h>
#include <cstdint>
#include <cstddef>

// ---------------------------------------------------------------------------
// TRecTransformer: linear-attention encoder/decoder.
// GEMMs: plain fp16 mma.sync m16n8k16 (fp32 accum). QKV projections batched
// into one wide GEMM per attention block (column-routed epilogue).
// ---------------------------------------------------------------------------

#define NTOK   16384
#define DMODEL 512
#define DFF    2048
#define LSEQ   4096
#define SCH    16

#define SZ ((size_t)NTOK * DMODEL)        // 8,388,608 elements

// ---- scratch layout (BYTE offsets) ----
#define B_H     ((size_t)0)
#define B_Z     (B_H   + SZ*4)
#define B_O     (B_Z   + SZ*4)
#define B_TMP   (B_O   + SZ*4)
#define B_Q     (B_TMP + SZ*4)
#define B_K     (B_Q   + SZ*4)
#define B_V     (B_K   + SZ*4)
#define B_PKV   (B_V   + SZ*4)
#define B_PKS   (B_PKV + (size_t)SCH*32*4096*4)
#define B_KVB   (B_PKS + (size_t)SCH*32*64*4)
#define B_KSB   (B_KVB + (size_t)32*4096*4)
// fp16 activations (single-rounded)
#define B_HH    (B_KSB + (size_t)32*64*4)
#define B_ZH    (B_HH  + SZ*2)
#define B_OH    (B_ZH  + SZ*2)
#define B_ATH   (B_OH  + SZ*2)
#define B_FH    (B_ATH + SZ*2)            // NTOK*DFF halves
// fp16 weights (single-rounded, transposed to [N,K])
#define B_WHA   (B_FH  + SZ*8)            // 48 x 512x512
#define B_WHF1  (B_WHA + (size_t)48*262144*2)   // 8 x [2048,512]
#define B_WHF2  (B_WHF1 + (size_t)8*1048576*2)  // 8 x [512,2048]
#define TOTAL_B (B_WHF2 + (size_t)8*1048576*2)

__device__ __align__(1024) unsigned char g_scratch[TOTAL_B];

typedef __half fp16;

// ---------------------------------------------------------------------------
// helpers
// ---------------------------------------------------------------------------
__device__ __forceinline__ uint32_t smem_u32(const void* p) {
    uint32_t a;
    asm("{ .reg .u64 t; cvta.to.shared.u64 t, %1; cvt.u32.u64 %0, t; }" : "=r"(a) : "l"(p));
    return a;
}
__device__ __forceinline__ void ldsm4(uint32_t* r, uint32_t addr) {
    asm volatile("ldmatrix.sync.aligned.m8n8.x4.shared.b16 {%0,%1,%2,%3}, [%4];"
        : "=r"(r[0]), "=r"(r[1]), "=r"(r[2]), "=r"(r[3]) : "r"(addr));
}
__device__ __forceinline__ void mma_f16(float* c, const uint32_t* a, const uint32_t* b) {
    asm volatile(
        "mma.sync.aligned.m16n8k16.row.col.f32.f16.f16.f32 "
        "{%0,%1,%2,%3}, {%4,%5,%6,%7}, {%8,%9}, {%0,%1,%2,%3};"
        : "+f"(c[0]), "+f"(c[1]), "+f"(c[2]), "+f"(c[3])
        : "r"(a[0]), "r"(a[1]), "r"(a[2]), "r"(a[3]), "r"(b[0]), "r"(b[1]));
}
__device__ __forceinline__ void cp16(uint32_t d, const void* s) {
    asm volatile("cp.async.cg.shared.global [%0], [%1], 16;" :: "r"(d), "l"(s));
}
__device__ __forceinline__ void cp_commit() { asm volatile("cp.async.commit_group;" ::: "memory"); }
__device__ __forceinline__ void cp_wait1()  { asm volatile("cp.async.wait_group 1;" ::: "memory"); }
__device__ __forceinline__ void cp_wait0()  { asm volatile("cp.async.wait_group 0;" ::: "memory"); }

// ---------------------------------------------------------------------------
// shared GEMM skeleton pieces (128x128 tile, Kc=32, 256 threads, 3 stages)
// ---------------------------------------------------------------------------
#define ROWB 80
#define MATB 10240
#define STGB 20480
#define SMEM_DYN (3 * STGB)

#define GEMM_PROLOGUE()                                                        \
    extern __shared__ char smc[];                                              \
    const uint32_t smB = smem_u32(smc);                                        \
    const int tid = threadIdx.x, lane = tid & 31, wid = tid >> 5;              \
    const int row0 = blockIdx.y * 128, col0 = blockIdx.x * 128;                \
    const int wm = wid & 1, wn = wid >> 1;                                     \
    float acc[4][4][4];                                                        \
    _Pragma("unroll")                                                          \
    for (int i = 0; i < 4; i++)                                                \
        _Pragma("unroll")                                                      \
        for (int j = 0; j < 4; j++)                                            \
            _Pragma("unroll")                                                  \
            for (int e = 0; e < 4; e++) acc[i][j][e] = 0.f;                    \
    const uint32_t aoff = (uint32_t)((wm * 64 + (lane & 7) + ((lane >> 3) & 1) * 8) * ROWB \
                                     + (lane >> 4) * 16);                      \
    const uint32_t boff = (uint32_t)((wn * 32 + (lane >> 4) * 8 + (lane & 7)) * ROWB \
                                     + ((lane >> 3) & 1) * 16);                \
    const int NC = K / 32;                                                     \
    const int pr = tid >> 2;                                                   \
    const int pb = (tid & 3) * 16;                                             \
    auto loadst = [&](int c, int s) {                                          \
        const int k0 = c * 32;                                                 \
        const uint32_t st = smB + (uint32_t)s * STGB;                          \
        _Pragma("unroll")                                                      \
        for (int m = 0; m < 2; m++) {                                          \
            const fp16* g = (m == 0) ? A : B;                                  \
            const int rb = (m == 0) ? row0 : col0;                             \
            _Pragma("unroll")                                                  \
            for (int hf = 0; hf < 2; hf++) {                                   \
                const int r = hf * 64 + pr;                                    \
                cp16(st + m * MATB + r * ROWB + pb,                            \
                     (const char*)(g + (size_t)(rb + r) * K + k0) + pb);       \
            }                                                                  \
        }                                                                      \
    };                                                                         \
    auto compute = [&](int s) {                                                \
        const uint32_t base = smB + (uint32_t)s * STGB;                        \
        _Pragma("unroll")                                                      \
        for (int ks = 0; ks < 2; ks++) {                                       \
            uint32_t ar[4][4], br[4][2];                                       \
            _Pragma("unroll")                                                  \
            for (int mi = 0; mi < 4; mi++)                                     \
                ldsm4(ar[mi], base + aoff + mi * 1280 + ks * 32);              \
            _Pragma("unroll")                                                  \
            for (int j = 0; j < 2; j++) {                                      \
                uint32_t t[4];                                                 \
                ldsm4(t, base + MATB + boff + j * 1280 + ks * 32);             \
                br[2 * j][0] = t[0]; br[2 * j][1] = t[1];                      \
                br[2 * j + 1][0] = t[2]; br[2 * j + 1][1] = t[3];              \
            }                                                                  \
            _Pragma("unroll")                                                  \
            for (int mi = 0; mi < 4; mi++)                                     \
                _Pragma("unroll")                                              \
                for (int ni = 0; ni < 4; ni++) mma_f16(acc[mi][ni], ar[mi], br[ni]); \
        }                                                                      \
    };                                                                         \
    loadst(0, 0); cp_commit();                                                 \
    loadst(1, 1); cp_commit();                                                 \
    for (int c = 0; c < NC; c++) {                                             \
        if (c + 1 < NC) cp_wait1(); else cp_wait0();                           \
        __syncthreads();                                                       \
        compute(c % 3);                                                        \
        if (c + 2 < NC) { loadst(c + 2, (c + 2) % 3); cp_commit(); }           \
    }                                                                          \
    const int gm0 = row0 + wm * 64;                                            \
    const int gn0 = col0 + wn * 32;

// ---------------------------------------------------------------------------
// standard GEMM: single output buffer. ACT: 0 none, 1 relu, 2 phi.
// OUTBF: 0 -> fp32 C, 1 -> fp16 Ch.
// ---------------------------------------------------------------------------
template<int ACT, int OUTBF>
__global__ __launch_bounds__(256) void gemm_tc(
    const fp16* __restrict__ A, const fp16* __restrict__ B,
    const float* __restrict__ bias,
    float* __restrict__ C, fp16* __restrict__ Ch,
    int M, int N, int K)
{
    GEMM_PROLOGUE();
    #pragma unroll
    for (int ni = 0; ni < 4; ni++) {
        const int cn = gn0 + ni * 8 + (lane & 3) * 2;
        const float b0 = bias[cn], b1 = bias[cn + 1];
        #pragma unroll
        for (int mi = 0; mi < 4; mi++) {
            const int rm = gm0 + mi * 16 + (lane >> 2);
            float t0 = acc[mi][ni][0] + b0;
            float t1 = acc[mi][ni][1] + b1;
            float t2 = acc[mi][ni][2] + b0;
            float t3 = acc[mi][ni][3] + b1;
            if (ACT == 1) {
                t0 = fmaxf(t0, 0.f); t1 = fmaxf(t1, 0.f);
                t2 = fmaxf(t2, 0.f); t3 = fmaxf(t3, 0.f);
            }
            if (ACT == 2) {
                t0 = t0 > 0.f ? t0 + 1.f : __expf(t0);
                t1 = t1 > 0.f ? t1 + 1.f : __expf(t1);
                t2 = t2 > 0.f ? t2 + 1.f : __expf(t2);
                t3 = t3 > 0.f ? t3 + 1.f : __expf(t3);
            }
            if (OUTBF == 0) {
                float2 v0; v0.x = t0; v0.y = t1;
                float2 v1; v1.x = t2; v1.y = t3;
                *(float2*)&C[(size_t)rm * N + cn]       = v0;
                *(float2*)&C[(size_t)(rm + 8) * N + cn] = v1;
            } else {
                __half2 hp;
                hp.x = __float2half_rn(t0); hp.y = __float2half_rn(t1);
                *(__half2*)&Ch[(size_t)rm * N + cn] = hp;
                hp.x = __float2half_rn(t2); hp.y = __float2half_rn(t3);
                *(__half2*)&Ch[(size_t)(rm + 8) * N + cn] = hp;
            }
        }
    }
}

// ---------------------------------------------------------------------------
// fused projection GEMM: columns routed to up-to-3 [M,512] buffers
// (buffer = col >> 9, inner col = col & 511). phi applied for col < phi_lim.
// ---------------------------------------------------------------------------
__global__ __launch_bounds__(256) void gemm_qkv(
    const fp16* __restrict__ A, const fp16* __restrict__ B,
    const float* __restrict__ bias,
    float* __restrict__ C0, float* __restrict__ C1, float* __restrict__ C2,
    int phi_lim, int M, int N, int K)
{
    GEMM_PROLOGUE();
    #pragma unroll
    for (int ni = 0; ni < 4; ni++) {
        const int cn = gn0 + ni * 8 + (lane & 3) * 2;
        const float b0 = bias[cn], b1 = bias[cn + 1];
        const int bi = cn >> 9;
        float* dst = (bi == 0) ? C0 : (bi == 1) ? C1 : C2;
        const int cc = cn & 511;
        const bool phi = cn < phi_lim;
        #pragma unroll
        for (int mi = 0; mi < 4; mi++) {
            const int rm = gm0 + mi * 16 + (lane >> 2);
            float t0 = acc[mi][ni][0] + b0;
            float t1 = acc[mi][ni][1] + b1;
            float t2 = acc[mi][ni][2] + b0;
            float t3 = acc[mi][ni][3] + b1;
            if (phi) {
                t0 = t0 > 0.f ? t0 + 1.f : __expf(t0);
                t1 = t1 > 0.f ? t1 + 1.f : __expf(t1);
                t2 = t2 > 0.f ? t2 + 1.f : __expf(t2);
                t3 = t3 > 0.f ? t3 + 1.f : __expf(t3);
            }
            float2 v0; v0.x = t0; v0.y = t1;
            float2 v1; v1.x = t2; v1.y = t3;
            *(float2*)&dst[(size_t)rm * 512 + cc]       = v0;
            *(float2*)&dst[(size_t)(rm + 8) * 512 + cc] = v1;
        }
    }
}

// ---------------------------------------------------------------------------
// fused weight transpose + fp16 round: W[K,N] fp32 -> Wh [N,K] fp16
// ---------------------------------------------------------------------------
__global__ __launch_bounds__(256) void transpose_w16(
    const float* __restrict__ W, fp16* __restrict__ Wh, int K, int N)
{
    __shared__ float t[32][33];
    const size_t mo = (size_t)blockIdx.z * K * N;
    const float* Wm = W + mo;
    const int n0 = blockIdx.x * 32, k0 = blockIdx.y * 32;
    const int tx = threadIdx.x & 31, ty = threadIdx.x >> 5;
    #pragma unroll
    for (int i = 0; i < 32; i += 8)
        t[ty + i][tx] = Wm[(size_t)(k0 + ty + i) * N + n0 + tx];
    __syncthreads();
    #pragma unroll
    for (int i = 0; i < 32; i += 8)
        Wh[mo + (size_t)(n0 + ty + i) * K + k0 + tx] = __float2half_rn(t[tx][ty + i]);
}

// ---------------------------------------------------------------------------
// linear-attention kernels
// ---------------------------------------------------------------------------
__global__ __launch_bounds__(256) void kv_partial(
    const float* __restrict__ Kt, const float* __restrict__ Vt,
    float* __restrict__ pkv, float* __restrict__ pks)
{
    const int bh = blockIdx.x, ch = blockIdx.y;
    const int b = bh >> 3, h = bh & 7;
    const int tid = threadIdx.x;
    __shared__ float Ks[4][64], Vs[4][64];

    float acc[16];
    #pragma unroll
    for (int j = 0; j < 16; j++) acc[j] = 0.f;
    float ksa = 0.f;

    const int s0 = ch * (LSEQ / SCH);
    const size_t base = ((size_t)b * LSEQ) * DMODEL + h * 64;
    const int r = tid >> 6, d = tid & 63;

    for (int s = s0; s < s0 + LSEQ / SCH; s += 4) {
        const size_t off = base + (size_t)(s + r) * DMODEL + d;
        Ks[r][d] = Kt[off];
        Vs[r][d] = Vt[off];
        __syncthreads();
        #pragma unroll
        for (int rr = 0; rr < 4; rr++) {
            #pragma unroll
            for (int j = 0; j < 16; j++) {
                const int flat = j * 256 + tid;
                acc[j] = fmaf(Ks[rr][flat >> 6], Vs[rr][flat & 63], acc[j]);
            }
            if (tid < 64) ksa += Ks[rr][tid];
        }
        __syncthreads();
    }
    float* o = pkv + ((size_t)ch * 32 + bh) * 4096;
    #pragma unroll
    for (int j = 0; j < 16; j++) o[j * 256 + tid] = acc[j];
    if (tid < 64) pks[((size_t)ch * 32 + bh) * 64 + tid] = ksa;
}

__global__ __launch_bounds__(256) void kv_reduce(
    const float* __restrict__ pkv, const float* __restrict__ pks,
    float* __restrict__ kv, float* __restrict__ ks)
{
    const int bh = blockIdx.x, tid = threadIdx.x;
    for (int e = tid; e < 4096; e += 256) {
        float s = 0.f;
        #pragma unroll
        for (int c = 0; c < SCH; c++) s += pkv[((size_t)c * 32 + bh) * 4096 + e];
        kv[(size_t)bh * 4096 + e] = s;
    }
    if (tid < 64) {
        float s = 0.f;
        #pragma unroll
        for (int c = 0; c < SCH; c++) s += pks[((size_t)c * 32 + bh) * 64 + tid];
        ks[bh * 64 + tid] = s;
    }
}

__global__ __launch_bounds__(256) void attn_out(
    const float* __restrict__ Q, const float* __restrict__ kv,
    const float* __restrict__ ksum, fp16* __restrict__ Oh)
{
    const int bh = blockIdx.x, b = bh >> 3, h = bh & 7;
    __shared__ float kvs[64][64];
    __shared__ float kss[64];
    const int tid = threadIdx.x;
    for (int e = tid; e < 4096; e += 256) kvs[e >> 6][e & 63] = kv[(size_t)bh * 4096 + e];
    if (tid < 64) kss[tid] = ksum[bh * 64 + tid];
    __syncthreads();

    const int warp = tid >> 5, lane = tid & 31;
    const int tpb = LSEQ / gridDim.y;
    const int l0 = blockIdx.y * tpb;

    for (int l = l0 + warp; l < l0 + tpb; l += 8) {
        const float* q = Q + ((size_t)(b * LSEQ + l)) * DMODEL + h * 64;
        const float q0 = q[lane], q1 = q[lane + 32];
        float zd = q0 * kss[lane] + q1 * kss[lane + 32];
        #pragma unroll
        for (int o = 16; o > 0; o >>= 1) zd += __shfl_xor_sync(0xffffffffu, zd, o);
        const float z = 1.f / (zd + 1e-6f);

        float a0 = 0.f, a1 = 0.f;
        #pragma unroll
        for (int dd = 0; dd < 32; dd++) {
            const float qd = __shfl_sync(0xffffffffu, q0, dd);
            a0 = fmaf(qd, kvs[dd][lane],      a0);
            a1 = fmaf(qd, kvs[dd][lane + 32], a1);
        }
        #pragma unroll
        for (int dd = 0; dd < 32; dd++) {
            const float qd = __shfl_sync(0xffffffffu, q1, dd);
            a0 = fmaf(qd, kvs[dd + 32][lane],      a0);
            a1 = fmaf(qd, kvs[dd + 32][lane + 32], a1);
        }
        const size_t op = ((size_t)(b * LSEQ + l)) * DMODEL + h * 64;
        Oh[op + lane]      = __float2half_rn(a0 * z);
        Oh[op + lane + 32] = __float2half_rn(a1 * z);
    }
}

__global__ __launch_bounds__(128) void ln_kernel(
    const float* __restrict__ X, const float* __restrict__ R,
    const float* __restrict__ gb, float* __restrict__ Y,
    fp16* __restrict__ Yh)
{
    const int t = blockIdx.x, tid = threadIdx.x;
    const float* x = X + (size_t)t * DMODEL;
    float v[4];
    float s = 0.f;
    #pragma unroll
    for (int i = 0; i < 4; i++) {
        float val = x[tid + i * 128];
        if (R) val += R[(size_t)t * DMODEL + tid + i * 128];
        v[i] = val; s += val;
    }
    __shared__ float red[4];
    #pragma unroll
    for (int o = 16; o > 0; o >>= 1) s += __shfl_xor_sync(0xffffffffu, s, o);
    if ((tid & 31) == 0) red[tid >> 5] = s;
    __syncthreads();
    const float mu = (red[0] + red[1] + red[2] + red[3]) * (1.f / DMODEL);
    float qq = 0.f;
    #pragma unroll
    for (int i = 0; i < 4; i++) { const float dd = v[i] - mu; qq += dd * dd; }
    #pragma unroll
    for (int o = 16; o > 0; o >>= 1) qq += __shfl_xor_sync(0xffffffffu, qq, o);
    __syncthreads();
    if ((tid & 31) == 0) red[tid >> 5] = qq;
    __syncthreads();
    const float var = (red[0] + red[1] + red[2] + red[3]) * (1.f / DMODEL);
    const float rstd = rsqrtf(var + 1e-5f);
    #pragma unroll
    for (int i = 0; i < 4; i++) {
        const int j = tid + i * 128;
        const float out = (v[i] - mu) * rstd * gb[j] + gb[DMODEL + j];
        Y[(size_t)t * DMODEL + j] = out;
        if (Yh) Yh[(size_t)t * DMODEL + j] = __float2half_rn(out);
    }
}

__global__ void embed_kernel(
    const float* __restrict__ x, const float* __restrict__ pe,
    const float* __restrict__ ew, const float* __restrict__ eb,
    float* __restrict__ h, fp16* __restrict__ hh)
{
    const size_t idx = (size_t)blockIdx.x * blockDim.x + threadIdx.x;
    const int tok = (int)(idx >> 9);
    const int j   = (int)(idx & 511);
    const int l   = tok & (LSEQ - 1);
    float val;
    if (j < 256) val = x[(size_t)tok * 2] * ew[j] + x[(size_t)tok * 2 + 1] * ew[256 + j] + eb[j];
    else         val = pe[(size_t)l * 256 + (j - 256)];
    h[idx] = val;
    hh[idx] = __float2half_rn(val);
}

__global__ void dec_init_kernel(const float* __restrict__ ope, float* __restrict__ o,
                                fp16* __restrict__ oh)
{
    const size_t idx = (size_t)blockIdx.x * blockDim.x + threadIdx.x;
    const size_t tok = idx >> 9;
    const float val = ope[((tok & (LSEQ - 1)) << 9) | (idx & 511)];
    o[idx] = val;
    oh[idx] = __float2half_rn(val);
}

__global__ void pred_kernel(
    const float* __restrict__ Xf, const float* __restrict__ pw,
    const float* __restrict__ pb, float* __restrict__ out)
{
    const int gw = (int)(((size_t)blockIdx.x * blockDim.x + threadIdx.x) >> 5);
    const int lane = threadIdx.x & 31;
    if (gw >= NTOK) return;
    const float* xr = Xf + (size_t)gw * DMODEL;
    float a0 = 0.f, a1 = 0.f;
    #pragma unroll 4
    for (int j = lane; j < DMODEL; j += 32) {
        const float v = xr[j];
        a0 = fmaf(v, pw[2 * j],     a0);
        a1 = fmaf(v, pw[2 * j + 1], a1);
    }
    #pragma unroll
    for (int o = 16; o > 0; o >>= 1) {
        a0 += __shfl_xor_sync(0xffffffffu, a0, o);
        a1 += __shfl_xor_sync(0xffffffffu, a1, o);
    }
    if (lane == 0) { out[2 * gw] = a0 + pb[0]; out[2 * gw + 1] = a1 + pb[1]; }
}

// ---------------------------------------------------------------------------
// Host orchestration
// ---------------------------------------------------------------------------
struct Ptrs {
    float *h, *z, *o, *tmp, *q, *k, *v, *pkv, *pks, *kv, *ks;
    fp16 *hh, *zh, *oh, *ath, *fh;
    fp16 *wha, *whf1, *whf2;
};

static void gemm00(const fp16* a, const fp16* b, const float* bias,
                   float* C, int M, int N, int K) {
    gemm_tc<0,0><<<dim3(N/128, M/128), 256, SMEM_DYN>>>(a, b, bias, C, nullptr, M, N, K);
}
static void gemm11(const fp16* a, const fp16* b, const float* bias,
                   fp16* Ch, int M, int N, int K) {
    gemm_tc<1,1><<<dim3(N/128, M/128), 256, SMEM_DYN>>>(a, b, bias, nullptr, Ch, M, N, K);
}

// self-attention: fused QKV (N=1536, phi on cols < 1024)
static void attention_self(const fp16* xh, const fp16* wh, const float* b, const Ptrs& P)
{
    gemm_qkv<<<dim3(1536/128, NTOK/128), 256, SMEM_DYN>>>(
        xh, wh, b, P.q, P.k, P.v, 1024, NTOK, 1536, DMODEL);
    kv_partial<<<dim3(32, SCH), 256>>>(P.k, P.v, P.pkv, P.pks);
    kv_reduce<<<32, 256>>>(P.pkv, P.pks, P.kv, P.ks);
    attn_out<<<dim3(32, 32), 256>>>(P.q, P.kv, P.ks, P.ath);
    gemm00(P.ath, wh + (size_t)3 * DMODEL * DMODEL, b + 3 * DMODEL,
           P.tmp, NTOK, DMODEL, DMODEL);
}

// cross-attention: Q from xq (phi), fused KV from xkv (N=1024, phi on cols < 512)
static void attention_cross(const fp16* xqh, const fp16* xkh,
                            const fp16* wh, const float* b, const Ptrs& P)
{
    const size_t WS = (size_t)DMODEL * DMODEL;
    gemm_qkv<<<dim3(512/128, NTOK/128), 256, SMEM_DYN>>>(
        xqh, wh, b, P.q, nullptr, nullptr, 512, NTOK, 512, DMODEL);
    gemm_qkv<<<dim3(1024/128, NTOK/128), 256, SMEM_DYN>>>(
        xkh, wh + 1 * WS, b + 1 * DMODEL, P.k, P.v, nullptr, 512, NTOK, 1024, DMODEL);
    kv_partial<<<dim3(32, SCH), 256>>>(P.k, P.v, P.pkv, P.pks);
    kv_reduce<<<32, 256>>>(P.pkv, P.pks, P.kv, P.ks);
    attn_out<<<dim3(32, 32), 256>>>(P.q, P.kv, P.ks, P.ath);
    gemm00(P.ath, wh + 3 * WS, b + 3 * DMODEL, P.tmp, NTOK, DMODEL, DMODEL);
}

extern "C" void kernel_launch(void* const* d_in, const int* in_sizes, int n_in,
                              void* d_out, int out_size)
{
    const float* x            = (const float*)d_in[0];
    const float* out_pos_emb  = (const float*)d_in[1];
    const float* pe_input     = (const float*)d_in[2];
    const float* emb_w        = (const float*)d_in[3];
    const float* emb_b        = (const float*)d_in[4];
    const float* enc_attn_w   = (const float*)d_in[5];
    const float* enc_attn_b   = (const float*)d_in[6];
    const float* enc_ln       = (const float*)d_in[7];
    const float* enc_ff_w1    = (const float*)d_in[8];
    const float* enc_ff_b1    = (const float*)d_in[9];
    const float* enc_ff_w2    = (const float*)d_in[10];
    const float* enc_ff_b2    = (const float*)d_in[11];
    const float* enc_final_ln = (const float*)d_in[12];
    const float* dec_self_w   = (const float*)d_in[13];
    const float* dec_self_b   = (const float*)d_in[14];
    const float* dec_cross_w  = (const float*)d_in[15];
    const float* dec_cross_b  = (const float*)d_in[16];
    const float* dec_ln       = (const float*)d_in[17];
    const float* dec_ff_w1    = (const float*)d_in[18];
    const float* dec_ff_b1    = (const float*)d_in[19];
    const float* dec_ff_w2    = (const float*)d_in[20];
    const float* dec_ff_b2    = (const float*)d_in[21];
    const float* dec_final_ln = (const float*)d_in[22];
    const float* pred_w       = (const float*)d_in[23];
    const float* pred_b       = (const float*)d_in[24];

    cudaFuncSetAttribute(gemm_tc<0,0>, cudaFuncAttributeMaxDynamicSharedMemorySize, SMEM_DYN);
    cudaFuncSetAttribute(gemm_tc<1,1>, cudaFuncAttributeMaxDynamicSharedMemorySize, SMEM_DYN);
    cudaFuncSetAttribute(gemm_qkv,     cudaFuncAttributeMaxDynamicSharedMemorySize, SMEM_DYN);

    unsigned char* S = nullptr;
    cudaGetSymbolAddress((void**)&S, g_scratch);

    Ptrs P;
    P.h   = (float*)(S + B_H);   P.z   = (float*)(S + B_Z);   P.o  = (float*)(S + B_O);
    P.tmp = (float*)(S + B_TMP); P.q   = (float*)(S + B_Q);   P.k  = (float*)(S + B_K);
    P.v   = (float*)(S + B_V);   P.pkv = (float*)(S + B_PKV); P.pks = (float*)(S + B_PKS);
    P.kv  = (float*)(S + B_KVB); P.ks  = (float*)(S + B_KSB);
    P.hh  = (fp16*)(S + B_HH);   P.zh  = (fp16*)(S + B_ZH);
    P.oh  = (fp16*)(S + B_OH);   P.ath = (fp16*)(S + B_ATH);
    P.fh  = (fp16*)(S + B_FH);
    P.wha = (fp16*)(S + B_WHA);
    P.whf1 = (fp16*)(S + B_WHF1);
    P.whf2 = (fp16*)(S + B_WHF2);

    // ---- transpose + fp16-round all weights ----
    transpose_w16<<<dim3(16, 16, 16), 256>>>(enc_attn_w,  P.wha,                     512, 512);
    transpose_w16<<<dim3(16, 16, 16), 256>>>(dec_self_w,  P.wha + (size_t)16*262144, 512, 512);
    transpose_w16<<<dim3(16, 16, 16), 256>>>(dec_cross_w, P.wha + (size_t)32*262144, 512, 512);
    transpose_w16<<<dim3(64, 16, 4),  256>>>(enc_ff_w1, P.whf1,                      512, 2048);
    transpose_w16<<<dim3(64, 16, 4),  256>>>(dec_ff_w1, P.whf1 + (size_t)4*1048576,  512, 2048);
    transpose_w16<<<dim3(16, 64, 4),  256>>>(enc_ff_w2, P.whf2,                      2048, 512);
    transpose_w16<<<dim3(16, 64, 4),  256>>>(dec_ff_w2, P.whf2 + (size_t)4*1048576,  2048, 512);

    const size_t WT4 = (size_t)4 * DMODEL * DMODEL;
    const size_t W1S = (size_t)DFF * DMODEL;
    const size_t W2S = (size_t)DMODEL * DFF;

    // ---- embed ----
    embed_kernel<<<(NTOK * DMODEL) / 256, 256>>>(x, pe_input, emb_w, emb_b, P.h, P.hh);

    // ---- encoder ----
    for (int l = 0; l < 4; l++) {
        const float* ln = enc_ln + (size_t)l * 2 * 2 * DMODEL;
        attention_self(P.hh, P.wha + (size_t)l * WT4,
                       enc_attn_b + (size_t)l * 4 * DMODEL, P);
        ln_kernel<<<NTOK, 128>>>(P.h, P.tmp, ln, P.h, P.hh);
        gemm11(P.hh, P.whf1 + (size_t)l * W1S,
               enc_ff_b1 + (size_t)l * DFF, P.fh, NTOK, DFF, DMODEL);
        gemm00(P.fh, P.whf2 + (size_t)l * W2S,
               enc_ff_b2 + (size_t)l * DMODEL, P.tmp, NTOK, DMODEL, DFF);
        ln_kernel<<<NTOK, 128>>>(P.h, P.tmp, ln + 2 * DMODEL, P.h, P.hh);
    }
    ln_kernel<<<NTOK, 128>>>(P.h, nullptr, enc_final_ln, P.z, P.zh);

    // ---- decoder ----
    dec_init_kernel<<<(NTOK * DMODEL) / 256, 256>>>(out_pos_emb, P.o, P.oh);
    for (int l = 0; l < 4; l++) {
        const float* ln = dec_ln + (size_t)l * 3 * 2 * DMODEL;
        attention_self(P.oh, P.wha + (size_t)(16 + l * 4) * DMODEL * DMODEL,
                       dec_self_b + (size_t)l * 4 * DMODEL, P);
        ln_kernel<<<NTOK, 128>>>(P.o, P.tmp, ln, P.o, P.oh);
        attention_cross(P.oh, P.zh,
                        P.wha + (size_t)(32 + l * 4) * DMODEL * DMODEL,
                        dec_cross_b + (size_t)l * 4 * DMODEL, P);
        ln_kernel<<<NTOK, 128>>>(P.o, P.tmp, ln + 2 * DMODEL, P.o, P.oh);
        gemm11(P.oh, P.whf1 + (size_t)(4 + l) * W1S,
               dec_ff_b1 + (size_t)l * DFF, P.fh, NTOK, DFF, DMODEL);
        gemm00(P.fh, P.whf2 + (size_t)(4 + l) * W2S,
               dec_ff_b2 + (size_t)l * DMODEL, P.tmp, NTOK, DMODEL, DFF);
        ln_kernel<<<NTOK, 128>>>(P.o, P.tmp, ln + 4 * DMODEL, P.o, P.oh);
    }
    ln_kernel<<<NTOK, 128>>>(P.o, nullptr, dec_final_ln, P.tmp, nullptr);

    // ---- prediction head ----
    pred_kernel<<<(NTOK * 32) / 256, 256>>>(P.tmp, pred_w, pred_b, (float*)d_out);
}

// round 9
// speedup vs baseline: 1.5400x; 1.5400x over previous
#include <cuda_runtime.h>
#include <cuda_fp16.h>
#include <cstdint>
#include <cstddef>

// ---------------------------------------------------------------------------
// TRecTransformer: linear-attention encoder/decoder.
// GEMMs: plain fp16 mma.sync m16n8k16 (fp32 accum), single-destination
// epilogues (round-8 fused/routed epilogue reverted: register spills).
// Q/K/V carried as fp16 to halve attention-chain traffic.
// ---------------------------------------------------------------------------

#define NTOK   16384
#define DMODEL 512
#define DFF    2048
#define LSEQ   4096
#define SCH    16

#define SZ ((size_t)NTOK * DMODEL)        // 8,388,608 elements

// ---- scratch layout (BYTE offsets) ----
#define B_H     ((size_t)0)
#define B_Z     (B_H   + SZ*4)
#define B_O     (B_Z   + SZ*4)
#define B_TMP   (B_O   + SZ*4)
#define B_Q     (B_TMP + SZ*4)            // fp16 now (half used)
#define B_K     (B_Q   + SZ*4)
#define B_V     (B_K   + SZ*4)
#define B_PKV   (B_V   + SZ*4)
#define B_PKS   (B_PKV + (size_t)SCH*32*4096*4)
#define B_KVB   (B_PKS + (size_t)SCH*32*64*4)
#define B_KSB   (B_KVB + (size_t)32*4096*4)
// fp16 activations (single-rounded)
#define B_HH    (B_KSB + (size_t)32*64*4)
#define B_ZH    (B_HH  + SZ*2)
#define B_OH    (B_ZH  + SZ*2)
#define B_ATH   (B_OH  + SZ*2)
#define B_FH    (B_ATH + SZ*2)            // NTOK*DFF halves
// fp16 weights (single-rounded, transposed to [N,K])
#define B_WHA   (B_FH  + SZ*8)            // 48 x 512x512
#define B_WHF1  (B_WHA + (size_t)48*262144*2)   // 8 x [2048,512]
#define B_WHF2  (B_WHF1 + (size_t)8*1048576*2)  // 8 x [512,2048]
#define TOTAL_B (B_WHF2 + (size_t)8*1048576*2)

__device__ __align__(1024) unsigned char g_scratch[TOTAL_B];

typedef __half fp16;

// ---------------------------------------------------------------------------
// helpers
// ---------------------------------------------------------------------------
__device__ __forceinline__ uint32_t smem_u32(const void* p) {
    uint32_t a;
    asm("{ .reg .u64 t; cvta.to.shared.u64 t, %1; cvt.u32.u64 %0, t; }" : "=r"(a) : "l"(p));
    return a;
}
__device__ __forceinline__ void ldsm4(uint32_t* r, uint32_t addr) {
    asm volatile("ldmatrix.sync.aligned.m8n8.x4.shared.b16 {%0,%1,%2,%3}, [%4];"
        : "=r"(r[0]), "=r"(r[1]), "=r"(r[2]), "=r"(r[3]) : "r"(addr));
}
__device__ __forceinline__ void mma_f16(float* c, const uint32_t* a, const uint32_t* b) {
    asm volatile(
        "mma.sync.aligned.m16n8k16.row.col.f32.f16.f16.f32 "
        "{%0,%1,%2,%3}, {%4,%5,%6,%7}, {%8,%9}, {%0,%1,%2,%3};"
        : "+f"(c[0]), "+f"(c[1]), "+f"(c[2]), "+f"(c[3])
        : "r"(a[0]), "r"(a[1]), "r"(a[2]), "r"(a[3]), "r"(b[0]), "r"(b[1]));
}
__device__ __forceinline__ void cp16(uint32_t d, const void* s) {
    asm volatile("cp.async.cg.shared.global [%0], [%1], 16;" :: "r"(d), "l"(s));
}
__device__ __forceinline__ void cp_commit() { asm volatile("cp.async.commit_group;" ::: "memory"); }
__device__ __forceinline__ void cp_wait1()  { asm volatile("cp.async.wait_group 1;" ::: "memory"); }
__device__ __forceinline__ void cp_wait0()  { asm volatile("cp.async.wait_group 0;" ::: "memory"); }

// ---------------------------------------------------------------------------
// GEMM: C[M,N] = act(A[M,K] @ W[N,K]^T + bias). fp16 mma.sync, fp32 accum.
// 128x128 tile, Kc=32, 256 threads, 3-stage cp.async pipeline,
// 2 smem matrices per stage (A, W).
// ACT: 0 none, 1 relu, 2 phi=elu+1.  OUTBF: 0 -> fp32 C, 1 -> fp16 Ch.
// ---------------------------------------------------------------------------
#define ROWB 80
#define MATB 10240
#define STGB 20480
#define SMEM_DYN (3 * STGB)

template<int ACT, int OUTBF>
__global__ __launch_bounds__(256) void gemm_tc(
    const fp16* __restrict__ A, const fp16* __restrict__ B,
    const float* __restrict__ bias,
    float* __restrict__ C, fp16* __restrict__ Ch,
    int M, int N, int K)
{
    extern __shared__ char smc[];
    const uint32_t smB = smem_u32(smc);

    const int tid = threadIdx.x, lane = tid & 31, wid = tid >> 5;
    const int row0 = blockIdx.y * 128, col0 = blockIdx.x * 128;
    const int wm = wid & 1, wn = wid >> 1;       // 2 x 4 warp grid

    float acc[4][4][4];
    #pragma unroll
    for (int i = 0; i < 4; i++)
        #pragma unroll
        for (int j = 0; j < 4; j++)
            #pragma unroll
            for (int e = 0; e < 4; e++) acc[i][j][e] = 0.f;

    const uint32_t aoff = (uint32_t)((wm * 64 + (lane & 7) + ((lane >> 3) & 1) * 8) * ROWB
                                     + (lane >> 4) * 16);
    const uint32_t boff = (uint32_t)((wn * 32 + (lane >> 4) * 8 + (lane & 7)) * ROWB
                                     + ((lane >> 3) & 1) * 16);

    const int NC = K / 32;
    const int pr = tid >> 2;             // producer row within 64-row half
    const int pb = (tid & 3) * 16;       // byte offset within 64B row chunk

    auto loadst = [&](int c, int s) {
        const int k0 = c * 32;
        const uint32_t st = smB + (uint32_t)s * STGB;
        #pragma unroll
        for (int m = 0; m < 2; m++) {
            const fp16* g = (m == 0) ? A : B;
            const int rb = (m == 0) ? row0 : col0;
            #pragma unroll
            for (int hf = 0; hf < 2; hf++) {
                const int r = hf * 64 + pr;
                cp16(st + m * MATB + r * ROWB + pb,
                     (const char*)(g + (size_t)(rb + r) * K + k0) + pb);
            }
        }
    };

    auto compute = [&](int s) {
        const uint32_t base = smB + (uint32_t)s * STGB;
        #pragma unroll
        for (int ks = 0; ks < 2; ks++) {
            uint32_t ar[4][4], br[4][2];
            #pragma unroll
            for (int mi = 0; mi < 4; mi++)
                ldsm4(ar[mi], base + aoff + mi * 1280 + ks * 32);
            #pragma unroll
            for (int j = 0; j < 2; j++) {
                uint32_t t[4];
                ldsm4(t, base + MATB + boff + j * 1280 + ks * 32);
                br[2 * j][0] = t[0]; br[2 * j][1] = t[1];
                br[2 * j + 1][0] = t[2]; br[2 * j + 1][1] = t[3];
            }
            #pragma unroll
            for (int mi = 0; mi < 4; mi++)
                #pragma unroll
                for (int ni = 0; ni < 4; ni++) mma_f16(acc[mi][ni], ar[mi], br[ni]);
        }
    };

    loadst(0, 0); cp_commit();
    loadst(1, 1); cp_commit();
    for (int c = 0; c < NC; c++) {
        if (c + 1 < NC) cp_wait1(); else cp_wait0();
        __syncthreads();
        compute(c % 3);
        if (c + 2 < NC) { loadst(c + 2, (c + 2) % 3); cp_commit(); }
    }

    // epilogue
    const int gm0 = row0 + wm * 64;
    const int gn0 = col0 + wn * 32;
    #pragma unroll
    for (int ni = 0; ni < 4; ni++) {
        const int cn = gn0 + ni * 8 + (lane & 3) * 2;
        const float b0 = bias[cn], b1 = bias[cn + 1];
        #pragma unroll
        for (int mi = 0; mi < 4; mi++) {
            const int rm = gm0 + mi * 16 + (lane >> 2);
            float t0 = acc[mi][ni][0] + b0;
            float t1 = acc[mi][ni][1] + b1;
            float t2 = acc[mi][ni][2] + b0;
            float t3 = acc[mi][ni][3] + b1;
            if (ACT == 1) {
                t0 = fmaxf(t0, 0.f); t1 = fmaxf(t1, 0.f);
                t2 = fmaxf(t2, 0.f); t3 = fmaxf(t3, 0.f);
            }
            if (ACT == 2) {
                t0 = t0 > 0.f ? t0 + 1.f : __expf(t0);
                t1 = t1 > 0.f ? t1 + 1.f : __expf(t1);
                t2 = t2 > 0.f ? t2 + 1.f : __expf(t2);
                t3 = t3 > 0.f ? t3 + 1.f : __expf(t3);
            }
            if (OUTBF == 0) {
                float2 v0; v0.x = t0; v0.y = t1;
                float2 v1; v1.x = t2; v1.y = t3;
                *(float2*)&C[(size_t)rm * N + cn]       = v0;
                *(float2*)&C[(size_t)(rm + 8) * N + cn] = v1;
            } else {
                __half2 hp;
                hp.x = __float2half_rn(t0); hp.y = __float2half_rn(t1);
                *(__half2*)&Ch[(size_t)rm * N + cn] = hp;
                hp.x = __float2half_rn(t2); hp.y = __float2half_rn(t3);
                *(__half2*)&Ch[(size_t)(rm + 8) * N + cn] = hp;
            }
        }
    }
}

// ---------------------------------------------------------------------------
// fused weight transpose + fp16 round: W[K,N] fp32 -> Wh [N,K] fp16
// ---------------------------------------------------------------------------
__global__ __launch_bounds__(256) void transpose_w16(
    const float* __restrict__ W, fp16* __restrict__ Wh, int K, int N)
{
    __shared__ float t[32][33];
    const size_t mo = (size_t)blockIdx.z * K * N;
    const float* Wm = W + mo;
    const int n0 = blockIdx.x * 32, k0 = blockIdx.y * 32;
    const int tx = threadIdx.x & 31, ty = threadIdx.x >> 5;
    #pragma unroll
    for (int i = 0; i < 32; i += 8)
        t[ty + i][tx] = Wm[(size_t)(k0 + ty + i) * N + n0 + tx];
    __syncthreads();
    #pragma unroll
    for (int i = 0; i < 32; i += 8)
        Wh[mo + (size_t)(n0 + ty + i) * K + k0 + tx] = __float2half_rn(t[tx][ty + i]);
}

// ---------------------------------------------------------------------------
// linear-attention kernels (Q/K/V now fp16; accumulate in fp32)
// ---------------------------------------------------------------------------
__global__ __launch_bounds__(256) void kv_partial(
    const fp16* __restrict__ Kt, const fp16* __restrict__ Vt,
    float* __restrict__ pkv, float* __restrict__ pks)
{
    const int bh = blockIdx.x, ch = blockIdx.y;
    const int b = bh >> 3, h = bh & 7;
    const int tid = threadIdx.x;
    __shared__ float Ks[4][64], Vs[4][64];

    float acc[16];
    #pragma unroll
    for (int j = 0; j < 16; j++) acc[j] = 0.f;
    float ksa = 0.f;

    const int s0 = ch * (LSEQ / SCH);
    const size_t base = ((size_t)b * LSEQ) * DMODEL + h * 64;
    const int r = tid >> 6, d = tid & 63;

    for (int s = s0; s < s0 + LSEQ / SCH; s += 4) {
        const size_t off = base + (size_t)(s + r) * DMODEL + d;
        Ks[r][d] = __half2float(Kt[off]);
        Vs[r][d] = __half2float(Vt[off]);
        __syncthreads();
        #pragma unroll
        for (int rr = 0; rr < 4; rr++) {
            #pragma unroll
            for (int j = 0; j < 16; j++) {
                const int flat = j * 256 + tid;
                acc[j] = fmaf(Ks[rr][flat >> 6], Vs[rr][flat & 63], acc[j]);
            }
            if (tid < 64) ksa += Ks[rr][tid];
        }
        __syncthreads();
    }
    float* o = pkv + ((size_t)ch * 32 + bh) * 4096;
    #pragma unroll
    for (int j = 0; j < 16; j++) o[j * 256 + tid] = acc[j];
    if (tid < 64) pks[((size_t)ch * 32 + bh) * 64 + tid] = ksa;
}

__global__ __launch_bounds__(256) void kv_reduce(
    const float* __restrict__ pkv, const float* __restrict__ pks,
    float* __restrict__ kv, float* __restrict__ ks)
{
    const int bh = blockIdx.x, tid = threadIdx.x;
    for (int e = tid; e < 4096; e += 256) {
        float s = 0.f;
        #pragma unroll
        for (int c = 0; c < SCH; c++) s += pkv[((size_t)c * 32 + bh) * 4096 + e];
        kv[(size_t)bh * 4096 + e] = s;
    }
    if (tid < 64) {
        float s = 0.f;
        #pragma unroll
        for (int c = 0; c < SCH; c++) s += pks[((size_t)c * 32 + bh) * 64 + tid];
        ks[bh * 64 + tid] = s;
    }
}

__global__ __launch_bounds__(256) void attn_out(
    const fp16* __restrict__ Q, const float* __restrict__ kv,
    const float* __restrict__ ksum, fp16* __restrict__ Oh)
{
    const int bh = blockIdx.x, b = bh >> 3, h = bh & 7;
    __shared__ float kvs[64][64];
    __shared__ float kss[64];
    const int tid = threadIdx.x;
    for (int e = tid; e < 4096; e += 256) kvs[e >> 6][e & 63] = kv[(size_t)bh * 4096 + e];
    if (tid < 64) kss[tid] = ksum[bh * 64 + tid];
    __syncthreads();

    const int warp = tid >> 5, lane = tid & 31;
    const int tpb = LSEQ / gridDim.y;
    const int l0 = blockIdx.y * tpb;

    for (int l = l0 + warp; l < l0 + tpb; l += 8) {
        const fp16* q = Q + ((size_t)(b * LSEQ + l)) * DMODEL + h * 64;
        const float q0 = __half2float(q[lane]), q1 = __half2float(q[lane + 32]);
        float zd = q0 * kss[lane] + q1 * kss[lane + 32];
        #pragma unroll
        for (int o = 16; o > 0; o >>= 1) zd += __shfl_xor_sync(0xffffffffu, zd, o);
        const float z = 1.f / (zd + 1e-6f);

        float a0 = 0.f, a1 = 0.f;
        #pragma unroll
        for (int dd = 0; dd < 32; dd++) {
            const float qd = __shfl_sync(0xffffffffu, q0, dd);
            a0 = fmaf(qd, kvs[dd][lane],      a0);
            a1 = fmaf(qd, kvs[dd][lane + 32], a1);
        }
        #pragma unroll
        for (int dd = 0; dd < 32; dd++) {
            const float qd = __shfl_sync(0xffffffffu, q1, dd);
            a0 = fmaf(qd, kvs[dd + 32][lane],      a0);
            a1 = fmaf(qd, kvs[dd + 32][lane + 32], a1);
        }
        const size_t op = ((size_t)(b * LSEQ + l)) * DMODEL + h * 64;
        Oh[op + lane]      = __float2half_rn(a0 * z);
        Oh[op + lane + 32] = __float2half_rn(a1 * z);
    }
}

__global__ __launch_bounds__(128) void ln_kernel(
    const float* __restrict__ X, const float* __restrict__ R,
    const float* __restrict__ gb, float* __restrict__ Y,
    fp16* __restrict__ Yh)
{
    const int t = blockIdx.x, tid = threadIdx.x;
    const float* x = X + (size_t)t * DMODEL;
    float v[4];
    float s = 0.f;
    #pragma unroll
    for (int i = 0; i < 4; i++) {
        float val = x[tid + i * 128];
        if (R) val += R[(size_t)t * DMODEL + tid + i * 128];
        v[i] = val; s += val;
    }
    __shared__ float red[4];
    #pragma unroll
    for (int o = 16; o > 0; o >>= 1) s += __shfl_xor_sync(0xffffffffu, s, o);
    if ((tid & 31) == 0) red[tid >> 5] = s;
    __syncthreads();
    const float mu = (red[0] + red[1] + red[2] + red[3]) * (1.f / DMODEL);
    float qq = 0.f;
    #pragma unroll
    for (int i = 0; i < 4; i++) { const float dd = v[i] - mu; qq += dd * dd; }
    #pragma unroll
    for (int o = 16; o > 0; o >>= 1) qq += __shfl_xor_sync(0xffffffffu, qq, o);
    __syncthreads();
    if ((tid & 31) == 0) red[tid >> 5] = qq;
    __syncthreads();
    const float var = (red[0] + red[1] + red[2] + red[3]) * (1.f / DMODEL);
    const float rstd = rsqrtf(var + 1e-5f);
    #pragma unroll
    for (int i = 0; i < 4; i++) {
        const int j = tid + i * 128;
        const float out = (v[i] - mu) * rstd * gb[j] + gb[DMODEL + j];
        Y[(size_t)t * DMODEL + j] = out;
        if (Yh) Yh[(size_t)t * DMODEL + j] = __float2half_rn(out);
    }
}

__global__ void embed_kernel(
    const float* __restrict__ x, const float* __restrict__ pe,
    const float* __restrict__ ew, const float* __restrict__ eb,
    float* __restrict__ h, fp16* __restrict__ hh)
{
    const size_t idx = (size_t)blockIdx.x * blockDim.x + threadIdx.x;
    const int tok = (int)(idx >> 9);
    const int j   = (int)(idx & 511);
    const int l   = tok & (LSEQ - 1);
    float val;
    if (j < 256) val = x[(size_t)tok * 2] * ew[j] + x[(size_t)tok * 2 + 1] * ew[256 + j] + eb[j];
    else         val = pe[(size_t)l * 256 + (j - 256)];
    h[idx] = val;
    hh[idx] = __float2half_rn(val);
}

__global__ void dec_init_kernel(const float* __restrict__ ope, float* __restrict__ o,
                                fp16* __restrict__ oh)
{
    const size_t idx = (size_t)blockIdx.x * blockDim.x + threadIdx.x;
    const size_t tok = idx >> 9;
    const float val = ope[((tok & (LSEQ - 1)) << 9) | (idx & 511)];
    o[idx] = val;
    oh[idx] = __float2half_rn(val);
}

__global__ void pred_kernel(
    const float* __restrict__ Xf, const float* __restrict__ pw,
    const float* __restrict__ pb, float* __restrict__ out)
{
    const int gw = (int)(((size_t)blockIdx.x * blockDim.x + threadIdx.x) >> 5);
    const int lane = threadIdx.x & 31;
    if (gw >= NTOK) return;
    const float* xr = Xf + (size_t)gw * DMODEL;
    float a0 = 0.f, a1 = 0.f;
    #pragma unroll 4
    for (int j = lane; j < DMODEL; j += 32) {
        const float v = xr[j];
        a0 = fmaf(v, pw[2 * j],     a0);
        a1 = fmaf(v, pw[2 * j + 1], a1);
    }
    #pragma unroll
    for (int o = 16; o > 0; o >>= 1) {
        a0 += __shfl_xor_sync(0xffffffffu, a0, o);
        a1 += __shfl_xor_sync(0xffffffffu, a1, o);
    }
    if (lane == 0) { out[2 * gw] = a0 + pb[0]; out[2 * gw + 1] = a1 + pb[1]; }
}

// ---------------------------------------------------------------------------
// Host orchestration
// ---------------------------------------------------------------------------
struct Ptrs {
    float *h, *z, *o, *tmp, *pkv, *pks, *kv, *ks;
    fp16 *q, *k, *v;
    fp16 *hh, *zh, *oh, *ath, *fh;
    fp16 *wha, *whf1, *whf2;
};

static void gemm21(const fp16* a, const fp16* b, const float* bias,
                   fp16* Ch, int M, int N, int K) {
    gemm_tc<2,1><<<dim3(N/128, M/128), 256, SMEM_DYN>>>(a, b, bias, nullptr, Ch, M, N, K);
}
static void gemm01(const fp16* a, const fp16* b, const float* bias,
                   fp16* Ch, int M, int N, int K) {
    gemm_tc<0,1><<<dim3(N/128, M/128), 256, SMEM_DYN>>>(a, b, bias, nullptr, Ch, M, N, K);
}
static void gemm00(const fp16* a, const fp16* b, const float* bias,
                   float* C, int M, int N, int K) {
    gemm_tc<0,0><<<dim3(N/128, M/128), 256, SMEM_DYN>>>(a, b, bias, C, nullptr, M, N, K);
}
static void gemm11(const fp16* a, const fp16* b, const float* bias,
                   fp16* Ch, int M, int N, int K) {
    gemm_tc<1,1><<<dim3(N/128, M/128), 256, SMEM_DYN>>>(a, b, bias, nullptr, Ch, M, N, K);
}

static void attention_block(const fp16* xqh, const fp16* xkh,
                            const fp16* wh, const float* b, const Ptrs& P)
{
    const size_t WS = (size_t)DMODEL * DMODEL;
    gemm21(xqh, wh + 0 * WS, b + 0 * DMODEL, P.q, NTOK, DMODEL, DMODEL);
    gemm21(xkh, wh + 1 * WS, b + 1 * DMODEL, P.k, NTOK, DMODEL, DMODEL);
    gemm01(xkh, wh + 2 * WS, b + 2 * DMODEL, P.v, NTOK, DMODEL, DMODEL);

    kv_partial<<<dim3(32, SCH), 256>>>(P.k, P.v, P.pkv, P.pks);
    kv_reduce<<<32, 256>>>(P.pkv, P.pks, P.kv, P.ks);
    attn_out<<<dim3(32, 32), 256>>>(P.q, P.kv, P.ks, P.ath);

    gemm00(P.ath, wh + 3 * WS, b + 3 * DMODEL, P.tmp, NTOK, DMODEL, DMODEL);
}

extern "C" void kernel_launch(void* const* d_in, const int* in_sizes, int n_in,
                              void* d_out, int out_size)
{
    const float* x            = (const float*)d_in[0];
    const float* out_pos_emb  = (const float*)d_in[1];
    const float* pe_input     = (const float*)d_in[2];
    const float* emb_w        = (const float*)d_in[3];
    const float* emb_b        = (const float*)d_in[4];
    const float* enc_attn_w   = (const float*)d_in[5];
    const float* enc_attn_b   = (const float*)d_in[6];
    const float* enc_ln       = (const float*)d_in[7];
    const float* enc_ff_w1    = (const float*)d_in[8];
    const float* enc_ff_b1    = (const float*)d_in[9];
    const float* enc_ff_w2    = (const float*)d_in[10];
    const float* enc_ff_b2    = (const float*)d_in[11];
    const float* enc_final_ln = (const float*)d_in[12];
    const float* dec_self_w   = (const float*)d_in[13];
    const float* dec_self_b   = (const float*)d_in[14];
    const float* dec_cross_w  = (const float*)d_in[15];
    const float* dec_cross_b  = (const float*)d_in[16];
    const float* dec_ln       = (const float*)d_in[17];
    const float* dec_ff_w1    = (const float*)d_in[18];
    const float* dec_ff_b1    = (const float*)d_in[19];
    const float* dec_ff_w2    = (const float*)d_in[20];
    const float* dec_ff_b2    = (const float*)d_in[21];
    const float* dec_final_ln = (const float*)d_in[22];
    const float* pred_w       = (const float*)d_in[23];
    const float* pred_b       = (const float*)d_in[24];

    cudaFuncSetAttribute(gemm_tc<2,1>, cudaFuncAttributeMaxDynamicSharedMemorySize, SMEM_DYN);
    cudaFuncSetAttribute(gemm_tc<0,1>, cudaFuncAttributeMaxDynamicSharedMemorySize, SMEM_DYN);
    cudaFuncSetAttribute(gemm_tc<0,0>, cudaFuncAttributeMaxDynamicSharedMemorySize, SMEM_DYN);
    cudaFuncSetAttribute(gemm_tc<1,1>, cudaFuncAttributeMaxDynamicSharedMemorySize, SMEM_DYN);

    unsigned char* S = nullptr;
    cudaGetSymbolAddress((void**)&S, g_scratch);

    Ptrs P;
    P.h   = (float*)(S + B_H);   P.z   = (float*)(S + B_Z);   P.o  = (float*)(S + B_O);
    P.tmp = (float*)(S + B_TMP);
    P.q   = (fp16*)(S + B_Q);    P.k   = (fp16*)(S + B_K);    P.v  = (fp16*)(S + B_V);
    P.pkv = (float*)(S + B_PKV); P.pks = (float*)(S + B_PKS);
    P.kv  = (float*)(S + B_KVB); P.ks  = (float*)(S + B_KSB);
    P.hh  = (fp16*)(S + B_HH);   P.zh  = (fp16*)(S + B_ZH);
    P.oh  = (fp16*)(S + B_OH);   P.ath = (fp16*)(S + B_ATH);
    P.fh  = (fp16*)(S + B_FH);
    P.wha = (fp16*)(S + B_WHA);
    P.whf1 = (fp16*)(S + B_WHF1);
    P.whf2 = (fp16*)(S + B_WHF2);

    // ---- transpose + fp16-round all weights ----
    transpose_w16<<<dim3(16, 16, 16), 256>>>(enc_attn_w,  P.wha,                     512, 512);
    transpose_w16<<<dim3(16, 16, 16), 256>>>(dec_self_w,  P.wha + (size_t)16*262144, 512, 512);
    transpose_w16<<<dim3(16, 16, 16), 256>>>(dec_cross_w, P.wha + (size_t)32*262144, 512, 512);
    transpose_w16<<<dim3(64, 16, 4),  256>>>(enc_ff_w1, P.whf1,                      512, 2048);
    transpose_w16<<<dim3(64, 16, 4),  256>>>(dec_ff_w1, P.whf1 + (size_t)4*1048576,  512, 2048);
    transpose_w16<<<dim3(16, 64, 4),  256>>>(enc_ff_w2, P.whf2,                      2048, 512);
    transpose_w16<<<dim3(16, 64, 4),  256>>>(dec_ff_w2, P.whf2 + (size_t)4*1048576,  2048, 512);

    const size_t WT4 = (size_t)4 * DMODEL * DMODEL;
    const size_t W1S = (size_t)DFF * DMODEL;
    const size_t W2S = (size_t)DMODEL * DFF;

    // ---- embed ----
    embed_kernel<<<(NTOK * DMODEL) / 256, 256>>>(x, pe_input, emb_w, emb_b, P.h, P.hh);

    // ---- encoder ----
    for (int l = 0; l < 4; l++) {
        const float* ln = enc_ln + (size_t)l * 2 * 2 * DMODEL;
        attention_block(P.hh, P.hh, P.wha + (size_t)l * WT4,
                        enc_attn_b + (size_t)l * 4 * DMODEL, P);
        ln_kernel<<<NTOK, 128>>>(P.h, P.tmp, ln, P.h, P.hh);
        gemm11(P.hh, P.whf1 + (size_t)l * W1S,
               enc_ff_b1 + (size_t)l * DFF, P.fh, NTOK, DFF, DMODEL);
        gemm00(P.fh, P.whf2 + (size_t)l * W2S,
               enc_ff_b2 + (size_t)l * DMODEL, P.tmp, NTOK, DMODEL, DFF);
        ln_kernel<<<NTOK, 128>>>(P.h, P.tmp, ln + 2 * DMODEL, P.h, P.hh);
    }
    ln_kernel<<<NTOK, 128>>>(P.h, nullptr, enc_final_ln, P.z, P.zh);

    // ---- decoder ----
    dec_init_kernel<<<(NTOK * DMODEL) / 256, 256>>>(out_pos_emb, P.o, P.oh);
    for (int l = 0; l < 4; l++) {
        const float* ln = dec_ln + (size_t)l * 3 * 2 * DMODEL;
        attention_block(P.oh, P.oh,
                        P.wha + (size_t)(16 + l * 4) * DMODEL * DMODEL,
                        dec_self_b + (size_t)l * 4 * DMODEL, P);
        ln_kernel<<<NTOK, 128>>>(P.o, P.tmp, ln, P.o, P.oh);
        attention_block(P.oh, P.zh,
                        P.wha + (size_t)(32 + l * 4) * DMODEL * DMODEL,
                        dec_cross_b + (size_t)l * 4 * DMODEL, P);
        ln_kernel<<<NTOK, 128>>>(P.o, P.tmp, ln + 2 * DMODEL, P.o, P.oh);
        gemm11(P.oh, P.whf1 + (size_t)(4 + l) * W1S,
               dec_ff_b1 + (size_t)l * DFF, P.fh, NTOK, DFF, DMODEL);
        gemm00(P.fh, P.whf2 + (size_t)(4 + l) * W2S,
               dec_ff_b2 + (size_t)l * DMODEL, P.tmp, NTOK, DMODEL, DFF);
        ln_kernel<<<NTOK, 128>>>(P.o, P.tmp, ln + 4 * DMODEL, P.o, P.oh);
    }
    ln_kernel<<<NTOK, 128>>>(P.o, nullptr, dec_final_ln, P.tmp, nullptr);

    // ---- prediction head ----
    pred_kernel<<<(NTOK * 32) / 256, 256>>>(P.tmp, pred_w, pred_b, (float*)d_out);
}

// round 10
// speedup vs baseline: 1.5618x; 1.0141x over previous
#include <cuda_runtime.h>
#include <cuda_fp16.h>
#include <cstdint>
#include <cstddef>

// ---------------------------------------------------------------------------
// TRecTransformer: linear-attention encoder/decoder.
// GEMMs: plain fp16 mma.sync m16n8k16 (fp32 accum). Q/K/V fp16.
// This round: float4-vectorized LayerNorm, spread kv_reduce grid,
// halved syncs in kv_partial.
// ---------------------------------------------------------------------------

#define NTOK   16384
#define DMODEL 512
#define DFF    2048
#define LSEQ   4096
#define SCH    16

#define SZ ((size_t)NTOK * DMODEL)        // 8,388,608 elements

// ---- scratch layout (BYTE offsets) ----
#define B_H     ((size_t)0)
#define B_Z     (B_H   + SZ*4)
#define B_O     (B_Z   + SZ*4)
#define B_TMP   (B_O   + SZ*4)
#define B_Q     (B_TMP + SZ*4)            // fp16 (half used)
#define B_K     (B_Q   + SZ*4)
#define B_V     (B_K   + SZ*4)
#define B_PKV   (B_V   + SZ*4)
#define B_PKS   (B_PKV + (size_t)SCH*32*4096*4)
#define B_KVB   (B_PKS + (size_t)SCH*32*64*4)
#define B_KSB   (B_KVB + (size_t)32*4096*4)
// fp16 activations (single-rounded)
#define B_HH    (B_KSB + (size_t)32*64*4)
#define B_ZH    (B_HH  + SZ*2)
#define B_OH    (B_ZH  + SZ*2)
#define B_ATH   (B_OH  + SZ*2)
#define B_FH    (B_ATH + SZ*2)            // NTOK*DFF halves
// fp16 weights (single-rounded, transposed to [N,K])
#define B_WHA   (B_FH  + SZ*8)            // 48 x 512x512
#define B_WHF1  (B_WHA + (size_t)48*262144*2)   // 8 x [2048,512]
#define B_WHF2  (B_WHF1 + (size_t)8*1048576*2)  // 8 x [512,2048]
#define TOTAL_B (B_WHF2 + (size_t)8*1048576*2)

__device__ __align__(1024) unsigned char g_scratch[TOTAL_B];

typedef __half fp16;

// ---------------------------------------------------------------------------
// helpers
// ---------------------------------------------------------------------------
__device__ __forceinline__ uint32_t smem_u32(const void* p) {
    uint32_t a;
    asm("{ .reg .u64 t; cvta.to.shared.u64 t, %1; cvt.u32.u64 %0, t; }" : "=r"(a) : "l"(p));
    return a;
}
__device__ __forceinline__ void ldsm4(uint32_t* r, uint32_t addr) {
    asm volatile("ldmatrix.sync.aligned.m8n8.x4.shared.b16 {%0,%1,%2,%3}, [%4];"
        : "=r"(r[0]), "=r"(r[1]), "=r"(r[2]), "=r"(r[3]) : "r"(addr));
}
__device__ __forceinline__ void mma_f16(float* c, const uint32_t* a, const uint32_t* b) {
    asm volatile(
        "mma.sync.aligned.m16n8k16.row.col.f32.f16.f16.f32 "
        "{%0,%1,%2,%3}, {%4,%5,%6,%7}, {%8,%9}, {%0,%1,%2,%3};"
        : "+f"(c[0]), "+f"(c[1]), "+f"(c[2]), "+f"(c[3])
        : "r"(a[0]), "r"(a[1]), "r"(a[2]), "r"(a[3]), "r"(b[0]), "r"(b[1]));
}
__device__ __forceinline__ void cp16(uint32_t d, const void* s) {
    asm volatile("cp.async.cg.shared.global [%0], [%1], 16;" :: "r"(d), "l"(s));
}
__device__ __forceinline__ void cp_commit() { asm volatile("cp.async.commit_group;" ::: "memory"); }
__device__ __forceinline__ void cp_wait1()  { asm volatile("cp.async.wait_group 1;" ::: "memory"); }
__device__ __forceinline__ void cp_wait0()  { asm volatile("cp.async.wait_group 0;" ::: "memory"); }

// ---------------------------------------------------------------------------
// GEMM: C[M,N] = act(A[M,K] @ W[N,K]^T + bias). fp16 mma.sync, fp32 accum.
// 128x128 tile, Kc=32, 256 threads, 3-stage cp.async pipeline.
// ACT: 0 none, 1 relu, 2 phi=elu+1.  OUTBF: 0 -> fp32 C, 1 -> fp16 Ch.
// ---------------------------------------------------------------------------
#define ROWB 80
#define MATB 10240
#define STGB 20480
#define SMEM_DYN (3 * STGB)

template<int ACT, int OUTBF>
__global__ __launch_bounds__(256) void gemm_tc(
    const fp16* __restrict__ A, const fp16* __restrict__ B,
    const float* __restrict__ bias,
    float* __restrict__ C, fp16* __restrict__ Ch,
    int M, int N, int K)
{
    extern __shared__ char smc[];
    const uint32_t smB = smem_u32(smc);

    const int tid = threadIdx.x, lane = tid & 31, wid = tid >> 5;
    const int row0 = blockIdx.y * 128, col0 = blockIdx.x * 128;
    const int wm = wid & 1, wn = wid >> 1;       // 2 x 4 warp grid

    float acc[4][4][4];
    #pragma unroll
    for (int i = 0; i < 4; i++)
        #pragma unroll
        for (int j = 0; j < 4; j++)
            #pragma unroll
            for (int e = 0; e < 4; e++) acc[i][j][e] = 0.f;

    const uint32_t aoff = (uint32_t)((wm * 64 + (lane & 7) + ((lane >> 3) & 1) * 8) * ROWB
                                     + (lane >> 4) * 16);
    const uint32_t boff = (uint32_t)((wn * 32 + (lane >> 4) * 8 + (lane & 7)) * ROWB
                                     + ((lane >> 3) & 1) * 16);

    const int NC = K / 32;
    const int pr = tid >> 2;             // producer row within 64-row half
    const int pb = (tid & 3) * 16;       // byte offset within 64B row chunk

    auto loadst = [&](int c, int s) {
        const int k0 = c * 32;
        const uint32_t st = smB + (uint32_t)s * STGB;
        #pragma unroll
        for (int m = 0; m < 2; m++) {
            const fp16* g = (m == 0) ? A : B;
            const int rb = (m == 0) ? row0 : col0;
            #pragma unroll
            for (int hf = 0; hf < 2; hf++) {
                const int r = hf * 64 + pr;
                cp16(st + m * MATB + r * ROWB + pb,
                     (const char*)(g + (size_t)(rb + r) * K + k0) + pb);
            }
        }
    };

    auto compute = [&](int s) {
        const uint32_t base = smB + (uint32_t)s * STGB;
        #pragma unroll
        for (int ks = 0; ks < 2; ks++) {
            uint32_t ar[4][4], br[4][2];
            #pragma unroll
            for (int mi = 0; mi < 4; mi++)
                ldsm4(ar[mi], base + aoff + mi * 1280 + ks * 32);
            #pragma unroll
            for (int j = 0; j < 2; j++) {
                uint32_t t[4];
                ldsm4(t, base + MATB + boff + j * 1280 + ks * 32);
                br[2 * j][0] = t[0]; br[2 * j][1] = t[1];
                br[2 * j + 1][0] = t[2]; br[2 * j + 1][1] = t[3];
            }
            #pragma unroll
            for (int mi = 0; mi < 4; mi++)
                #pragma unroll
                for (int ni = 0; ni < 4; ni++) mma_f16(acc[mi][ni], ar[mi], br[ni]);
        }
    };

    loadst(0, 0); cp_commit();
    loadst(1, 1); cp_commit();
    for (int c = 0; c < NC; c++) {
        if (c + 1 < NC) cp_wait1(); else cp_wait0();
        __syncthreads();
        compute(c % 3);
        if (c + 2 < NC) { loadst(c + 2, (c + 2) % 3); cp_commit(); }
    }

    // epilogue
    const int gm0 = row0 + wm * 64;
    const int gn0 = col0 + wn * 32;
    #pragma unroll
    for (int ni = 0; ni < 4; ni++) {
        const int cn = gn0 + ni * 8 + (lane & 3) * 2;
        const float b0 = bias[cn], b1 = bias[cn + 1];
        #pragma unroll
        for (int mi = 0; mi < 4; mi++) {
            const int rm = gm0 + mi * 16 + (lane >> 2);
            float t0 = acc[mi][ni][0] + b0;
            float t1 = acc[mi][ni][1] + b1;
            float t2 = acc[mi][ni][2] + b0;
            float t3 = acc[mi][ni][3] + b1;
            if (ACT == 1) {
                t0 = fmaxf(t0, 0.f); t1 = fmaxf(t1, 0.f);
                t2 = fmaxf(t2, 0.f); t3 = fmaxf(t3, 0.f);
            }
            if (ACT == 2) {
                t0 = t0 > 0.f ? t0 + 1.f : __expf(t0);
                t1 = t1 > 0.f ? t1 + 1.f : __expf(t1);
                t2 = t2 > 0.f ? t2 + 1.f : __expf(t2);
                t3 = t3 > 0.f ? t3 + 1.f : __expf(t3);
            }
            if (OUTBF == 0) {
                float2 v0; v0.x = t0; v0.y = t1;
                float2 v1; v1.x = t2; v1.y = t3;
                *(float2*)&C[(size_t)rm * N + cn]       = v0;
                *(float2*)&C[(size_t)(rm + 8) * N + cn] = v1;
            } else {
                __half2 hp;
                hp.x = __float2half_rn(t0); hp.y = __float2half_rn(t1);
                *(__half2*)&Ch[(size_t)rm * N + cn] = hp;
                hp.x = __float2half_rn(t2); hp.y = __float2half_rn(t3);
                *(__half2*)&Ch[(size_t)(rm + 8) * N + cn] = hp;
            }
        }
    }
}

// ---------------------------------------------------------------------------
// fused weight transpose + fp16 round: W[K,N] fp32 -> Wh [N,K] fp16
// ---------------------------------------------------------------------------
__global__ __launch_bounds__(256) void transpose_w16(
    const float* __restrict__ W, fp16* __restrict__ Wh, int K, int N)
{
    __shared__ float t[32][33];
    const size_t mo = (size_t)blockIdx.z * K * N;
    const float* Wm = W + mo;
    const int n0 = blockIdx.x * 32, k0 = blockIdx.y * 32;
    const int tx = threadIdx.x & 31, ty = threadIdx.x >> 5;
    #pragma unroll
    for (int i = 0; i < 32; i += 8)
        t[ty + i][tx] = Wm[(size_t)(k0 + ty + i) * N + n0 + tx];
    __syncthreads();
    #pragma unroll
    for (int i = 0; i < 32; i += 8)
        Wh[mo + (size_t)(n0 + ty + i) * K + k0 + tx] = __float2half_rn(t[tx][ty + i]);
}

// ---------------------------------------------------------------------------
// linear-attention kernels (Q/K/V fp16; accumulate fp32)
// ---------------------------------------------------------------------------
__global__ __launch_bounds__(256) void kv_partial(
    const fp16* __restrict__ Kt, const fp16* __restrict__ Vt,
    float* __restrict__ pkv, float* __restrict__ pks)
{
    const int bh = blockIdx.x, ch = blockIdx.y;
    const int b = bh >> 3, h = bh & 7;
    const int tid = threadIdx.x;
    __shared__ float Ks[8][64], Vs[8][64];

    float acc[16];
    #pragma unroll
    for (int j = 0; j < 16; j++) acc[j] = 0.f;
    float ksa = 0.f;

    const int s0 = ch * (LSEQ / SCH);
    const size_t base = ((size_t)b * LSEQ) * DMODEL + h * 64;
    const int r = tid >> 6, d = tid & 63;

    for (int s = s0; s < s0 + LSEQ / SCH; s += 8) {
        #pragma unroll
        for (int p = 0; p < 2; p++) {
            const int rr = r + p * 4;
            const size_t off = base + (size_t)(s + rr) * DMODEL + d;
            Ks[rr][d] = __half2float(Kt[off]);
            Vs[rr][d] = __half2float(Vt[off]);
        }
        __syncthreads();
        #pragma unroll
        for (int rr = 0; rr < 8; rr++) {
            #pragma unroll
            for (int j = 0; j < 16; j++) {
                const int flat = j * 256 + tid;
                acc[j] = fmaf(Ks[rr][flat >> 6], Vs[rr][flat & 63], acc[j]);
            }
            if (tid < 64) ksa += Ks[rr][tid];
        }
        __syncthreads();
    }
    float* o = pkv + ((size_t)ch * 32 + bh) * 4096;
    #pragma unroll
    for (int j = 0; j < 16; j++) o[j * 256 + tid] = acc[j];
    if (tid < 64) pks[((size_t)ch * 32 + bh) * 64 + tid] = ksa;
}

// grid (32, 8): each y-slice reduces 512 kv elements; y==0 also reduces pks.
__global__ __launch_bounds__(256) void kv_reduce(
    const float* __restrict__ pkv, const float* __restrict__ pks,
    float* __restrict__ kv, float* __restrict__ ks)
{
    const int bh = blockIdx.x, tid = threadIdx.x;
    const int e0 = blockIdx.y * 512;
    for (int e = e0 + tid; e < e0 + 512; e += 256) {
        float s = 0.f;
        #pragma unroll
        for (int c = 0; c < SCH; c++) s += pkv[((size_t)c * 32 + bh) * 4096 + e];
        kv[(size_t)bh * 4096 + e] = s;
    }
    if (blockIdx.y == 0 && tid < 64) {
        float s = 0.f;
        #pragma unroll
        for (int c = 0; c < SCH; c++) s += pks[((size_t)c * 32 + bh) * 64 + tid];
        ks[bh * 64 + tid] = s;
    }
}

__global__ __launch_bounds__(256) void attn_out(
    const fp16* __restrict__ Q, const float* __restrict__ kv,
    const float* __restrict__ ksum, fp16* __restrict__ Oh)
{
    const int bh = blockIdx.x, b = bh >> 3, h = bh & 7;
    __shared__ float kvs[64][64];
    __shared__ float kss[64];
    const int tid = threadIdx.x;
    for (int e = tid; e < 4096; e += 256) kvs[e >> 6][e & 63] = kv[(size_t)bh * 4096 + e];
    if (tid < 64) kss[tid] = ksum[bh * 64 + tid];
    __syncthreads();

    const int warp = tid >> 5, lane = tid & 31;
    const int tpb = LSEQ / gridDim.y;
    const int l0 = blockIdx.y * tpb;

    for (int l = l0 + warp; l < l0 + tpb; l += 8) {
        const fp16* q = Q + ((size_t)(b * LSEQ + l)) * DMODEL + h * 64;
        const float q0 = __half2float(q[lane]), q1 = __half2float(q[lane + 32]);
        float zd = q0 * kss[lane] + q1 * kss[lane + 32];
        #pragma unroll
        for (int o = 16; o > 0; o >>= 1) zd += __shfl_xor_sync(0xffffffffu, zd, o);
        const float z = 1.f / (zd + 1e-6f);

        float a0 = 0.f, a1 = 0.f;
        #pragma unroll
        for (int dd = 0; dd < 32; dd++) {
            const float qd = __shfl_sync(0xffffffffu, q0, dd);
            a0 = fmaf(qd, kvs[dd][lane],      a0);
            a1 = fmaf(qd, kvs[dd][lane + 32], a1);
        }
        #pragma unroll
        for (int dd = 0; dd < 32; dd++) {
            const float qd = __shfl_sync(0xffffffffu, q1, dd);
            a0 = fmaf(qd, kvs[dd + 32][lane],      a0);
            a1 = fmaf(qd, kvs[dd + 32][lane + 32], a1);
        }
        const size_t op = ((size_t)(b * LSEQ + l)) * DMODEL + h * 64;
        Oh[op + lane]      = __float2half_rn(a0 * z);
        Oh[op + lane + 32] = __float2half_rn(a1 * z);
    }
}

// ---------------------------------------------------------------------------
// LayerNorm: float4-vectorized. 128 threads x 1 float4 per token.
// Y = LN(X + R) * gamma + beta; optional fp16 copy Yh.
// ---------------------------------------------------------------------------
__global__ __launch_bounds__(128) void ln_kernel(
    const float* __restrict__ X, const float* __restrict__ R,
    const float* __restrict__ gb, float* __restrict__ Y,
    fp16* __restrict__ Yh)
{
    const int t = blockIdx.x, tid = threadIdx.x;
    float4 v = ((const float4*)(X + (size_t)t * DMODEL))[tid];
    if (R) {
        const float4 rv = ((const float4*)(R + (size_t)t * DMODEL))[tid];
        v.x += rv.x; v.y += rv.y; v.z += rv.z; v.w += rv.w;
    }
    float s = v.x + v.y + v.z + v.w;

    __shared__ float red[4];
    #pragma unroll
    for (int o = 16; o > 0; o >>= 1) s += __shfl_xor_sync(0xffffffffu, s, o);
    if ((tid & 31) == 0) red[tid >> 5] = s;
    __syncthreads();
    const float mu = (red[0] + red[1] + red[2] + red[3]) * (1.f / DMODEL);

    const float dx = v.x - mu, dy = v.y - mu, dz = v.z - mu, dw = v.w - mu;
    float qq = dx * dx + dy * dy + dz * dz + dw * dw;
    #pragma unroll
    for (int o = 16; o > 0; o >>= 1) qq += __shfl_xor_sync(0xffffffffu, qq, o);
    __syncthreads();
    if ((tid & 31) == 0) red[tid >> 5] = qq;
    __syncthreads();
    const float var = (red[0] + red[1] + red[2] + red[3]) * (1.f / DMODEL);
    const float rstd = rsqrtf(var + 1e-5f);

    const float4 g = ((const float4*)gb)[tid];
    const float4 be = ((const float4*)(gb + DMODEL))[tid];
    float4 out;
    out.x = dx * rstd * g.x + be.x;
    out.y = dy * rstd * g.y + be.y;
    out.z = dz * rstd * g.z + be.z;
    out.w = dw * rstd * g.w + be.w;
    ((float4*)(Y + (size_t)t * DMODEL))[tid] = out;
    if (Yh) {
        __half2 h0, h1;
        h0.x = __float2half_rn(out.x); h0.y = __float2half_rn(out.y);
        h1.x = __float2half_rn(out.z); h1.y = __float2half_rn(out.w);
        uint2 pk;
        pk.x = *(uint32_t*)&h0; pk.y = *(uint32_t*)&h1;
        ((uint2*)(Yh + (size_t)t * DMODEL))[tid] = pk;
    }
}

__global__ void embed_kernel(
    const float* __restrict__ x, const float* __restrict__ pe,
    const float* __restrict__ ew, const float* __restrict__ eb,
    float* __restrict__ h, fp16* __restrict__ hh)
{
    const size_t idx = (size_t)blockIdx.x * blockDim.x + threadIdx.x;
    const int tok = (int)(idx >> 9);
    const int j   = (int)(idx & 511);
    const int l   = tok & (LSEQ - 1);
    float val;
    if (j < 256) val = x[(size_t)tok * 2] * ew[j] + x[(size_t)tok * 2 + 1] * ew[256 + j] + eb[j];
    else         val = pe[(size_t)l * 256 + (j - 256)];
    h[idx] = val;
    hh[idx] = __float2half_rn(val);
}

__global__ void dec_init_kernel(const float* __restrict__ ope, float* __restrict__ o,
                                fp16* __restrict__ oh)
{
    const size_t idx = (size_t)blockIdx.x * blockDim.x + threadIdx.x;
    const size_t tok = idx >> 9;
    const float val = ope[((tok & (LSEQ - 1)) << 9) | (idx & 511)];
    o[idx] = val;
    oh[idx] = __float2half_rn(val);
}

__global__ void pred_kernel(
    const float* __restrict__ Xf, const float* __restrict__ pw,
    const float* __restrict__ pb, float* __restrict__ out)
{
    const int gw = (int)(((size_t)blockIdx.x * blockDim.x + threadIdx.x) >> 5);
    const int lane = threadIdx.x & 31;
    if (gw >= NTOK) return;
    const float* xr = Xf + (size_t)gw * DMODEL;
    float a0 = 0.f, a1 = 0.f;
    #pragma unroll 4
    for (int j = lane; j < DMODEL; j += 32) {
        const float v = xr[j];
        a0 = fmaf(v, pw[2 * j],     a0);
        a1 = fmaf(v, pw[2 * j + 1], a1);
    }
    #pragma unroll
    for (int o = 16; o > 0; o >>= 1) {
        a0 += __shfl_xor_sync(0xffffffffu, a0, o);
        a1 += __shfl_xor_sync(0xffffffffu, a1, o);
    }
    if (lane == 0) { out[2 * gw] = a0 + pb[0]; out[2 * gw + 1] = a1 + pb[1]; }
}

// ---------------------------------------------------------------------------
// Host orchestration
// ---------------------------------------------------------------------------
struct Ptrs {
    float *h, *z, *o, *tmp, *pkv, *pks, *kv, *ks;
    fp16 *q, *k, *v;
    fp16 *hh, *zh, *oh, *ath, *fh;
    fp16 *wha, *whf1, *whf2;
};

static void gemm21(const fp16* a, const fp16* b, const float* bias,
                   fp16* Ch, int M, int N, int K) {
    gemm_tc<2,1><<<dim3(N/128, M/128), 256, SMEM_DYN>>>(a, b, bias, nullptr, Ch, M, N, K);
}
static void gemm01(const fp16* a, const fp16* b, const float* bias,
                   fp16* Ch, int M, int N, int K) {
    gemm_tc<0,1><<<dim3(N/128, M/128), 256, SMEM_DYN>>>(a, b, bias, nullptr, Ch, M, N, K);
}
static void gemm00(const fp16* a, const fp16* b, const float* bias,
                   float* C, int M, int N, int K) {
    gemm_tc<0,0><<<dim3(N/128, M/128), 256, SMEM_DYN>>>(a, b, bias, C, nullptr, M, N, K);
}
static void gemm11(const fp16* a, const fp16* b, const float* bias,
                   fp16* Ch, int M, int N, int K) {
    gemm_tc<1,1><<<dim3(N/128, M/128), 256, SMEM_DYN>>>(a, b, bias, nullptr, Ch, M, N, K);
}

static void attention_block(const fp16* xqh, const fp16* xkh,
                            const fp16* wh, const float* b, const Ptrs& P)
{
    const size_t WS = (size_t)DMODEL * DMODEL;
    gemm21(xqh, wh + 0 * WS, b + 0 * DMODEL, P.q, NTOK, DMODEL, DMODEL);
    gemm21(xkh, wh + 1 * WS, b + 1 * DMODEL, P.k, NTOK, DMODEL, DMODEL);
    gemm01(xkh, wh + 2 * WS, b + 2 * DMODEL, P.v, NTOK, DMODEL, DMODEL);

    kv_partial<<<dim3(32, SCH), 256>>>(P.k, P.v, P.pkv, P.pks);
    kv_reduce<<<dim3(32, 8), 256>>>(P.pkv, P.pks, P.kv, P.ks);
    attn_out<<<dim3(32, 32), 256>>>(P.q, P.kv, P.ks, P.ath);

    gemm00(P.ath, wh + 3 * WS, b + 3 * DMODEL, P.tmp, NTOK, DMODEL, DMODEL);
}

extern "C" void kernel_launch(void* const* d_in, const int* in_sizes, int n_in,
                              void* d_out, int out_size)
{
    const float* x            = (const float*)d_in[0];
    const float* out_pos_emb  = (const float*)d_in[1];
    const float* pe_input     = (const float*)d_in[2];
    const float* emb_w        = (const float*)d_in[3];
    const float* emb_b        = (const float*)d_in[4];
    const float* enc_attn_w   = (const float*)d_in[5];
    const float* enc_attn_b   = (const float*)d_in[6];
    const float* enc_ln       = (const float*)d_in[7];
    const float* enc_ff_w1    = (const float*)d_in[8];
    const float* enc_ff_b1    = (const float*)d_in[9];
    const float* enc_ff_w2    = (const float*)d_in[10];
    const float* enc_ff_b2    = (const float*)d_in[11];
    const float* enc_final_ln = (const float*)d_in[12];
    const float* dec_self_w   = (const float*)d_in[13];
    const float* dec_self_b   = (const float*)d_in[14];
    const float* dec_cross_w  = (const float*)d_in[15];
    const float* dec_cross_b  = (const float*)d_in[16];
    const float* dec_ln       = (const float*)d_in[17];
    const float* dec_ff_w1    = (const float*)d_in[18];
    const float* dec_ff_b1    = (const float*)d_in[19];
    const float* dec_ff_w2    = (const float*)d_in[20];
    const float* dec_ff_b2    = (const float*)d_in[21];
    const float* dec_final_ln = (const float*)d_in[22];
    const float* pred_w       = (const float*)d_in[23];
    const float* pred_b       = (const float*)d_in[24];

    cudaFuncSetAttribute(gemm_tc<2,1>, cudaFuncAttributeMaxDynamicSharedMemorySize, SMEM_DYN);
    cudaFuncSetAttribute(gemm_tc<0,1>, cudaFuncAttributeMaxDynamicSharedMemorySize, SMEM_DYN);
    cudaFuncSetAttribute(gemm_tc<0,0>, cudaFuncAttributeMaxDynamicSharedMemorySize, SMEM_DYN);
    cudaFuncSetAttribute(gemm_tc<1,1>, cudaFuncAttributeMaxDynamicSharedMemorySize, SMEM_DYN);

    unsigned char* S = nullptr;
    cudaGetSymbolAddress((void**)&S, g_scratch);

    Ptrs P;
    P.h   = (float*)(S + B_H);   P.z   = (float*)(S + B_Z);   P.o  = (float*)(S + B_O);
    P.tmp = (float*)(S + B_TMP);
    P.q   = (fp16*)(S + B_Q);    P.k   = (fp16*)(S + B_K);    P.v  = (fp16*)(S + B_V);
    P.pkv = (float*)(S + B_PKV); P.pks = (float*)(S + B_PKS);
    P.kv  = (float*)(S + B_KVB); P.ks  = (float*)(S + B_KSB);
    P.hh  = (fp16*)(S + B_HH);   P.zh  = (fp16*)(S + B_ZH);
    P.oh  = (fp16*)(S + B_OH);   P.ath = (fp16*)(S + B_ATH);
    P.fh  = (fp16*)(S + B_FH);
    P.wha = (fp16*)(S + B_WHA);
    P.whf1 = (fp16*)(S + B_WHF1);
    P.whf2 = (fp16*)(S + B_WHF2);

    // ---- transpose + fp16-round all weights ----
    transpose_w16<<<dim3(16, 16, 16), 256>>>(enc_attn_w,  P.wha,                     512, 512);
    transpose_w16<<<dim3(16, 16, 16), 256>>>(dec_self_w,  P.wha + (size_t)16*262144, 512, 512);
    transpose_w16<<<dim3(16, 16, 16), 256>>>(dec_cross_w, P.wha + (size_t)32*262144, 512, 512);
    transpose_w16<<<dim3(64, 16, 4),  256>>>(enc_ff_w1, P.whf1,                      512, 2048);
    transpose_w16<<<dim3(64, 16, 4),  256>>>(dec_ff_w1, P.whf1 + (size_t)4*1048576,  512, 2048);
    transpose_w16<<<dim3(16, 64, 4),  256>>>(enc_ff_w2, P.whf2,                      2048, 512);
    transpose_w16<<<dim3(16, 64, 4),  256>>>(dec_ff_w2, P.whf2 + (size_t)4*1048576,  2048, 512);

    const size_t WT4 = (size_t)4 * DMODEL * DMODEL;
    const size_t W1S = (size_t)DFF * DMODEL;
    const size_t W2S = (size_t)DMODEL * DFF;

    // ---- embed ----
    embed_kernel<<<(NTOK * DMODEL) / 256, 256>>>(x, pe_input, emb_w, emb_b, P.h, P.hh);

    // ---- encoder ----
    for (int l = 0; l < 4; l++) {
        const float* ln = enc_ln + (size_t)l * 2 * 2 * DMODEL;
        attention_block(P.hh, P.hh, P.wha + (size_t)l * WT4,
                        enc_attn_b + (size_t)l * 4 * DMODEL, P);
        ln_kernel<<<NTOK, 128>>>(P.h, P.tmp, ln, P.h, P.hh);
        gemm11(P.hh, P.whf1 + (size_t)l * W1S,
               enc_ff_b1 + (size_t)l * DFF, P.fh, NTOK, DFF, DMODEL);
        gemm00(P.fh, P.whf2 + (size_t)l * W2S,
               enc_ff_b2 + (size_t)l * DMODEL, P.tmp, NTOK, DMODEL, DFF);
        ln_kernel<<<NTOK, 128>>>(P.h, P.tmp, ln + 2 * DMODEL, P.h, P.hh);
    }
    ln_kernel<<<NTOK, 128>>>(P.h, nullptr, enc_final_ln, P.z, P.zh);

    // ---- decoder ----
    dec_init_kernel<<<(NTOK * DMODEL) / 256, 256>>>(out_pos_emb, P.o, P.oh);
    for (int l = 0; l < 4; l++) {
        const float* ln = dec_ln + (size_t)l * 3 * 2 * DMODEL;
        attention_block(P.oh, P.oh,
                        P.wha + (size_t)(16 + l * 4) * DMODEL * DMODEL,
                        dec_self_b + (size_t)l * 4 * DMODEL, P);
        ln_kernel<<<NTOK, 128>>>(P.o, P.tmp, ln, P.o, P.oh);
        attention_block(P.oh, P.zh,
                        P.wha + (size_t)(32 + l * 4) * DMODEL * DMODEL,
                        dec_cross_b + (size_t)l * 4 * DMODEL, P);
        ln_kernel<<<NTOK, 128>>>(P.o, P.tmp, ln + 2 * DMODEL, P.o, P.oh);
        gemm11(P.oh, P.whf1 + (size_t)(4 + l) * W1S,
               dec_ff_b1 + (size_t)l * DFF, P.fh, NTOK, DFF, DMODEL);
        gemm00(P.fh, P.whf2 + (size_t)(4 + l) * W2S,
               dec_ff_b2 + (size_t)l * DMODEL, P.tmp, NTOK, DMODEL, DFF);
        ln_kernel<<<NTOK, 128>>>(P.o, P.tmp, ln + 4 * DMODEL, P.o, P.oh);
    }
    ln_kernel<<<NTOK, 128>>>(P.o, nullptr, dec_final_ln, P.tmp, nullptr);

    // ---- prediction head ----
    pred_kernel<<<(NTOK * 32) / 256, 256>>>(P.tmp, pred_w, pred_b, (float*)d_out);
}

// round 11
// speedup vs baseline: 1.9280x; 1.2345x over previous
#include <cuda_runtime.h>
#include <cuda_fp16.h>
#include <cstdint>
#include <cstddef>

// ---------------------------------------------------------------------------
// TRecTransformer: linear-attention encoder/decoder.
// GEMMs: plain fp16 mma.sync m16n8k16 (fp32 accum). Q/K/V fp16.
// This round: register-tiled kv_partial (4x4 outer product, LDS.128) and
// attn_out (8-token batches) to remove the smem-issue bottleneck.
// ---------------------------------------------------------------------------

#define NTOK   16384
#define DMODEL 512
#define DFF    2048
#define LSEQ   4096
#define SCH    16

#define SZ ((size_t)NTOK * DMODEL)        // 8,388,608 elements

// ---- scratch layout (BYTE offsets) ----
#define B_H     ((size_t)0)
#define B_Z     (B_H   + SZ*4)
#define B_O     (B_Z   + SZ*4)
#define B_TMP   (B_O   + SZ*4)
#define B_Q     (B_TMP + SZ*4)            // fp16 (half used)
#define B_K     (B_Q   + SZ*4)
#define B_V     (B_K   + SZ*4)
#define B_PKV   (B_V   + SZ*4)
#define B_PKS   (B_PKV + (size_t)SCH*32*4096*4)
#define B_KVB   (B_PKS + (size_t)SCH*32*64*4)
#define B_KSB   (B_KVB + (size_t)32*4096*4)
// fp16 activations (single-rounded)
#define B_HH    (B_KSB + (size_t)32*64*4)
#define B_ZH    (B_HH  + SZ*2)
#define B_OH    (B_ZH  + SZ*2)
#define B_ATH   (B_OH  + SZ*2)
#define B_FH    (B_ATH + SZ*2)            // NTOK*DFF halves
// fp16 weights (single-rounded, transposed to [N,K])
#define B_WHA   (B_FH  + SZ*8)            // 48 x 512x512
#define B_WHF1  (B_WHA + (size_t)48*262144*2)   // 8 x [2048,512]
#define B_WHF2  (B_WHF1 + (size_t)8*1048576*2)  // 8 x [512,2048]
#define TOTAL_B (B_WHF2 + (size_t)8*1048576*2)

__device__ __align__(1024) unsigned char g_scratch[TOTAL_B];

typedef __half fp16;

// ---------------------------------------------------------------------------
// helpers
// ---------------------------------------------------------------------------
__device__ __forceinline__ uint32_t smem_u32(const void* p) {
    uint32_t a;
    asm("{ .reg .u64 t; cvta.to.shared.u64 t, %1; cvt.u32.u64 %0, t; }" : "=r"(a) : "l"(p));
    return a;
}
__device__ __forceinline__ void ldsm4(uint32_t* r, uint32_t addr) {
    asm volatile("ldmatrix.sync.aligned.m8n8.x4.shared.b16 {%0,%1,%2,%3}, [%4];"
        : "=r"(r[0]), "=r"(r[1]), "=r"(r[2]), "=r"(r[3]) : "r"(addr));
}
__device__ __forceinline__ void mma_f16(float* c, const uint32_t* a, const uint32_t* b) {
    asm volatile(
        "mma.sync.aligned.m16n8k16.row.col.f32.f16.f16.f32 "
        "{%0,%1,%2,%3}, {%4,%5,%6,%7}, {%8,%9}, {%0,%1,%2,%3};"
        : "+f"(c[0]), "+f"(c[1]), "+f"(c[2]), "+f"(c[3])
        : "r"(a[0]), "r"(a[1]), "r"(a[2]), "r"(a[3]), "r"(b[0]), "r"(b[1]));
}
__device__ __forceinline__ void cp16(uint32_t d, const void* s) {
    asm volatile("cp.async.cg.shared.global [%0], [%1], 16;" :: "r"(d), "l"(s));
}
__device__ __forceinline__ void cp_commit() { asm volatile("cp.async.commit_group;" ::: "memory"); }
__device__ __forceinline__ void cp_wait1()  { asm volatile("cp.async.wait_group 1;" ::: "memory"); }
__device__ __forceinline__ void cp_wait0()  { asm volatile("cp.async.wait_group 0;" ::: "memory"); }

// ---------------------------------------------------------------------------
// GEMM: C[M,N] = act(A[M,K] @ W[N,K]^T + bias). fp16 mma.sync, fp32 accum.
// 128x128 tile, Kc=32, 256 threads, 3-stage cp.async pipeline.
// ACT: 0 none, 1 relu, 2 phi=elu+1.  OUTBF: 0 -> fp32 C, 1 -> fp16 Ch.
// ---------------------------------------------------------------------------
#define ROWB 80
#define MATB 10240
#define STGB 20480
#define SMEM_DYN (3 * STGB)

template<int ACT, int OUTBF>
__global__ __launch_bounds__(256) void gemm_tc(
    const fp16* __restrict__ A, const fp16* __restrict__ B,
    const float* __restrict__ bias,
    float* __restrict__ C, fp16* __restrict__ Ch,
    int M, int N, int K)
{
    extern __shared__ char smc[];
    const uint32_t smB = smem_u32(smc);

    const int tid = threadIdx.x, lane = tid & 31, wid = tid >> 5;
    const int row0 = blockIdx.y * 128, col0 = blockIdx.x * 128;
    const int wm = wid & 1, wn = wid >> 1;       // 2 x 4 warp grid

    float acc[4][4][4];
    #pragma unroll
    for (int i = 0; i < 4; i++)
        #pragma unroll
        for (int j = 0; j < 4; j++)
            #pragma unroll
            for (int e = 0; e < 4; e++) acc[i][j][e] = 0.f;

    const uint32_t aoff = (uint32_t)((wm * 64 + (lane & 7) + ((lane >> 3) & 1) * 8) * ROWB
                                     + (lane >> 4) * 16);
    const uint32_t boff = (uint32_t)((wn * 32 + (lane >> 4) * 8 + (lane & 7)) * ROWB
                                     + ((lane >> 3) & 1) * 16);

    const int NC = K / 32;
    const int pr = tid >> 2;             // producer row within 64-row half
    const int pb = (tid & 3) * 16;       // byte offset within 64B row chunk

    auto loadst = [&](int c, int s) {
        const int k0 = c * 32;
        const uint32_t st = smB + (uint32_t)s * STGB;
        #pragma unroll
        for (int m = 0; m < 2; m++) {
            const fp16* g = (m == 0) ? A : B;
            const int rb = (m == 0) ? row0 : col0;
            #pragma unroll
            for (int hf = 0; hf < 2; hf++) {
                const int r = hf * 64 + pr;
                cp16(st + m * MATB + r * ROWB + pb,
                     (const char*)(g + (size_t)(rb + r) * K + k0) + pb);
            }
        }
    };

    auto compute = [&](int s) {
        const uint32_t base = smB + (uint32_t)s * STGB;
        #pragma unroll
        for (int ks = 0; ks < 2; ks++) {
            uint32_t ar[4][4], br[4][2];
            #pragma unroll
            for (int mi = 0; mi < 4; mi++)
                ldsm4(ar[mi], base + aoff + mi * 1280 + ks * 32);
            #pragma unroll
            for (int j = 0; j < 2; j++) {
                uint32_t t[4];
                ldsm4(t, base + MATB + boff + j * 1280 + ks * 32);
                br[2 * j][0] = t[0]; br[2 * j][1] = t[1];
                br[2 * j + 1][0] = t[2]; br[2 * j + 1][1] = t[3];
            }
            #pragma unroll
            for (int mi = 0; mi < 4; mi++)
                #pragma unroll
                for (int ni = 0; ni < 4; ni++) mma_f16(acc[mi][ni], ar[mi], br[ni]);
        }
    };

    loadst(0, 0); cp_commit();
    loadst(1, 1); cp_commit();
    for (int c = 0; c < NC; c++) {
        if (c + 1 < NC) cp_wait1(); else cp_wait0();
        __syncthreads();
        compute(c % 3);
        if (c + 2 < NC) { loadst(c + 2, (c + 2) % 3); cp_commit(); }
    }

    // epilogue
    const int gm0 = row0 + wm * 64;
    const int gn0 = col0 + wn * 32;
    #pragma unroll
    for (int ni = 0; ni < 4; ni++) {
        const int cn = gn0 + ni * 8 + (lane & 3) * 2;
        const float b0 = bias[cn], b1 = bias[cn + 1];
        #pragma unroll
        for (int mi = 0; mi < 4; mi++) {
            const int rm = gm0 + mi * 16 + (lane >> 2);
            float t0 = acc[mi][ni][0] + b0;
            float t1 = acc[mi][ni][1] + b1;
            float t2 = acc[mi][ni][2] + b0;
            float t3 = acc[mi][ni][3] + b1;
            if (ACT == 1) {
                t0 = fmaxf(t0, 0.f); t1 = fmaxf(t1, 0.f);
                t2 = fmaxf(t2, 0.f); t3 = fmaxf(t3, 0.f);
            }
            if (ACT == 2) {
                t0 = t0 > 0.f ? t0 + 1.f : __expf(t0);
                t1 = t1 > 0.f ? t1 + 1.f : __expf(t1);
                t2 = t2 > 0.f ? t2 + 1.f : __expf(t2);
                t3 = t3 > 0.f ? t3 + 1.f : __expf(t3);
            }
            if (OUTBF == 0) {
                float2 v0; v0.x = t0; v0.y = t1;
                float2 v1; v1.x = t2; v1.y = t3;
                *(float2*)&C[(size_t)rm * N + cn]       = v0;
                *(float2*)&C[(size_t)(rm + 8) * N + cn] = v1;
            } else {
                __half2 hp;
                hp.x = __float2half_rn(t0); hp.y = __float2half_rn(t1);
                *(__half2*)&Ch[(size_t)rm * N + cn] = hp;
                hp.x = __float2half_rn(t2); hp.y = __float2half_rn(t3);
                *(__half2*)&Ch[(size_t)(rm + 8) * N + cn] = hp;
            }
        }
    }
}

// ---------------------------------------------------------------------------
// fused weight transpose + fp16 round: W[K,N] fp32 -> Wh [N,K] fp16
// ---------------------------------------------------------------------------
__global__ __launch_bounds__(256) void transpose_w16(
    const float* __restrict__ W, fp16* __restrict__ Wh, int K, int N)
{
    __shared__ float t[32][33];
    const size_t mo = (size_t)blockIdx.z * K * N;
    const float* Wm = W + mo;
    const int n0 = blockIdx.x * 32, k0 = blockIdx.y * 32;
    const int tx = threadIdx.x & 31, ty = threadIdx.x >> 5;
    #pragma unroll
    for (int i = 0; i < 32; i += 8)
        t[ty + i][tx] = Wm[(size_t)(k0 + ty + i) * N + n0 + tx];
    __syncthreads();
    #pragma unroll
    for (int i = 0; i < 32; i += 8)
        Wh[mo + (size_t)(n0 + ty + i) * K + k0 + tx] = __float2half_rn(t[tx][ty + i]);
}

// ---------------------------------------------------------------------------
// kv partial: register-tiled 4x4 outer product per thread.
// pkv[ch,bh][d][m] = sum_{s in chunk} K[s,d]*V[s,m]; pks = sum K.
// grid (32, SCH), 256 threads (16x16 thread grid over (d,m)).
// ---------------------------------------------------------------------------
__global__ __launch_bounds__(256) void kv_partial(
    const fp16* __restrict__ Kt, const fp16* __restrict__ Vt,
    float* __restrict__ pkv, float* __restrict__ pks)
{
    const int bh = blockIdx.x, ch = blockIdx.y;
    const int b = bh >> 3, h = bh & 7;
    const int tid = threadIdx.x;
    __shared__ float Ks[8][64], Vs[8][64];

    float acc[4][4];
    #pragma unroll
    for (int i = 0; i < 4; i++)
        #pragma unroll
        for (int j = 0; j < 4; j++) acc[i][j] = 0.f;
    float ksa[4] = {0.f, 0.f, 0.f, 0.f};

    const int td = tid >> 4, tm = tid & 15;
    const int s0 = ch * (LSEQ / SCH);
    const size_t base = ((size_t)b * LSEQ) * DMODEL + h * 64;
    const int lr = tid >> 5, lc = (tid & 31) * 2;   // loader: 8 rows x 64 halves

    for (int s = s0; s < s0 + LSEQ / SCH; s += 8) {
        const size_t off = base + (size_t)(s + lr) * DMODEL + lc;
        const float2 kf = __half22float2(*(const __half2*)(Kt + off));
        const float2 vf = __half22float2(*(const __half2*)(Vt + off));
        *(float2*)&Ks[lr][lc] = kf;
        *(float2*)&Vs[lr][lc] = vf;
        __syncthreads();
        #pragma unroll
        for (int rr = 0; rr < 8; rr++) {
            const float4 k4 = *(const float4*)&Ks[rr][td * 4];
            const float4 v4 = *(const float4*)&Vs[rr][tm * 4];
            acc[0][0] = fmaf(k4.x, v4.x, acc[0][0]);
            acc[0][1] = fmaf(k4.x, v4.y, acc[0][1]);
            acc[0][2] = fmaf(k4.x, v4.z, acc[0][2]);
            acc[0][3] = fmaf(k4.x, v4.w, acc[0][3]);
            acc[1][0] = fmaf(k4.y, v4.x, acc[1][0]);
            acc[1][1] = fmaf(k4.y, v4.y, acc[1][1]);
            acc[1][2] = fmaf(k4.y, v4.z, acc[1][2]);
            acc[1][3] = fmaf(k4.y, v4.w, acc[1][3]);
            acc[2][0] = fmaf(k4.z, v4.x, acc[2][0]);
            acc[2][1] = fmaf(k4.z, v4.y, acc[2][1]);
            acc[2][2] = fmaf(k4.z, v4.z, acc[2][2]);
            acc[2][3] = fmaf(k4.z, v4.w, acc[2][3]);
            acc[3][0] = fmaf(k4.w, v4.x, acc[3][0]);
            acc[3][1] = fmaf(k4.w, v4.y, acc[3][1]);
            acc[3][2] = fmaf(k4.w, v4.z, acc[3][2]);
            acc[3][3] = fmaf(k4.w, v4.w, acc[3][3]);
            if (tm == 0) {
                ksa[0] += k4.x; ksa[1] += k4.y;
                ksa[2] += k4.z; ksa[3] += k4.w;
            }
        }
        __syncthreads();
    }

    float* o = pkv + ((size_t)ch * 32 + bh) * 4096;
    #pragma unroll
    for (int i = 0; i < 4; i++) {
        float4 v;
        v.x = acc[i][0]; v.y = acc[i][1]; v.z = acc[i][2]; v.w = acc[i][3];
        *(float4*)&o[(td * 4 + i) * 64 + tm * 4] = v;
    }
    if (tm == 0) {
        float* p = pks + ((size_t)ch * 32 + bh) * 64 + td * 4;
        p[0] = ksa[0]; p[1] = ksa[1]; p[2] = ksa[2]; p[3] = ksa[3];
    }
}

// grid (32, 4): float4 reduction, one float4 per thread per y-slice.
__global__ __launch_bounds__(256) void kv_reduce(
    const float* __restrict__ pkv, const float* __restrict__ pks,
    float* __restrict__ kv, float* __restrict__ ks)
{
    const int bh = blockIdx.x, tid = threadIdx.x;
    const int e4 = blockIdx.y * 256 + tid;        // float4 index within 1024
    float4 s; s.x = s.y = s.z = s.w = 0.f;
    #pragma unroll
    for (int c = 0; c < SCH; c++) {
        const float4 v = ((const float4*)pkv)[((size_t)c * 32 + bh) * 1024 + e4];
        s.x += v.x; s.y += v.y; s.z += v.z; s.w += v.w;
    }
    ((float4*)kv)[(size_t)bh * 1024 + e4] = s;
    if (blockIdx.y == 0 && tid < 64) {
        float t = 0.f;
        #pragma unroll
        for (int c = 0; c < SCH; c++) t += pks[((size_t)c * 32 + bh) * 64 + tid];
        ks[bh * 64 + tid] = t;
    }
}

// ---------------------------------------------------------------------------
// attn out: 8-token register batches per warp.
// O[l, h*64+m] = (sum_d Q[l,d] kv[d,m]) / (Q . ksum + eps)
// grid (32, 32), 256 threads.
// ---------------------------------------------------------------------------
__global__ __launch_bounds__(256) void attn_out(
    const fp16* __restrict__ Q, const float* __restrict__ kv,
    const float* __restrict__ ksum, fp16* __restrict__ Oh)
{
    const int bh = blockIdx.x, b = bh >> 3, h = bh & 7;
    __shared__ float kvs[64][64];
    __shared__ float kss[64];
    const int tid = threadIdx.x;
    #pragma unroll
    for (int e = 0; e < 4; e++)
        ((float4*)kvs)[e * 256 + tid] = ((const float4*)kv)[(size_t)bh * 1024 + e * 256 + tid];
    if (tid < 64) kss[tid] = ksum[bh * 64 + tid];
    __syncthreads();

    const int warp = tid >> 5, lane = tid & 31;
    const int lw = blockIdx.y * 128 + warp * 16;

    #pragma unroll
    for (int g = 0; g < 2; g++) {
        const int lt = lw + g * 8;
        float q0[8], q1[8], a0[8], a1[8], z[8];
        #pragma unroll
        for (int t = 0; t < 8; t++) {
            const fp16* q = Q + ((size_t)(b * LSEQ + lt + t)) * DMODEL + h * 64;
            q0[t] = __half2float(q[lane]);
            q1[t] = __half2float(q[lane + 32]);
            a0[t] = 0.f; a1[t] = 0.f;
        }
        const float ks0 = kss[lane], ks1 = kss[lane + 32];
        #pragma unroll
        for (int t = 0; t < 8; t++) {
            float zd = q0[t] * ks0 + q1[t] * ks1;
            #pragma unroll
            for (int o = 16; o > 0; o >>= 1) zd += __shfl_xor_sync(0xffffffffu, zd, o);
            z[t] = 1.f / (zd + 1e-6f);
        }
        #pragma unroll
        for (int dd = 0; dd < 32; dd++) {
            const float kA = kvs[dd][lane], kB = kvs[dd][lane + 32];
            #pragma unroll
            for (int t = 0; t < 8; t++) {
                const float qd = __shfl_sync(0xffffffffu, q0[t], dd);
                a0[t] = fmaf(qd, kA, a0[t]);
                a1[t] = fmaf(qd, kB, a1[t]);
            }
        }
        #pragma unroll
        for (int dd = 0; dd < 32; dd++) {
            const float kA = kvs[dd + 32][lane], kB = kvs[dd + 32][lane + 32];
            #pragma unroll
            for (int t = 0; t < 8; t++) {
                const float qd = __shfl_sync(0xffffffffu, q1[t], dd);
                a0[t] = fmaf(qd, kA, a0[t]);
                a1[t] = fmaf(qd, kB, a1[t]);
            }
        }
        #pragma unroll
        for (int t = 0; t < 8; t++) {
            const size_t op = ((size_t)(b * LSEQ + lt + t)) * DMODEL + h * 64;
            Oh[op + lane]      = __float2half_rn(a0[t] * z[t]);
            Oh[op + lane + 32] = __float2half_rn(a1[t] * z[t]);
        }
    }
}

// ---------------------------------------------------------------------------
// LayerNorm: float4-vectorized. 128 threads x 1 float4 per token.
// ---------------------------------------------------------------------------
__global__ __launch_bounds__(128) void ln_kernel(
    const float* __restrict__ X, const float* __restrict__ R,
    const float* __restrict__ gb, float* __restrict__ Y,
    fp16* __restrict__ Yh)
{
    const int t = blockIdx.x, tid = threadIdx.x;
    float4 v = ((const float4*)(X + (size_t)t * DMODEL))[tid];
    if (R) {
        const float4 rv = ((const float4*)(R + (size_t)t * DMODEL))[tid];
        v.x += rv.x; v.y += rv.y; v.z += rv.z; v.w += rv.w;
    }
    float s = v.x + v.y + v.z + v.w;

    __shared__ float red[4];
    #pragma unroll
    for (int o = 16; o > 0; o >>= 1) s += __shfl_xor_sync(0xffffffffu, s, o);
    if ((tid & 31) == 0) red[tid >> 5] = s;
    __syncthreads();
    const float mu = (red[0] + red[1] + red[2] + red[3]) * (1.f / DMODEL);

    const float dx = v.x - mu, dy = v.y - mu, dz = v.z - mu, dw = v.w - mu;
    float qq = dx * dx + dy * dy + dz * dz + dw * dw;
    #pragma unroll
    for (int o = 16; o > 0; o >>= 1) qq += __shfl_xor_sync(0xffffffffu, qq, o);
    __syncthreads();
    if ((tid & 31) == 0) red[tid >> 5] = qq;
    __syncthreads();
    const float var = (red[0] + red[1] + red[2] + red[3]) * (1.f / DMODEL);
    const float rstd = rsqrtf(var + 1e-5f);

    const float4 g = ((const float4*)gb)[tid];
    const float4 be = ((const float4*)(gb + DMODEL))[tid];
    float4 out;
    out.x = dx * rstd * g.x + be.x;
    out.y = dy * rstd * g.y + be.y;
    out.z = dz * rstd * g.z + be.z;
    out.w = dw * rstd * g.w + be.w;
    ((float4*)(Y + (size_t)t * DMODEL))[tid] = out;
    if (Yh) {
        __half2 h0, h1;
        h0.x = __float2half_rn(out.x); h0.y = __float2half_rn(out.y);
        h1.x = __float2half_rn(out.z); h1.y = __float2half_rn(out.w);
        uint2 pk;
        pk.x = *(uint32_t*)&h0; pk.y = *(uint32_t*)&h1;
        ((uint2*)(Yh + (size_t)t * DMODEL))[tid] = pk;
    }
}

__global__ void embed_kernel(
    const float* __restrict__ x, const float* __restrict__ pe,
    const float* __restrict__ ew, const float* __restrict__ eb,
    float* __restrict__ h, fp16* __restrict__ hh)
{
    const size_t idx = (size_t)blockIdx.x * blockDim.x + threadIdx.x;
    const int tok = (int)(idx >> 9);
    const int j   = (int)(idx & 511);
    const int l   = tok & (LSEQ - 1);
    float val;
    if (j < 256) val = x[(size_t)tok * 2] * ew[j] + x[(size_t)tok * 2 + 1] * ew[256 + j] + eb[j];
    else         val = pe[(size_t)l * 256 + (j - 256)];
    h[idx] = val;
    hh[idx] = __float2half_rn(val);
}

__global__ void dec_init_kernel(const float* __restrict__ ope, float* __restrict__ o,
                                fp16* __restrict__ oh)
{
    const size_t idx = (size_t)blockIdx.x * blockDim.x + threadIdx.x;
    const size_t tok = idx >> 9;
    const float val = ope[((tok & (LSEQ - 1)) << 9) | (idx & 511)];
    o[idx] = val;
    oh[idx] = __float2half_rn(val);
}

__global__ void pred_kernel(
    const float* __restrict__ Xf, const float* __restrict__ pw,
    const float* __restrict__ pb, float* __restrict__ out)
{
    const int gw = (int)(((size_t)blockIdx.x * blockDim.x + threadIdx.x) >> 5);
    const int lane = threadIdx.x & 31;
    if (gw >= NTOK) return;
    const float* xr = Xf + (size_t)gw * DMODEL;
    float a0 = 0.f, a1 = 0.f;
    #pragma unroll 4
    for (int j = lane; j < DMODEL; j += 32) {
        const float v = xr[j];
        a0 = fmaf(v, pw[2 * j],     a0);
        a1 = fmaf(v, pw[2 * j + 1], a1);
    }
    #pragma unroll
    for (int o = 16; o > 0; o >>= 1) {
        a0 += __shfl_xor_sync(0xffffffffu, a0, o);
        a1 += __shfl_xor_sync(0xffffffffu, a1, o);
    }
    if (lane == 0) { out[2 * gw] = a0 + pb[0]; out[2 * gw + 1] = a1 + pb[1]; }
}

// ---------------------------------------------------------------------------
// Host orchestration
// ---------------------------------------------------------------------------
struct Ptrs {
    float *h, *z, *o, *tmp, *pkv, *pks, *kv, *ks;
    fp16 *q, *k, *v;
    fp16 *hh, *zh, *oh, *ath, *fh;
    fp16 *wha, *whf1, *whf2;
};

static void gemm21(const fp16* a, const fp16* b, const float* bias,
                   fp16* Ch, int M, int N, int K) {
    gemm_tc<2,1><<<dim3(N/128, M/128), 256, SMEM_DYN>>>(a, b, bias, nullptr, Ch, M, N, K);
}
static void gemm01(const fp16* a, const fp16* b, const float* bias,
                   fp16* Ch, int M, int N, int K) {
    gemm_tc<0,1><<<dim3(N/128, M/128), 256, SMEM_DYN>>>(a, b, bias, nullptr, Ch, M, N, K);
}
static void gemm00(const fp16* a, const fp16* b, const float* bias,
                   float* C, int M, int N, int K) {
    gemm_tc<0,0><<<dim3(N/128, M/128), 256, SMEM_DYN>>>(a, b, bias, C, nullptr, M, N, K);
}
static void gemm11(const fp16* a, const fp16* b, const float* bias,
                   fp16* Ch, int M, int N, int K) {
    gemm_tc<1,1><<<dim3(N/128, M/128), 256, SMEM_DYN>>>(a, b, bias, nullptr, Ch, M, N, K);
}

static void attention_block(const fp16* xqh, const fp16* xkh,
                            const fp16* wh, const float* b, const Ptrs& P)
{
    const size_t WS = (size_t)DMODEL * DMODEL;
    gemm21(xqh, wh + 0 * WS, b + 0 * DMODEL, P.q, NTOK, DMODEL, DMODEL);
    gemm21(xkh, wh + 1 * WS, b + 1 * DMODEL, P.k, NTOK, DMODEL, DMODEL);
    gemm01(xkh, wh + 2 * WS, b + 2 * DMODEL, P.v, NTOK, DMODEL, DMODEL);

    kv_partial<<<dim3(32, SCH), 256>>>(P.k, P.v, P.pkv, P.pks);
    kv_reduce<<<dim3(32, 4), 256>>>(P.pkv, P.pks, P.kv, P.ks);
    attn_out<<<dim3(32, 32), 256>>>(P.q, P.kv, P.ks, P.ath);

    gemm00(P.ath, wh + 3 * WS, b + 3 * DMODEL, P.tmp, NTOK, DMODEL, DMODEL);
}

extern "C" void kernel_launch(void* const* d_in, const int* in_sizes, int n_in,
                              void* d_out, int out_size)
{
    const float* x            = (const float*)d_in[0];
    const float* out_pos_emb  = (const float*)d_in[1];
    const float* pe_input     = (const float*)d_in[2];
    const float* emb_w        = (const float*)d_in[3];
    const float* emb_b        = (const float*)d_in[4];
    const float* enc_attn_w   = (const float*)d_in[5];
    const float* enc_attn_b   = (const float*)d_in[6];
    const float* enc_ln       = (const float*)d_in[7];
    const float* enc_ff_w1    = (const float*)d_in[8];
    const float* enc_ff_b1    = (const float*)d_in[9];
    const float* enc_ff_w2    = (const float*)d_in[10];
    const float* enc_ff_b2    = (const float*)d_in[11];
    const float* enc_final_ln = (const float*)d_in[12];
    const float* dec_self_w   = (const float*)d_in[13];
    const float* dec_self_b   = (const float*)d_in[14];
    const float* dec_cross_w  = (const float*)d_in[15];
    const float* dec_cross_b  = (const float*)d_in[16];
    const float* dec_ln       = (const float*)d_in[17];
    const float* dec_ff_w1    = (const float*)d_in[18];
    const float* dec_ff_b1    = (const float*)d_in[19];
    const float* dec_ff_w2    = (const float*)d_in[20];
    const float* dec_ff_b2    = (const float*)d_in[21];
    const float* dec_final_ln = (const float*)d_in[22];
    const float* pred_w       = (const float*)d_in[23];
    const float* pred_b       = (const float*)d_in[24];

    cudaFuncSetAttribute(gemm_tc<2,1>, cudaFuncAttributeMaxDynamicSharedMemorySize, SMEM_DYN);
    cudaFuncSetAttribute(gemm_tc<0,1>, cudaFuncAttributeMaxDynamicSharedMemorySize, SMEM_DYN);
    cudaFuncSetAttribute(gemm_tc<0,0>, cudaFuncAttributeMaxDynamicSharedMemorySize, SMEM_DYN);
    cudaFuncSetAttribute(gemm_tc<1,1>, cudaFuncAttributeMaxDynamicSharedMemorySize, SMEM_DYN);

    unsigned char* S = nullptr;
    cudaGetSymbolAddress((void**)&S, g_scratch);

    Ptrs P;
    P.h   = (float*)(S + B_H);   P.z   = (float*)(S + B_Z);   P.o  = (float*)(S + B_O);
    P.tmp = (float*)(S + B_TMP);
    P.q   = (fp16*)(S + B_Q);    P.k   = (fp16*)(S + B_K);    P.v  = (fp16*)(S + B_V);
    P.pkv = (float*)(S + B_PKV); P.pks = (float*)(S + B_PKS);
    P.kv  = (float*)(S + B_KVB); P.ks  = (float*)(S + B_KSB);
    P.hh  = (fp16*)(S + B_HH);   P.zh  = (fp16*)(S + B_ZH);
    P.oh  = (fp16*)(S + B_OH);   P.ath = (fp16*)(S + B_ATH);
    P.fh  = (fp16*)(S + B_FH);
    P.wha = (fp16*)(S + B_WHA);
    P.whf1 = (fp16*)(S + B_WHF1);
    P.whf2 = (fp16*)(S + B_WHF2);

    // ---- transpose + fp16-round all weights ----
    transpose_w16<<<dim3(16, 16, 16), 256>>>(enc_attn_w,  P.wha,                     512, 512);
    transpose_w16<<<dim3(16, 16, 16), 256>>>(dec_self_w,  P.wha + (size_t)16*262144, 512, 512);
    transpose_w16<<<dim3(16, 16, 16), 256>>>(dec_cross_w, P.wha + (size_t)32*262144, 512, 512);
    transpose_w16<<<dim3(64, 16, 4),  256>>>(enc_ff_w1, P.whf1,                      512, 2048);
    transpose_w16<<<dim3(64, 16, 4),  256>>>(dec_ff_w1, P.whf1 + (size_t)4*1048576,  512, 2048);
    transpose_w16<<<dim3(16, 64, 4),  256>>>(enc_ff_w2, P.whf2,                      2048, 512);
    transpose_w16<<<dim3(16, 64, 4),  256>>>(dec_ff_w2, P.whf2 + (size_t)4*1048576,  2048, 512);

    const size_t WT4 = (size_t)4 * DMODEL * DMODEL;
    const size_t W1S = (size_t)DFF * DMODEL;
    const size_t W2S = (size_t)DMODEL * DFF;

    // ---- embed ----
    embed_kernel<<<(NTOK * DMODEL) / 256, 256>>>(x, pe_input, emb_w, emb_b, P.h, P.hh);

    // ---- encoder ----
    for (int l = 0; l < 4; l++) {
        const float* ln = enc_ln + (size_t)l * 2 * 2 * DMODEL;
        attention_block(P.hh, P.hh, P.wha + (size_t)l * WT4,
                        enc_attn_b + (size_t)l * 4 * DMODEL, P);
        ln_kernel<<<NTOK, 128>>>(P.h, P.tmp, ln, P.h, P.hh);
        gemm11(P.hh, P.whf1 + (size_t)l * W1S,
               enc_ff_b1 + (size_t)l * DFF, P.fh, NTOK, DFF, DMODEL);
        gemm00(P.fh, P.whf2 + (size_t)l * W2S,
               enc_ff_b2 + (size_t)l * DMODEL, P.tmp, NTOK, DMODEL, DFF);
        ln_kernel<<<NTOK, 128>>>(P.h, P.tmp, ln + 2 * DMODEL, P.h, P.hh);
    }
    ln_kernel<<<NTOK, 128>>>(P.h, nullptr, enc_final_ln, P.z, P.zh);

    // ---- decoder ----
    dec_init_kernel<<<(NTOK * DMODEL) / 256, 256>>>(out_pos_emb, P.o, P.oh);
    for (int l = 0; l < 4; l++) {
        const float* ln = dec_ln + (size_t)l * 3 * 2 * DMODEL;
        attention_block(P.oh, P.oh,
                        P.wha + (size_t)(16 + l * 4) * DMODEL * DMODEL,
                        dec_self_b + (size_t)l * 4 * DMODEL, P);
        ln_kernel<<<NTOK, 128>>>(P.o, P.tmp, ln, P.o, P.oh);
        attention_block(P.oh, P.zh,
                        P.wha + (size_t)(32 + l * 4) * DMODEL * DMODEL,
                        dec_cross_b + (size_t)l * 4 * DMODEL, P);
        ln_kernel<<<NTOK, 128>>>(P.o, P.tmp, ln + 2 * DMODEL, P.o, P.oh);
        gemm11(P.oh, P.whf1 + (size_t)(4 + l) * W1S,
               dec_ff_b1 + (size_t)l * DFF, P.fh, NTOK, DFF, DMODEL);
        gemm00(P.fh, P.whf2 + (size_t)(4 + l) * W2S,
               dec_ff_b2 + (size_t)l * DMODEL, P.tmp, NTOK, DMODEL, DFF);
        ln_kernel<<<NTOK, 128>>>(P.o, P.tmp, ln + 4 * DMODEL, P.o, P.oh);
    }
    ln_kernel<<<NTOK, 128>>>(P.o, nullptr, dec_final_ln, P.tmp, nullptr);

    // ---- prediction head ----
    pred_kernel<<<(NTOK * 32) / 256, 256>>>(P.tmp, pred_w, pred_b, (float*)d_out);
}

// round 12
// speedup vs baseline: 1.9690x; 1.0213x over previous
#include <cuda_runtime.h>
#include <cuda_fp16.h>
#include <cstdint>
#include <cstddef>

// ---------------------------------------------------------------------------
// TRecTransformer: linear-attention encoder/decoder.
// GEMMs: plain fp16 mma.sync m16n8k16 (fp32 accum). Q/K/V fp16.
// This round: MLP-4 LayerNorm (4 tokens/CTA), fused Q|K projection (ldc),
// vectorized embed/dec_init, fp16 prediction head input.
// ---------------------------------------------------------------------------

#define NTOK   16384
#define DMODEL 512
#define DFF    2048
#define LSEQ   4096
#define SCH    16

#define SZ ((size_t)NTOK * DMODEL)        // 8,388,608 elements

// ---- scratch layout (BYTE offsets) ----
#define B_H     ((size_t)0)
#define B_Z     (B_H   + SZ*4)
#define B_O     (B_Z   + SZ*4)
#define B_TMP   (B_O   + SZ*4)
#define B_QK    (B_TMP + SZ*4)            // fp16 [NTOK,1024]: Q cols 0-511, K 512-1023
#define B_V     (B_QK  + SZ*4)
#define B_PKV   (B_V   + SZ*4)
#define B_PKS   (B_PKV + (size_t)SCH*32*4096*4)
#define B_KVB   (B_PKS + (size_t)SCH*32*64*4)
#define B_KSB   (B_KVB + (size_t)32*4096*4)
// fp16 activations (single-rounded)
#define B_HH    (B_KSB + (size_t)32*64*4)
#define B_ZH    (B_HH  + SZ*2)
#define B_OH    (B_ZH  + SZ*2)
#define B_ATH   (B_OH  + SZ*2)
#define B_FH    (B_ATH + SZ*2)            // NTOK*DFF halves
// fp16 weights (single-rounded, transposed to [N,K])
#define B_WHA   (B_FH  + SZ*8)            // 48 x 512x512
#define B_WHF1  (B_WHA + (size_t)48*262144*2)   // 8 x [2048,512]
#define B_WHF2  (B_WHF1 + (size_t)8*1048576*2)  // 8 x [512,2048]
#define TOTAL_B (B_WHF2 + (size_t)8*1048576*2)

__device__ __align__(1024) unsigned char g_scratch[TOTAL_B];

typedef __half fp16;

// ---------------------------------------------------------------------------
// helpers
// ---------------------------------------------------------------------------
__device__ __forceinline__ uint32_t smem_u32(const void* p) {
    uint32_t a;
    asm("{ .reg .u64 t; cvta.to.shared.u64 t, %1; cvt.u32.u64 %0, t; }" : "=r"(a) : "l"(p));
    return a;
}
__device__ __forceinline__ void ldsm4(uint32_t* r, uint32_t addr) {
    asm volatile("ldmatrix.sync.aligned.m8n8.x4.shared.b16 {%0,%1,%2,%3}, [%4];"
        : "=r"(r[0]), "=r"(r[1]), "=r"(r[2]), "=r"(r[3]) : "r"(addr));
}
__device__ __forceinline__ void mma_f16(float* c, const uint32_t* a, const uint32_t* b) {
    asm volatile(
        "mma.sync.aligned.m16n8k16.row.col.f32.f16.f16.f32 "
        "{%0,%1,%2,%3}, {%4,%5,%6,%7}, {%8,%9}, {%0,%1,%2,%3};"
        : "+f"(c[0]), "+f"(c[1]), "+f"(c[2]), "+f"(c[3])
        : "r"(a[0]), "r"(a[1]), "r"(a[2]), "r"(a[3]), "r"(b[0]), "r"(b[1]));
}
__device__ __forceinline__ void cp16(uint32_t d, const void* s) {
    asm volatile("cp.async.cg.shared.global [%0], [%1], 16;" :: "r"(d), "l"(s));
}
__device__ __forceinline__ void cp_commit() { asm volatile("cp.async.commit_group;" ::: "memory"); }
__device__ __forceinline__ void cp_wait1()  { asm volatile("cp.async.wait_group 1;" ::: "memory"); }
__device__ __forceinline__ void cp_wait0()  { asm volatile("cp.async.wait_group 0;" ::: "memory"); }

// ---------------------------------------------------------------------------
// GEMM: C[M,N] = act(A[M,K] @ W[N,K]^T + bias). fp16 mma.sync, fp32 accum.
// 128x128 tile, Kc=32, 256 threads, 3-stage cp.async pipeline. Output row
// stride ldc (allows writing into a wider buffer).
// ACT: 0 none, 1 relu, 2 phi=elu+1.  OUTBF: 0 -> fp32 C, 1 -> fp16 Ch.
// ---------------------------------------------------------------------------
#define ROWB 80
#define MATB 10240
#define STGB 20480
#define SMEM_DYN (3 * STGB)

template<int ACT, int OUTBF>
__global__ __launch_bounds__(256) void gemm_tc(
    const fp16* __restrict__ A, const fp16* __restrict__ B,
    const float* __restrict__ bias,
    float* __restrict__ C, fp16* __restrict__ Ch,
    int M, int N, int K, int ldc)
{
    extern __shared__ char smc[];
    const uint32_t smB = smem_u32(smc);

    const int tid = threadIdx.x, lane = tid & 31, wid = tid >> 5;
    const int row0 = blockIdx.y * 128, col0 = blockIdx.x * 128;
    const int wm = wid & 1, wn = wid >> 1;       // 2 x 4 warp grid

    float acc[4][4][4];
    #pragma unroll
    for (int i = 0; i < 4; i++)
        #pragma unroll
        for (int j = 0; j < 4; j++)
            #pragma unroll
            for (int e = 0; e < 4; e++) acc[i][j][e] = 0.f;

    const uint32_t aoff = (uint32_t)((wm * 64 + (lane & 7) + ((lane >> 3) & 1) * 8) * ROWB
                                     + (lane >> 4) * 16);
    const uint32_t boff = (uint32_t)((wn * 32 + (lane >> 4) * 8 + (lane & 7)) * ROWB
                                     + ((lane >> 3) & 1) * 16);

    const int NC = K / 32;
    const int pr = tid >> 2;             // producer row within 64-row half
    const int pb = (tid & 3) * 16;       // byte offset within 64B row chunk

    auto loadst = [&](int c, int s) {
        const int k0 = c * 32;
        const uint32_t st = smB + (uint32_t)s * STGB;
        #pragma unroll
        for (int m = 0; m < 2; m++) {
            const fp16* g = (m == 0) ? A : B;
            const int rb = (m == 0) ? row0 : col0;
            #pragma unroll
            for (int hf = 0; hf < 2; hf++) {
                const int r = hf * 64 + pr;
                cp16(st + m * MATB + r * ROWB + pb,
                     (const char*)(g + (size_t)(rb + r) * K + k0) + pb);
            }
        }
    };

    auto compute = [&](int s) {
        const uint32_t base = smB + (uint32_t)s * STGB;
        #pragma unroll
        for (int ks = 0; ks < 2; ks++) {
            uint32_t ar[4][4], br[4][2];
            #pragma unroll
            for (int mi = 0; mi < 4; mi++)
                ldsm4(ar[mi], base + aoff + mi * 1280 + ks * 32);
            #pragma unroll
            for (int j = 0; j < 2; j++) {
                uint32_t t[4];
                ldsm4(t, base + MATB + boff + j * 1280 + ks * 32);
                br[2 * j][0] = t[0]; br[2 * j][1] = t[1];
                br[2 * j + 1][0] = t[2]; br[2 * j + 1][1] = t[3];
            }
            #pragma unroll
            for (int mi = 0; mi < 4; mi++)
                #pragma unroll
                for (int ni = 0; ni < 4; ni++) mma_f16(acc[mi][ni], ar[mi], br[ni]);
        }
    };

    loadst(0, 0); cp_commit();
    loadst(1, 1); cp_commit();
    for (int c = 0; c < NC; c++) {
        if (c + 1 < NC) cp_wait1(); else cp_wait0();
        __syncthreads();
        compute(c % 3);
        if (c + 2 < NC) { loadst(c + 2, (c + 2) % 3); cp_commit(); }
    }

    // epilogue
    const int gm0 = row0 + wm * 64;
    const int gn0 = col0 + wn * 32;
    #pragma unroll
    for (int ni = 0; ni < 4; ni++) {
        const int cn = gn0 + ni * 8 + (lane & 3) * 2;
        const float b0 = bias[cn], b1 = bias[cn + 1];
        #pragma unroll
        for (int mi = 0; mi < 4; mi++) {
            const int rm = gm0 + mi * 16 + (lane >> 2);
            float t0 = acc[mi][ni][0] + b0;
            float t1 = acc[mi][ni][1] + b1;
            float t2 = acc[mi][ni][2] + b0;
            float t3 = acc[mi][ni][3] + b1;
            if (ACT == 1) {
                t0 = fmaxf(t0, 0.f); t1 = fmaxf(t1, 0.f);
                t2 = fmaxf(t2, 0.f); t3 = fmaxf(t3, 0.f);
            }
            if (ACT == 2) {
                t0 = t0 > 0.f ? t0 + 1.f : __expf(t0);
                t1 = t1 > 0.f ? t1 + 1.f : __expf(t1);
                t2 = t2 > 0.f ? t2 + 1.f : __expf(t2);
                t3 = t3 > 0.f ? t3 + 1.f : __expf(t3);
            }
            if (OUTBF == 0) {
                float2 v0; v0.x = t0; v0.y = t1;
                float2 v1; v1.x = t2; v1.y = t3;
                *(float2*)&C[(size_t)rm * ldc + cn]       = v0;
                *(float2*)&C[(size_t)(rm + 8) * ldc + cn] = v1;
            } else {
                __half2 hp;
                hp.x = __float2half_rn(t0); hp.y = __float2half_rn(t1);
                *(__half2*)&Ch[(size_t)rm * ldc + cn] = hp;
                hp.x = __float2half_rn(t2); hp.y = __float2half_rn(t3);
                *(__half2*)&Ch[(size_t)(rm + 8) * ldc + cn] = hp;
            }
        }
    }
}

// ---------------------------------------------------------------------------
// fused weight transpose + fp16 round: W[K,N] fp32 -> Wh [N,K] fp16
// ---------------------------------------------------------------------------
__global__ __launch_bounds__(256) void transpose_w16(
    const float* __restrict__ W, fp16* __restrict__ Wh, int K, int N)
{
    __shared__ float t[32][33];
    const size_t mo = (size_t)blockIdx.z * K * N;
    const float* Wm = W + mo;
    const int n0 = blockIdx.x * 32, k0 = blockIdx.y * 32;
    const int tx = threadIdx.x & 31, ty = threadIdx.x >> 5;
    #pragma unroll
    for (int i = 0; i < 32; i += 8)
        t[ty + i][tx] = Wm[(size_t)(k0 + ty + i) * N + n0 + tx];
    __syncthreads();
    #pragma unroll
    for (int i = 0; i < 32; i += 8)
        Wh[mo + (size_t)(n0 + ty + i) * K + k0 + tx] = __float2half_rn(t[tx][ty + i]);
}

// ---------------------------------------------------------------------------
// kv partial: register-tiled 4x4 outer product per thread. K,V row strides.
// ---------------------------------------------------------------------------
__global__ __launch_bounds__(256) void kv_partial(
    const fp16* __restrict__ Kt, int ldk,
    const fp16* __restrict__ Vt, int ldv,
    float* __restrict__ pkv, float* __restrict__ pks)
{
    const int bh = blockIdx.x, ch = blockIdx.y;
    const int b = bh >> 3, h = bh & 7;
    const int tid = threadIdx.x;
    __shared__ float Ks[8][64], Vs[8][64];

    float acc[4][4];
    #pragma unroll
    for (int i = 0; i < 4; i++)
        #pragma unroll
        for (int j = 0; j < 4; j++) acc[i][j] = 0.f;
    float ksa[4] = {0.f, 0.f, 0.f, 0.f};

    const int td = tid >> 4, tm = tid & 15;
    const int s0 = ch * (LSEQ / SCH);
    const int lr = tid >> 5, lc = (tid & 31) * 2;

    for (int s = s0; s < s0 + LSEQ / SCH; s += 8) {
        const size_t row = (size_t)(b * LSEQ + s + lr);
        const float2 kf = __half22float2(*(const __half2*)(Kt + row * ldk + h * 64 + lc));
        const float2 vf = __half22float2(*(const __half2*)(Vt + row * ldv + h * 64 + lc));
        *(float2*)&Ks[lr][lc] = kf;
        *(float2*)&Vs[lr][lc] = vf;
        __syncthreads();
        #pragma unroll
        for (int rr = 0; rr < 8; rr++) {
            const float4 k4 = *(const float4*)&Ks[rr][td * 4];
            const float4 v4 = *(const float4*)&Vs[rr][tm * 4];
            acc[0][0] = fmaf(k4.x, v4.x, acc[0][0]);
            acc[0][1] = fmaf(k4.x, v4.y, acc[0][1]);
            acc[0][2] = fmaf(k4.x, v4.z, acc[0][2]);
            acc[0][3] = fmaf(k4.x, v4.w, acc[0][3]);
            acc[1][0] = fmaf(k4.y, v4.x, acc[1][0]);
            acc[1][1] = fmaf(k4.y, v4.y, acc[1][1]);
            acc[1][2] = fmaf(k4.y, v4.z, acc[1][2]);
            acc[1][3] = fmaf(k4.y, v4.w, acc[1][3]);
            acc[2][0] = fmaf(k4.z, v4.x, acc[2][0]);
            acc[2][1] = fmaf(k4.z, v4.y, acc[2][1]);
            acc[2][2] = fmaf(k4.z, v4.z, acc[2][2]);
            acc[2][3] = fmaf(k4.z, v4.w, acc[2][3]);
            acc[3][0] = fmaf(k4.w, v4.x, acc[3][0]);
            acc[3][1] = fmaf(k4.w, v4.y, acc[3][1]);
            acc[3][2] = fmaf(k4.w, v4.z, acc[3][2]);
            acc[3][3] = fmaf(k4.w, v4.w, acc[3][3]);
            if (tm == 0) {
                ksa[0] += k4.x; ksa[1] += k4.y;
                ksa[2] += k4.z; ksa[3] += k4.w;
            }
        }
        __syncthreads();
    }

    float* o = pkv + ((size_t)ch * 32 + bh) * 4096;
    #pragma unroll
    for (int i = 0; i < 4; i++) {
        float4 v;
        v.x = acc[i][0]; v.y = acc[i][1]; v.z = acc[i][2]; v.w = acc[i][3];
        *(float4*)&o[(td * 4 + i) * 64 + tm * 4] = v;
    }
    if (tm == 0) {
        float* p = pks + ((size_t)ch * 32 + bh) * 64 + td * 4;
        p[0] = ksa[0]; p[1] = ksa[1]; p[2] = ksa[2]; p[3] = ksa[3];
    }
}

__global__ __launch_bounds__(256) void kv_reduce(
    const float* __restrict__ pkv, const float* __restrict__ pks,
    float* __restrict__ kv, float* __restrict__ ks)
{
    const int bh = blockIdx.x, tid = threadIdx.x;
    const int e4 = blockIdx.y * 256 + tid;
    float4 s; s.x = s.y = s.z = s.w = 0.f;
    #pragma unroll
    for (int c = 0; c < SCH; c++) {
        const float4 v = ((const float4*)pkv)[((size_t)c * 32 + bh) * 1024 + e4];
        s.x += v.x; s.y += v.y; s.z += v.z; s.w += v.w;
    }
    ((float4*)kv)[(size_t)bh * 1024 + e4] = s;
    if (blockIdx.y == 0 && tid < 64) {
        float t = 0.f;
        #pragma unroll
        for (int c = 0; c < SCH; c++) t += pks[((size_t)c * 32 + bh) * 64 + tid];
        ks[bh * 64 + tid] = t;
    }
}

// ---------------------------------------------------------------------------
// attn out: 8-token register batches per warp. Q row stride ldq.
// ---------------------------------------------------------------------------
__global__ __launch_bounds__(256) void attn_out(
    const fp16* __restrict__ Q, int ldq, const float* __restrict__ kv,
    const float* __restrict__ ksum, fp16* __restrict__ Oh)
{
    const int bh = blockIdx.x, b = bh >> 3, h = bh & 7;
    __shared__ float kvs[64][64];
    __shared__ float kss[64];
    const int tid = threadIdx.x;
    #pragma unroll
    for (int e = 0; e < 4; e++)
        ((float4*)kvs)[e * 256 + tid] = ((const float4*)kv)[(size_t)bh * 1024 + e * 256 + tid];
    if (tid < 64) kss[tid] = ksum[bh * 64 + tid];
    __syncthreads();

    const int warp = tid >> 5, lane = tid & 31;
    const int lw = blockIdx.y * 128 + warp * 16;

    #pragma unroll
    for (int g = 0; g < 2; g++) {
        const int lt = lw + g * 8;
        float q0[8], q1[8], a0[8], a1[8], z[8];
        #pragma unroll
        for (int t = 0; t < 8; t++) {
            const fp16* q = Q + (size_t)(b * LSEQ + lt + t) * ldq + h * 64;
            q0[t] = __half2float(q[lane]);
            q1[t] = __half2float(q[lane + 32]);
            a0[t] = 0.f; a1[t] = 0.f;
        }
        const float ks0 = kss[lane], ks1 = kss[lane + 32];
        #pragma unroll
        for (int t = 0; t < 8; t++) {
            float zd = q0[t] * ks0 + q1[t] * ks1;
            #pragma unroll
            for (int o = 16; o > 0; o >>= 1) zd += __shfl_xor_sync(0xffffffffu, zd, o);
            z[t] = 1.f / (zd + 1e-6f);
        }
        #pragma unroll
        for (int dd = 0; dd < 32; dd++) {
            const float kA = kvs[dd][lane], kB = kvs[dd][lane + 32];
            #pragma unroll
            for (int t = 0; t < 8; t++) {
                const float qd = __shfl_sync(0xffffffffu, q0[t], dd);
                a0[t] = fmaf(qd, kA, a0[t]);
                a1[t] = fmaf(qd, kB, a1[t]);
            }
        }
        #pragma unroll
        for (int dd = 0; dd < 32; dd++) {
            const float kA = kvs[dd + 32][lane], kB = kvs[dd + 32][lane + 32];
            #pragma unroll
            for (int t = 0; t < 8; t++) {
                const float qd = __shfl_sync(0xffffffffu, q1[t], dd);
                a0[t] = fmaf(qd, kA, a0[t]);
                a1[t] = fmaf(qd, kB, a1[t]);
            }
        }
        #pragma unroll
        for (int t = 0; t < 8; t++) {
            const size_t op = ((size_t)(b * LSEQ + lt + t)) * DMODEL + h * 64;
            Oh[op + lane]      = __float2half_rn(a0[t] * z[t]);
            Oh[op + lane + 32] = __float2half_rn(a1[t] * z[t]);
        }
    }
}

// ---------------------------------------------------------------------------
// LayerNorm: 4 tokens per 256-thread CTA; 64 threads/token; each thread
// loads 2 float4 of X and 2 of R (front-batched, MLP 4).
// Y nullable (fp32), Yh nullable (fp16).
// ---------------------------------------------------------------------------
__global__ __launch_bounds__(256) void ln_kernel(
    const float* __restrict__ X, const float* __restrict__ R,
    const float* __restrict__ gb, float* __restrict__ Y,
    fp16* __restrict__ Yh)
{
    const int tid = threadIdx.x;
    const int tok = blockIdx.x * 4 + (tid >> 6);
    const int u = tid & 63;                     // thread within token
    const size_t base4 = (size_t)tok * 128;     // float4 row base

    float4 va = ((const float4*)X)[base4 + u];
    float4 vb = ((const float4*)X)[base4 + u + 64];
    if (R) {
        const float4 ra = ((const float4*)R)[base4 + u];
        const float4 rb = ((const float4*)R)[base4 + u + 64];
        va.x += ra.x; va.y += ra.y; va.z += ra.z; va.w += ra.w;
        vb.x += rb.x; vb.y += rb.y; vb.z += rb.z; vb.w += rb.w;
    }
    float s = va.x + va.y + va.z + va.w + vb.x + vb.y + vb.z + vb.w;

    __shared__ float redS[4][2], redQ[4][2];
    const int tk = tid >> 6, w2 = (tid >> 5) & 1;
    #pragma unroll
    for (int o = 16; o > 0; o >>= 1) s += __shfl_xor_sync(0xffffffffu, s, o);
    if ((tid & 31) == 0) redS[tk][w2] = s;
    __syncthreads();
    const float mu = (redS[tk][0] + redS[tk][1]) * (1.f / DMODEL);

    const float ax = va.x - mu, ay = va.y - mu, az = va.z - mu, aw = va.w - mu;
    const float bx = vb.x - mu, by = vb.y - mu, bz = vb.z - mu, bw = vb.w - mu;
    float qq = ax * ax + ay * ay + az * az + aw * aw
             + bx * bx + by * by + bz * bz + bw * bw;
    #pragma unroll
    for (int o = 16; o > 0; o >>= 1) qq += __shfl_xor_sync(0xffffffffu, qq, o);
    if ((tid & 31) == 0) redQ[tk][w2] = qq;
    __syncthreads();
    const float var = (redQ[tk][0] + redQ[tk][1]) * (1.f / DMODEL);
    const float rstd = rsqrtf(var + 1e-5f);

    const float4 ga = ((const float4*)gb)[u];
    const float4 gc = ((const float4*)gb)[u + 64];
    const float4 ba = ((const float4*)(gb + DMODEL))[u];
    const float4 bc = ((const float4*)(gb + DMODEL))[u + 64];
    float4 oa, ob;
    oa.x = ax * rstd * ga.x + ba.x;  oa.y = ay * rstd * ga.y + ba.y;
    oa.z = az * rstd * ga.z + ba.z;  oa.w = aw * rstd * ga.w + ba.w;
    ob.x = bx * rstd * gc.x + bc.x;  ob.y = by * rstd * gc.y + bc.y;
    ob.z = bz * rstd * gc.z + bc.z;  ob.w = bw * rstd * gc.w + bc.w;
    if (Y) {
        ((float4*)Y)[base4 + u]      = oa;
        ((float4*)Y)[base4 + u + 64] = ob;
    }
    if (Yh) {
        __half2 h0, h1;
        uint2 pk;
        h0.x = __float2half_rn(oa.x); h0.y = __float2half_rn(oa.y);
        h1.x = __float2half_rn(oa.z); h1.y = __float2half_rn(oa.w);
        pk.x = *(uint32_t*)&h0; pk.y = *(uint32_t*)&h1;
        ((uint2*)Yh)[base4 + u] = pk;
        h0.x = __float2half_rn(ob.x); h0.y = __float2half_rn(ob.y);
        h1.x = __float2half_rn(ob.z); h1.y = __float2half_rn(ob.w);
        pk.x = *(uint32_t*)&h0; pk.y = *(uint32_t*)&h1;
        ((uint2*)Yh)[base4 + u + 64] = pk;
    }
}

// embed: 4 consecutive elements per thread.
__global__ void embed_kernel(
    const float* __restrict__ x, const float* __restrict__ pe,
    const float* __restrict__ ew, const float* __restrict__ eb,
    float* __restrict__ h, fp16* __restrict__ hh)
{
    const size_t i4 = (size_t)blockIdx.x * blockDim.x + threadIdx.x;
    const int tok = (int)(i4 >> 7);
    const int j4  = (int)(i4 & 127);
    const int j   = j4 * 4;
    const int l   = tok & (LSEQ - 1);
    float4 v;
    if (j < 256) {
        const float x0 = x[(size_t)tok * 2], x1 = x[(size_t)tok * 2 + 1];
        const float4 w0 = *(const float4*)(ew + j);
        const float4 w1 = *(const float4*)(ew + 256 + j);
        const float4 b  = *(const float4*)(eb + j);
        v.x = x0 * w0.x + x1 * w1.x + b.x;
        v.y = x0 * w0.y + x1 * w1.y + b.y;
        v.z = x0 * w0.z + x1 * w1.z + b.z;
        v.w = x0 * w0.w + x1 * w1.w + b.w;
    } else {
        v = *(const float4*)(pe + (size_t)l * 256 + (j - 256));
    }
    ((float4*)h)[i4] = v;
    __half2 h0, h1;
    h0.x = __float2half_rn(v.x); h0.y = __float2half_rn(v.y);
    h1.x = __float2half_rn(v.z); h1.y = __float2half_rn(v.w);
    uint2 pk; pk.x = *(uint32_t*)&h0; pk.y = *(uint32_t*)&h1;
    ((uint2*)hh)[i4] = pk;
}

__global__ void dec_init_kernel(const float* __restrict__ ope, float* __restrict__ o,
                                fp16* __restrict__ oh)
{
    const size_t i4 = (size_t)blockIdx.x * blockDim.x + threadIdx.x;
    const size_t tok = i4 >> 7;
    const float4 v = ((const float4*)ope)[((tok & (LSEQ - 1)) << 7) | (i4 & 127)];
    ((float4*)o)[i4] = v;
    __half2 h0, h1;
    h0.x = __float2half_rn(v.x); h0.y = __float2half_rn(v.y);
    h1.x = __float2half_rn(v.z); h1.y = __float2half_rn(v.w);
    uint2 pk; pk.x = *(uint32_t*)&h0; pk.y = *(uint32_t*)&h1;
    ((uint2*)oh)[i4] = pk;
}

// prediction head: reads fp16 input.
__global__ void pred_kernel(
    const fp16* __restrict__ Xh, const float* __restrict__ pw,
    const float* __restrict__ pb, float* __restrict__ out)
{
    const int gw = (int)(((size_t)blockIdx.x * blockDim.x + threadIdx.x) >> 5);
    const int lane = threadIdx.x & 31;
    if (gw >= NTOK) return;
    const fp16* xr = Xh + (size_t)gw * DMODEL;
    float a0 = 0.f, a1 = 0.f;
    #pragma unroll 4
    for (int j = lane; j < DMODEL; j += 32) {
        const float v = __half2float(xr[j]);
        a0 = fmaf(v, pw[2 * j],     a0);
        a1 = fmaf(v, pw[2 * j + 1], a1);
    }
    #pragma unroll
    for (int o = 16; o > 0; o >>= 1) {
        a0 += __shfl_xor_sync(0xffffffffu, a0, o);
        a1 += __shfl_xor_sync(0xffffffffu, a1, o);
    }
    if (lane == 0) { out[2 * gw] = a0 + pb[0]; out[2 * gw + 1] = a1 + pb[1]; }
}

// ---------------------------------------------------------------------------
// Host orchestration
// ---------------------------------------------------------------------------
struct Ptrs {
    float *h, *z, *o, *tmp, *pkv, *pks, *kv, *ks;
    fp16 *qk, *v;
    fp16 *hh, *zh, *oh, *ath, *fh;
    fp16 *wha, *whf1, *whf2;
};

static void gemm21(const fp16* a, const fp16* b, const float* bias,
                   fp16* Ch, int M, int N, int K, int ldc) {
    gemm_tc<2,1><<<dim3(N/128, M/128), 256, SMEM_DYN>>>(a, b, bias, nullptr, Ch, M, N, K, ldc);
}
static void gemm01(const fp16* a, const fp16* b, const float* bias,
                   fp16* Ch, int M, int N, int K, int ldc) {
    gemm_tc<0,1><<<dim3(N/128, M/128), 256, SMEM_DYN>>>(a, b, bias, nullptr, Ch, M, N, K, ldc);
}
static void gemm00(const fp16* a, const fp16* b, const float* bias,
                   float* C, int M, int N, int K) {
    gemm_tc<0,0><<<dim3(N/128, M/128), 256, SMEM_DYN>>>(a, b, bias, C, nullptr, M, N, K, N);
}
static void gemm11(const fp16* a, const fp16* b, const float* bias,
                   fp16* Ch, int M, int N, int K) {
    gemm_tc<1,1><<<dim3(N/128, M/128), 256, SMEM_DYN>>>(a, b, bias, nullptr, Ch, M, N, K, N);
}

// self-attention: fused Q|K GEMM (N=1024, both phi) into qk[NTOK,1024].
static void attention_self(const fp16* xh, const fp16* wh, const float* b, const Ptrs& P)
{
    gemm21(xh, wh, b, P.qk, NTOK, 1024, DMODEL, 1024);
    gemm01(xh, wh + (size_t)2 * DMODEL * DMODEL, b + 2 * DMODEL, P.v, NTOK, DMODEL, DMODEL, DMODEL);

    kv_partial<<<dim3(32, SCH), 256>>>(P.qk + 512, 1024, P.v, 512, P.pkv, P.pks);
    kv_reduce<<<dim3(32, 4), 256>>>(P.pkv, P.pks, P.kv, P.ks);
    attn_out<<<dim3(32, 32), 256>>>(P.qk, 1024, P.kv, P.ks, P.ath);

    gemm00(P.ath, wh + (size_t)3 * DMODEL * DMODEL, b + 3 * DMODEL, P.tmp, NTOK, DMODEL, DMODEL);
}

// cross-attention: Q from xq, K/V from xkv; Q,K land in qk at ldc=1024.
static void attention_cross(const fp16* xqh, const fp16* xkh,
                            const fp16* wh, const float* b, const Ptrs& P)
{
    const size_t WS = (size_t)DMODEL * DMODEL;
    gemm21(xqh, wh,          b,              P.qk,       NTOK, DMODEL, DMODEL, 1024);
    gemm21(xkh, wh + 1 * WS, b + 1 * DMODEL, P.qk + 512, NTOK, DMODEL, DMODEL, 1024);
    gemm01(xkh, wh + 2 * WS, b + 2 * DMODEL, P.v,        NTOK, DMODEL, DMODEL, DMODEL);

    kv_partial<<<dim3(32, SCH), 256>>>(P.qk + 512, 1024, P.v, 512, P.pkv, P.pks);
    kv_reduce<<<dim3(32, 4), 256>>>(P.pkv, P.pks, P.kv, P.ks);
    attn_out<<<dim3(32, 32), 256>>>(P.qk, 1024, P.kv, P.ks, P.ath);

    gemm00(P.ath, wh + 3 * WS, b + 3 * DMODEL, P.tmp, NTOK, DMODEL, DMODEL);
}

extern "C" void kernel_launch(void* const* d_in, const int* in_sizes, int n_in,
                              void* d_out, int out_size)
{
    const float* x            = (const float*)d_in[0];
    const float* out_pos_emb  = (const float*)d_in[1];
    const float* pe_input     = (const float*)d_in[2];
    const float* emb_w        = (const float*)d_in[3];
    const float* emb_b        = (const float*)d_in[4];
    const float* enc_attn_w   = (const float*)d_in[5];
    const float* enc_attn_b   = (const float*)d_in[6];
    const float* enc_ln       = (const float*)d_in[7];
    const float* enc_ff_w1    = (const float*)d_in[8];
    const float* enc_ff_b1    = (const float*)d_in[9];
    const float* enc_ff_w2    = (const float*)d_in[10];
    const float* enc_ff_b2    = (const float*)d_in[11];
    const float* enc_final_ln = (const float*)d_in[12];
    const float* dec_self_w   = (const float*)d_in[13];
    const float* dec_self_b   = (const float*)d_in[14];
    const float* dec_cross_w  = (const float*)d_in[15];
    const float* dec_cross_b  = (const float*)d_in[16];
    const float* dec_ln       = (const float*)d_in[17];
    const float* dec_ff_w1    = (const float*)d_in[18];
    const float* dec_ff_b1    = (const float*)d_in[19];
    const float* dec_ff_w2    = (const float*)d_in[20];
    const float* dec_ff_b2    = (const float*)d_in[21];
    const float* dec_final_ln = (const float*)d_in[22];
    const float* pred_w       = (const float*)d_in[23];
    const float* pred_b       = (const float*)d_in[24];

    cudaFuncSetAttribute(gemm_tc<2,1>, cudaFuncAttributeMaxDynamicSharedMemorySize, SMEM_DYN);
    cudaFuncSetAttribute(gemm_tc<0,1>, cudaFuncAttributeMaxDynamicSharedMemorySize, SMEM_DYN);
    cudaFuncSetAttribute(gemm_tc<0,0>, cudaFuncAttributeMaxDynamicSharedMemorySize, SMEM_DYN);
    cudaFuncSetAttribute(gemm_tc<1,1>, cudaFuncAttributeMaxDynamicSharedMemorySize, SMEM_DYN);

    unsigned char* S = nullptr;
    cudaGetSymbolAddress((void**)&S, g_scratch);

    Ptrs P;
    P.h   = (float*)(S + B_H);   P.z   = (float*)(S + B_Z);   P.o  = (float*)(S + B_O);
    P.tmp = (float*)(S + B_TMP);
    P.qk  = (fp16*)(S + B_QK);   P.v   = (fp16*)(S + B_V);
    P.pkv = (float*)(S + B_PKV); P.pks = (float*)(S + B_PKS);
    P.kv  = (float*)(S + B_KVB); P.ks  = (float*)(S + B_KSB);
    P.hh  = (fp16*)(S + B_HH);   P.zh  = (fp16*)(S + B_ZH);
    P.oh  = (fp16*)(S + B_OH);   P.ath = (fp16*)(S + B_ATH);
    P.fh  = (fp16*)(S + B_FH);
    P.wha = (fp16*)(S + B_WHA);
    P.whf1 = (fp16*)(S + B_WHF1);
    P.whf2 = (fp16*)(S + B_WHF2);

    // ---- transpose + fp16-round all weights ----
    transpose_w16<<<dim3(16, 16, 16), 256>>>(enc_attn_w,  P.wha,                     512, 512);
    transpose_w16<<<dim3(16, 16, 16), 256>>>(dec_self_w,  P.wha + (size_t)16*262144, 512, 512);
    transpose_w16<<<dim3(16, 16, 16), 256>>>(dec_cross_w, P.wha + (size_t)32*262144, 512, 512);
    transpose_w16<<<dim3(64, 16, 4),  256>>>(enc_ff_w1, P.whf1,                      512, 2048);
    transpose_w16<<<dim3(64, 16, 4),  256>>>(dec_ff_w1, P.whf1 + (size_t)4*1048576,  512, 2048);
    transpose_w16<<<dim3(16, 64, 4),  256>>>(enc_ff_w2, P.whf2,                      2048, 512);
    transpose_w16<<<dim3(16, 64, 4),  256>>>(dec_ff_w2, P.whf2 + (size_t)4*1048576,  2048, 512);

    const size_t WT4 = (size_t)4 * DMODEL * DMODEL;
    const size_t W1S = (size_t)DFF * DMODEL;
    const size_t W2S = (size_t)DMODEL * DFF;

    // ---- embed ----
    embed_kernel<<<(NTOK * 128) / 256, 256>>>(x, pe_input, emb_w, emb_b, P.h, P.hh);

    // ---- encoder ----
    for (int l = 0; l < 4; l++) {
        const float* ln = enc_ln + (size_t)l * 2 * 2 * DMODEL;
        attention_self(P.hh, P.wha + (size_t)l * WT4,
                       enc_attn_b + (size_t)l * 4 * DMODEL, P);
        ln_kernel<<<NTOK / 4, 256>>>(P.h, P.tmp, ln, P.h, P.hh);
        gemm11(P.hh, P.whf1 + (size_t)l * W1S,
               enc_ff_b1 + (size_t)l * DFF, P.fh, NTOK, DFF, DMODEL);
        gemm00(P.fh, P.whf2 + (size_t)l * W2S,
               enc_ff_b2 + (size_t)l * DMODEL, P.tmp, NTOK, DMODEL, DFF);
        ln_kernel<<<NTOK / 4, 256>>>(P.h, P.tmp, ln + 2 * DMODEL, P.h, P.hh);
    }
    ln_kernel<<<NTOK / 4, 256>>>(P.h, nullptr, enc_final_ln, nullptr, P.zh);

    // ---- decoder ----
    dec_init_kernel<<<(NTOK * 128) / 256, 256>>>(out_pos_emb, P.o, P.oh);
    for (int l = 0; l < 4; l++) {
        const float* ln = dec_ln + (size_t)l * 3 * 2 * DMODEL;
        attention_self(P.oh, P.wha + (size_t)(16 + l * 4) * DMODEL * DMODEL,
                       dec_self_b + (size_t)l * 4 * DMODEL, P);
        ln_kernel<<<NTOK / 4, 256>>>(P.o, P.tmp, ln, P.o, P.oh);
        attention_cross(P.oh, P.zh,
                        P.wha + (size_t)(32 + l * 4) * DMODEL * DMODEL,
                        dec_cross_b + (size_t)l * 4 * DMODEL, P);
        ln_kernel<<<NTOK / 4, 256>>>(P.o, P.tmp, ln + 2 * DMODEL, P.o, P.oh);
        gemm11(P.oh, P.whf1 + (size_t)(4 + l) * W1S,
               dec_ff_b1 + (size_t)l * DFF, P.fh, NTOK, DFF, DMODEL);
        gemm00(P.fh, P.whf2 + (size_t)(4 + l) * W2S,
               dec_ff_b2 + (size_t)l * DMODEL, P.tmp, NTOK, DMODEL, DFF);
        ln_kernel<<<NTOK / 4, 256>>>(P.o, P.tmp, ln + 4 * DMODEL, P.o, P.oh);
    }
    ln_kernel<<<NTOK / 4, 256>>>(P.o, nullptr, dec_final_ln, nullptr, P.ath);

    // ---- prediction head ----
    pred_kernel<<<(NTOK * 32) / 256, 256>>>(P.ath, pred_w, pred_b, (float*)d_out);
}

// round 13
// speedup vs baseline: 2.0025x; 1.0170x over previous
#include <cuda_runtime.h>
#include <cuda_fp16.h>
#include <cstdint>
#include <cstddef>

// ---------------------------------------------------------------------------
// TRecTransformer: linear-attention encoder/decoder.
// GEMMs: plain fp16 mma.sync m16n8k16 (fp32 accum).
// This round: fp16-only glue trunk (residual stream, sublayer outputs, LN
// all fp16 storage / fp32 compute).
// ---------------------------------------------------------------------------

#define NTOK   16384
#define DMODEL 512
#define DFF    2048
#define LSEQ   4096
#define SCH    16

#define SZ ((size_t)NTOK * DMODEL)        // 8,388,608 elements

// ---- scratch layout (BYTE offsets) ----
#define B_TMPH  ((size_t)0)               // fp16 sublayer output [NTOK,512]
#define B_QK    (B_TMPH + SZ*2)           // fp16 [NTOK,1024]
#define B_V     (B_QK  + SZ*4)            // fp16 [NTOK,512]
#define B_PKV   (B_V   + SZ*2)
#define B_PKS   (B_PKV + (size_t)SCH*32*4096*4)
#define B_KVB   (B_PKS + (size_t)SCH*32*64*4)
#define B_KSB   (B_KVB + (size_t)32*4096*4)
#define B_HH    (B_KSB + (size_t)32*64*4) // fp16 trunk (encoder)
#define B_ZH    (B_HH  + SZ*2)
#define B_OH    (B_ZH  + SZ*2)            // fp16 trunk (decoder)
#define B_ATH   (B_OH  + SZ*2)
#define B_FH    (B_ATH + SZ*2)            // NTOK*DFF halves
#define B_WHA   (B_FH  + SZ*8)            // 48 x 512x512
#define B_WHF1  (B_WHA + (size_t)48*262144*2)
#define B_WHF2  (B_WHF1 + (size_t)8*1048576*2)
#define TOTAL_B (B_WHF2 + (size_t)8*1048576*2)

__device__ __align__(1024) unsigned char g_scratch[TOTAL_B];

typedef __half fp16;

// ---------------------------------------------------------------------------
// helpers
// ---------------------------------------------------------------------------
__device__ __forceinline__ uint32_t smem_u32(const void* p) {
    uint32_t a;
    asm("{ .reg .u64 t; cvta.to.shared.u64 t, %1; cvt.u32.u64 %0, t; }" : "=r"(a) : "l"(p));
    return a;
}
__device__ __forceinline__ void ldsm4(uint32_t* r, uint32_t addr) {
    asm volatile("ldmatrix.sync.aligned.m8n8.x4.shared.b16 {%0,%1,%2,%3}, [%4];"
        : "=r"(r[0]), "=r"(r[1]), "=r"(r[2]), "=r"(r[3]) : "r"(addr));
}
__device__ __forceinline__ void mma_f16(float* c, const uint32_t* a, const uint32_t* b) {
    asm volatile(
        "mma.sync.aligned.m16n8k16.row.col.f32.f16.f16.f32 "
        "{%0,%1,%2,%3}, {%4,%5,%6,%7}, {%8,%9}, {%0,%1,%2,%3};"
        : "+f"(c[0]), "+f"(c[1]), "+f"(c[2]), "+f"(c[3])
        : "r"(a[0]), "r"(a[1]), "r"(a[2]), "r"(a[3]), "r"(b[0]), "r"(b[1]));
}
__device__ __forceinline__ void cp16(uint32_t d, const void* s) {
    asm volatile("cp.async.cg.shared.global [%0], [%1], 16;" :: "r"(d), "l"(s));
}
__device__ __forceinline__ void cp_commit() { asm volatile("cp.async.commit_group;" ::: "memory"); }
__device__ __forceinline__ void cp_wait1()  { asm volatile("cp.async.wait_group 1;" ::: "memory"); }
__device__ __forceinline__ void cp_wait0()  { asm volatile("cp.async.wait_group 0;" ::: "memory"); }

// ---------------------------------------------------------------------------
// GEMM: Ch[M,N](ldc) = act(A[M,K] @ W[N,K]^T + bias), fp16 out.
// 128x128 tile, Kc=32, 256 threads, 3-stage cp.async pipeline.
// ACT: 0 none, 1 relu, 2 phi=elu+1.
// ---------------------------------------------------------------------------
#define ROWB 80
#define MATB 10240
#define STGB 20480
#define SMEM_DYN (3 * STGB)

template<int ACT>
__global__ __launch_bounds__(256) void gemm_tc(
    const fp16* __restrict__ A, const fp16* __restrict__ B,
    const float* __restrict__ bias, fp16* __restrict__ Ch,
    int M, int N, int K, int ldc)
{
    extern __shared__ char smc[];
    const uint32_t smB = smem_u32(smc);

    const int tid = threadIdx.x, lane = tid & 31, wid = tid >> 5;
    const int row0 = blockIdx.y * 128, col0 = blockIdx.x * 128;
    const int wm = wid & 1, wn = wid >> 1;

    float acc[4][4][4];
    #pragma unroll
    for (int i = 0; i < 4; i++)
        #pragma unroll
        for (int j = 0; j < 4; j++)
            #pragma unroll
            for (int e = 0; e < 4; e++) acc[i][j][e] = 0.f;

    const uint32_t aoff = (uint32_t)((wm * 64 + (lane & 7) + ((lane >> 3) & 1) * 8) * ROWB
                                     + (lane >> 4) * 16);
    const uint32_t boff = (uint32_t)((wn * 32 + (lane >> 4) * 8 + (lane & 7)) * ROWB
                                     + ((lane >> 3) & 1) * 16);

    const int NC = K / 32;
    const int pr = tid >> 2;
    const int pb = (tid & 3) * 16;

    auto loadst = [&](int c, int s) {
        const int k0 = c * 32;
        const uint32_t st = smB + (uint32_t)s * STGB;
        #pragma unroll
        for (int m = 0; m < 2; m++) {
            const fp16* g = (m == 0) ? A : B;
            const int rb = (m == 0) ? row0 : col0;
            #pragma unroll
            for (int hf = 0; hf < 2; hf++) {
                const int r = hf * 64 + pr;
                cp16(st + m * MATB + r * ROWB + pb,
                     (const char*)(g + (size_t)(rb + r) * K + k0) + pb);
            }
        }
    };

    auto compute = [&](int s) {
        const uint32_t base = smB + (uint32_t)s * STGB;
        #pragma unroll
        for (int ks = 0; ks < 2; ks++) {
            uint32_t ar[4][4], br[4][2];
            #pragma unroll
            for (int mi = 0; mi < 4; mi++)
                ldsm4(ar[mi], base + aoff + mi * 1280 + ks * 32);
            #pragma unroll
            for (int j = 0; j < 2; j++) {
                uint32_t t[4];
                ldsm4(t, base + MATB + boff + j * 1280 + ks * 32);
                br[2 * j][0] = t[0]; br[2 * j][1] = t[1];
                br[2 * j + 1][0] = t[2]; br[2 * j + 1][1] = t[3];
            }
            #pragma unroll
            for (int mi = 0; mi < 4; mi++)
                #pragma unroll
                for (int ni = 0; ni < 4; ni++) mma_f16(acc[mi][ni], ar[mi], br[ni]);
        }
    };

    loadst(0, 0); cp_commit();
    loadst(1, 1); cp_commit();
    for (int c = 0; c < NC; c++) {
        if (c + 1 < NC) cp_wait1(); else cp_wait0();
        __syncthreads();
        compute(c % 3);
        if (c + 2 < NC) { loadst(c + 2, (c + 2) % 3); cp_commit(); }
    }

    const int gm0 = row0 + wm * 64;
    const int gn0 = col0 + wn * 32;
    #pragma unroll
    for (int ni = 0; ni < 4; ni++) {
        const int cn = gn0 + ni * 8 + (lane & 3) * 2;
        const float b0 = bias[cn], b1 = bias[cn + 1];
        #pragma unroll
        for (int mi = 0; mi < 4; mi++) {
            const int rm = gm0 + mi * 16 + (lane >> 2);
            float t0 = acc[mi][ni][0] + b0;
            float t1 = acc[mi][ni][1] + b1;
            float t2 = acc[mi][ni][2] + b0;
            float t3 = acc[mi][ni][3] + b1;
            if (ACT == 1) {
                t0 = fmaxf(t0, 0.f); t1 = fmaxf(t1, 0.f);
                t2 = fmaxf(t2, 0.f); t3 = fmaxf(t3, 0.f);
            }
            if (ACT == 2) {
                t0 = t0 > 0.f ? t0 + 1.f : __expf(t0);
                t1 = t1 > 0.f ? t1 + 1.f : __expf(t1);
                t2 = t2 > 0.f ? t2 + 1.f : __expf(t2);
                t3 = t3 > 0.f ? t3 + 1.f : __expf(t3);
            }
            __half2 hp;
            hp.x = __float2half_rn(t0); hp.y = __float2half_rn(t1);
            *(__half2*)&Ch[(size_t)rm * ldc + cn] = hp;
            hp.x = __float2half_rn(t2); hp.y = __float2half_rn(t3);
            *(__half2*)&Ch[(size_t)(rm + 8) * ldc + cn] = hp;
        }
    }
}

// ---------------------------------------------------------------------------
// fused weight transpose + fp16 round: W[K,N] fp32 -> Wh [N,K] fp16
// ---------------------------------------------------------------------------
__global__ __launch_bounds__(256) void transpose_w16(
    const float* __restrict__ W, fp16* __restrict__ Wh, int K, int N)
{
    __shared__ float t[32][33];
    const size_t mo = (size_t)blockIdx.z * K * N;
    const float* Wm = W + mo;
    const int n0 = blockIdx.x * 32, k0 = blockIdx.y * 32;
    const int tx = threadIdx.x & 31, ty = threadIdx.x >> 5;
    #pragma unroll
    for (int i = 0; i < 32; i += 8)
        t[ty + i][tx] = Wm[(size_t)(k0 + ty + i) * N + n0 + tx];
    __syncthreads();
    #pragma unroll
    for (int i = 0; i < 32; i += 8)
        Wh[mo + (size_t)(n0 + ty + i) * K + k0 + tx] = __float2half_rn(t[tx][ty + i]);
}

// ---------------------------------------------------------------------------
// kv partial: register-tiled 4x4 outer product per thread. K,V row strides.
// ---------------------------------------------------------------------------
__global__ __launch_bounds__(256) void kv_partial(
    const fp16* __restrict__ Kt, int ldk,
    const fp16* __restrict__ Vt, int ldv,
    float* __restrict__ pkv, float* __restrict__ pks)
{
    const int bh = blockIdx.x, ch = blockIdx.y;
    const int b = bh >> 3, h = bh & 7;
    const int tid = threadIdx.x;
    __shared__ float Ks[8][64], Vs[8][64];

    float acc[4][4];
    #pragma unroll
    for (int i = 0; i < 4; i++)
        #pragma unroll
        for (int j = 0; j < 4; j++) acc[i][j] = 0.f;
    float ksa[4] = {0.f, 0.f, 0.f, 0.f};

    const int td = tid >> 4, tm = tid & 15;
    const int s0 = ch * (LSEQ / SCH);
    const int lr = tid >> 5, lc = (tid & 31) * 2;

    for (int s = s0; s < s0 + LSEQ / SCH; s += 8) {
        const size_t row = (size_t)(b * LSEQ + s + lr);
        const float2 kf = __half22float2(*(const __half2*)(Kt + row * ldk + h * 64 + lc));
        const float2 vf = __half22float2(*(const __half2*)(Vt + row * ldv + h * 64 + lc));
        *(float2*)&Ks[lr][lc] = kf;
        *(float2*)&Vs[lr][lc] = vf;
        __syncthreads();
        #pragma unroll
        for (int rr = 0; rr < 8; rr++) {
            const float4 k4 = *(const float4*)&Ks[rr][td * 4];
            const float4 v4 = *(const float4*)&Vs[rr][tm * 4];
            acc[0][0] = fmaf(k4.x, v4.x, acc[0][0]);
            acc[0][1] = fmaf(k4.x, v4.y, acc[0][1]);
            acc[0][2] = fmaf(k4.x, v4.z, acc[0][2]);
            acc[0][3] = fmaf(k4.x, v4.w, acc[0][3]);
            acc[1][0] = fmaf(k4.y, v4.x, acc[1][0]);
            acc[1][1] = fmaf(k4.y, v4.y, acc[1][1]);
            acc[1][2] = fmaf(k4.y, v4.z, acc[1][2]);
            acc[1][3] = fmaf(k4.y, v4.w, acc[1][3]);
            acc[2][0] = fmaf(k4.z, v4.x, acc[2][0]);
            acc[2][1] = fmaf(k4.z, v4.y, acc[2][1]);
            acc[2][2] = fmaf(k4.z, v4.z, acc[2][2]);
            acc[2][3] = fmaf(k4.z, v4.w, acc[2][3]);
            acc[3][0] = fmaf(k4.w, v4.x, acc[3][0]);
            acc[3][1] = fmaf(k4.w, v4.y, acc[3][1]);
            acc[3][2] = fmaf(k4.w, v4.z, acc[3][2]);
            acc[3][3] = fmaf(k4.w, v4.w, acc[3][3]);
            if (tm == 0) {
                ksa[0] += k4.x; ksa[1] += k4.y;
                ksa[2] += k4.z; ksa[3] += k4.w;
            }
        }
        __syncthreads();
    }

    float* o = pkv + ((size_t)ch * 32 + bh) * 4096;
    #pragma unroll
    for (int i = 0; i < 4; i++) {
        float4 v;
        v.x = acc[i][0]; v.y = acc[i][1]; v.z = acc[i][2]; v.w = acc[i][3];
        *(float4*)&o[(td * 4 + i) * 64 + tm * 4] = v;
    }
    if (tm == 0) {
        float* p = pks + ((size_t)ch * 32 + bh) * 64 + td * 4;
        p[0] = ksa[0]; p[1] = ksa[1]; p[2] = ksa[2]; p[3] = ksa[3];
    }
}

__global__ __launch_bounds__(256) void kv_reduce(
    const float* __restrict__ pkv, const float* __restrict__ pks,
    float* __restrict__ kv, float* __restrict__ ks)
{
    const int bh = blockIdx.x, tid = threadIdx.x;
    const int e4 = blockIdx.y * 256 + tid;
    float4 s; s.x = s.y = s.z = s.w = 0.f;
    #pragma unroll
    for (int c = 0; c < SCH; c++) {
        const float4 v = ((const float4*)pkv)[((size_t)c * 32 + bh) * 1024 + e4];
        s.x += v.x; s.y += v.y; s.z += v.z; s.w += v.w;
    }
    ((float4*)kv)[(size_t)bh * 1024 + e4] = s;
    if (blockIdx.y == 0 && tid < 64) {
        float t = 0.f;
        #pragma unroll
        for (int c = 0; c < SCH; c++) t += pks[((size_t)c * 32 + bh) * 64 + tid];
        ks[bh * 64 + tid] = t;
    }
}

// ---------------------------------------------------------------------------
// attn out: 8-token register batches per warp. Q row stride ldq.
// ---------------------------------------------------------------------------
__global__ __launch_bounds__(256) void attn_out(
    const fp16* __restrict__ Q, int ldq, const float* __restrict__ kv,
    const float* __restrict__ ksum, fp16* __restrict__ Oh)
{
    const int bh = blockIdx.x, b = bh >> 3, h = bh & 7;
    __shared__ float kvs[64][64];
    __shared__ float kss[64];
    const int tid = threadIdx.x;
    #pragma unroll
    for (int e = 0; e < 4; e++)
        ((float4*)kvs)[e * 256 + tid] = ((const float4*)kv)[(size_t)bh * 1024 + e * 256 + tid];
    if (tid < 64) kss[tid] = ksum[bh * 64 + tid];
    __syncthreads();

    const int warp = tid >> 5, lane = tid & 31;
    const int lw = blockIdx.y * 128 + warp * 16;

    #pragma unroll
    for (int g = 0; g < 2; g++) {
        const int lt = lw + g * 8;
        float q0[8], q1[8], a0[8], a1[8], z[8];
        #pragma unroll
        for (int t = 0; t < 8; t++) {
            const fp16* q = Q + (size_t)(b * LSEQ + lt + t) * ldq + h * 64;
            q0[t] = __half2float(q[lane]);
            q1[t] = __half2float(q[lane + 32]);
            a0[t] = 0.f; a1[t] = 0.f;
        }
        const float ks0 = kss[lane], ks1 = kss[lane + 32];
        #pragma unroll
        for (int t = 0; t < 8; t++) {
            float zd = q0[t] * ks0 + q1[t] * ks1;
            #pragma unroll
            for (int o = 16; o > 0; o >>= 1) zd += __shfl_xor_sync(0xffffffffu, zd, o);
            z[t] = 1.f / (zd + 1e-6f);
        }
        #pragma unroll
        for (int dd = 0; dd < 32; dd++) {
            const float kA = kvs[dd][lane], kB = kvs[dd][lane + 32];
            #pragma unroll
            for (int t = 0; t < 8; t++) {
                const float qd = __shfl_sync(0xffffffffu, q0[t], dd);
                a0[t] = fmaf(qd, kA, a0[t]);
                a1[t] = fmaf(qd, kB, a1[t]);
            }
        }
        #pragma unroll
        for (int dd = 0; dd < 32; dd++) {
            const float kA = kvs[dd + 32][lane], kB = kvs[dd + 32][lane + 32];
            #pragma unroll
            for (int t = 0; t < 8; t++) {
                const float qd = __shfl_sync(0xffffffffu, q1[t], dd);
                a0[t] = fmaf(qd, kA, a0[t]);
                a1[t] = fmaf(qd, kB, a1[t]);
            }
        }
        #pragma unroll
        for (int t = 0; t < 8; t++) {
            const size_t op = ((size_t)(b * LSEQ + lt + t)) * DMODEL + h * 64;
            Oh[op + lane]      = __float2half_rn(a0[t] * z[t]);
            Oh[op + lane + 32] = __float2half_rn(a1[t] * z[t]);
        }
    }
}

// ---------------------------------------------------------------------------
// LayerNorm (fp16 in/out, fp32 compute): 4 tokens per 256-thread CTA,
// 64 threads/token, each thread handles 8 consecutive elements (uint4).
// Yh = LN(X + R) * gamma + beta. R nullable.
// ---------------------------------------------------------------------------
__global__ __launch_bounds__(256) void ln_kernel(
    const fp16* __restrict__ X, const fp16* __restrict__ R,
    const float* __restrict__ gb, fp16* __restrict__ Yh)
{
    const int tid = threadIdx.x;
    const int tok = blockIdx.x * 4 + (tid >> 6);
    const int u = tid & 63;
    const size_t base8 = (size_t)tok * 64;      // uint4 units per row

    const uint4 xv = ((const uint4*)X)[base8 + u];
    float v[8];
    {
        const __half2* xh = (const __half2*)&xv;
        #pragma unroll
        for (int i = 0; i < 4; i++) {
            const float2 f = __half22float2(xh[i]);
            v[2 * i] = f.x; v[2 * i + 1] = f.y;
        }
    }
    if (R) {
        const uint4 rv = ((const uint4*)R)[base8 + u];
        const __half2* rh = (const __half2*)&rv;
        #pragma unroll
        for (int i = 0; i < 4; i++) {
            const float2 f = __half22float2(rh[i]);
            v[2 * i] += f.x; v[2 * i + 1] += f.y;
        }
    }
    float s = 0.f;
    #pragma unroll
    for (int i = 0; i < 8; i++) s += v[i];

    __shared__ float redS[4][2], redQ[4][2];
    const int tk = tid >> 6, w2 = (tid >> 5) & 1;
    #pragma unroll
    for (int o = 16; o > 0; o >>= 1) s += __shfl_xor_sync(0xffffffffu, s, o);
    if ((tid & 31) == 0) redS[tk][w2] = s;
    __syncthreads();
    const float mu = (redS[tk][0] + redS[tk][1]) * (1.f / DMODEL);

    float qq = 0.f;
    #pragma unroll
    for (int i = 0; i < 8; i++) { v[i] -= mu; qq += v[i] * v[i]; }
    #pragma unroll
    for (int o = 16; o > 0; o >>= 1) qq += __shfl_xor_sync(0xffffffffu, qq, o);
    if ((tid & 31) == 0) redQ[tk][w2] = qq;
    __syncthreads();
    const float var = (redQ[tk][0] + redQ[tk][1]) * (1.f / DMODEL);
    const float rstd = rsqrtf(var + 1e-5f);

    const float4 g0 = ((const float4*)gb)[u * 2];
    const float4 g1 = ((const float4*)gb)[u * 2 + 1];
    const float4 b0 = ((const float4*)(gb + DMODEL))[u * 2];
    const float4 b1 = ((const float4*)(gb + DMODEL))[u * 2 + 1];
    float o0 = v[0] * rstd * g0.x + b0.x;
    float o1 = v[1] * rstd * g0.y + b0.y;
    float o2 = v[2] * rstd * g0.z + b0.z;
    float o3 = v[3] * rstd * g0.w + b0.w;
    float o4 = v[4] * rstd * g1.x + b1.x;
    float o5 = v[5] * rstd * g1.y + b1.y;
    float o6 = v[6] * rstd * g1.z + b1.z;
    float o7 = v[7] * rstd * g1.w + b1.w;

    uint4 out;
    __half2 hp;
    hp.x = __float2half_rn(o0); hp.y = __float2half_rn(o1); out.x = *(uint32_t*)&hp;
    hp.x = __float2half_rn(o2); hp.y = __float2half_rn(o3); out.y = *(uint32_t*)&hp;
    hp.x = __float2half_rn(o4); hp.y = __float2half_rn(o5); out.z = *(uint32_t*)&hp;
    hp.x = __float2half_rn(o6); hp.y = __float2half_rn(o7); out.w = *(uint32_t*)&hp;
    ((uint4*)Yh)[base8 + u] = out;
}

// embed: fp16 output only.
__global__ void embed_kernel(
    const float* __restrict__ x, const float* __restrict__ pe,
    const float* __restrict__ ew, const float* __restrict__ eb,
    fp16* __restrict__ hh)
{
    const size_t i4 = (size_t)blockIdx.x * blockDim.x + threadIdx.x;
    const int tok = (int)(i4 >> 7);
    const int j   = (int)(i4 & 127) * 4;
    const int l   = tok & (LSEQ - 1);
    float4 v;
    if (j < 256) {
        const float x0 = x[(size_t)tok * 2], x1 = x[(size_t)tok * 2 + 1];
        const float4 w0 = *(const float4*)(ew + j);
        const float4 w1 = *(const float4*)(ew + 256 + j);
        const float4 b  = *(const float4*)(eb + j);
        v.x = x0 * w0.x + x1 * w1.x + b.x;
        v.y = x0 * w0.y + x1 * w1.y + b.y;
        v.z = x0 * w0.z + x1 * w1.z + b.z;
        v.w = x0 * w0.w + x1 * w1.w + b.w;
    } else {
        v = *(const float4*)(pe + (size_t)l * 256 + (j - 256));
    }
    __half2 h0, h1;
    h0.x = __float2half_rn(v.x); h0.y = __float2half_rn(v.y);
    h1.x = __float2half_rn(v.z); h1.y = __float2half_rn(v.w);
    uint2 pk; pk.x = *(uint32_t*)&h0; pk.y = *(uint32_t*)&h1;
    ((uint2*)hh)[i4] = pk;
}

__global__ void dec_init_kernel(const float* __restrict__ ope, fp16* __restrict__ oh)
{
    const size_t i4 = (size_t)blockIdx.x * blockDim.x + threadIdx.x;
    const size_t tok = i4 >> 7;
    const float4 v = ((const float4*)ope)[((tok & (LSEQ - 1)) << 7) | (i4 & 127)];
    __half2 h0, h1;
    h0.x = __float2half_rn(v.x); h0.y = __float2half_rn(v.y);
    h1.x = __float2half_rn(v.z); h1.y = __float2half_rn(v.w);
    uint2 pk; pk.x = *(uint32_t*)&h0; pk.y = *(uint32_t*)&h1;
    ((uint2*)oh)[i4] = pk;
}

__global__ void pred_kernel(
    const fp16* __restrict__ Xh, const float* __restrict__ pw,
    const float* __restrict__ pb, float* __restrict__ out)
{
    const int gw = (int)(((size_t)blockIdx.x * blockDim.x + threadIdx.x) >> 5);
    const int lane = threadIdx.x & 31;
    if (gw >= NTOK) return;
    const fp16* xr = Xh + (size_t)gw * DMODEL;
    float a0 = 0.f, a1 = 0.f;
    #pragma unroll 4
    for (int j = lane; j < DMODEL; j += 32) {
        const float v = __half2float(xr[j]);
        a0 = fmaf(v, pw[2 * j],     a0);
        a1 = fmaf(v, pw[2 * j + 1], a1);
    }
    #pragma unroll
    for (int o = 16; o > 0; o >>= 1) {
        a0 += __shfl_xor_sync(0xffffffffu, a0, o);
        a1 += __shfl_xor_sync(0xffffffffu, a1, o);
    }
    if (lane == 0) { out[2 * gw] = a0 + pb[0]; out[2 * gw + 1] = a1 + pb[1]; }
}

// ---------------------------------------------------------------------------
// Host orchestration
// ---------------------------------------------------------------------------
struct Ptrs {
    float *pkv, *pks, *kv, *ks;
    fp16 *tmph, *qk, *v;
    fp16 *hh, *zh, *oh, *ath, *fh;
    fp16 *wha, *whf1, *whf2;
};

static void gemm2(const fp16* a, const fp16* b, const float* bias,
                  fp16* Ch, int M, int N, int K, int ldc) {
    gemm_tc<2><<<dim3(N/128, M/128), 256, SMEM_DYN>>>(a, b, bias, Ch, M, N, K, ldc);
}
static void gemm0(const fp16* a, const fp16* b, const float* bias,
                  fp16* Ch, int M, int N, int K, int ldc) {
    gemm_tc<0><<<dim3(N/128, M/128), 256, SMEM_DYN>>>(a, b, bias, Ch, M, N, K, ldc);
}
static void gemm1(const fp16* a, const fp16* b, const float* bias,
                  fp16* Ch, int M, int N, int K, int ldc) {
    gemm_tc<1><<<dim3(N/128, M/128), 256, SMEM_DYN>>>(a, b, bias, Ch, M, N, K, ldc);
}

static void attention_self(const fp16* xh, const fp16* wh, const float* b, const Ptrs& P)
{
    gemm2(xh, wh, b, P.qk, NTOK, 1024, DMODEL, 1024);
    gemm0(xh, wh + (size_t)2 * DMODEL * DMODEL, b + 2 * DMODEL, P.v, NTOK, DMODEL, DMODEL, DMODEL);

    kv_partial<<<dim3(32, SCH), 256>>>(P.qk + 512, 1024, P.v, 512, P.pkv, P.pks);
    kv_reduce<<<dim3(32, 4), 256>>>(P.pkv, P.pks, P.kv, P.ks);
    attn_out<<<dim3(32, 32), 256>>>(P.qk, 1024, P.kv, P.ks, P.ath);

    gemm0(P.ath, wh + (size_t)3 * DMODEL * DMODEL, b + 3 * DMODEL, P.tmph, NTOK, DMODEL, DMODEL, DMODEL);
}

static void attention_cross(const fp16* xqh, const fp16* xkh,
                            const fp16* wh, const float* b, const Ptrs& P)
{
    const size_t WS = (size_t)DMODEL * DMODEL;
    gemm2(xqh, wh,          b,              P.qk,       NTOK, DMODEL, DMODEL, 1024);
    gemm2(xkh, wh + 1 * WS, b + 1 * DMODEL, P.qk + 512, NTOK, DMODEL, DMODEL, 1024);
    gemm0(xkh, wh + 2 * WS, b + 2 * DMODEL, P.v,        NTOK, DMODEL, DMODEL, DMODEL);

    kv_partial<<<dim3(32, SCH), 256>>>(P.qk + 512, 1024, P.v, 512, P.pkv, P.pks);
    kv_reduce<<<dim3(32, 4), 256>>>(P.pkv, P.pks, P.kv, P.ks);
    attn_out<<<dim3(32, 32), 256>>>(P.qk, 1024, P.kv, P.ks, P.ath);

    gemm0(P.ath, wh + 3 * WS, b + 3 * DMODEL, P.tmph, NTOK, DMODEL, DMODEL, DMODEL);
}

extern "C" void kernel_launch(void* const* d_in, const int* in_sizes, int n_in,
                              void* d_out, int out_size)
{
    const float* x            = (const float*)d_in[0];
    const float* out_pos_emb  = (const float*)d_in[1];
    const float* pe_input     = (const float*)d_in[2];
    const float* emb_w        = (const float*)d_in[3];
    const float* emb_b        = (const float*)d_in[4];
    const float* enc_attn_w   = (const float*)d_in[5];
    const float* enc_attn_b   = (const float*)d_in[6];
    const float* enc_ln       = (const float*)d_in[7];
    const float* enc_ff_w1    = (const float*)d_in[8];
    const float* enc_ff_b1    = (const float*)d_in[9];
    const float* enc_ff_w2    = (const float*)d_in[10];
    const float* enc_ff_b2    = (const float*)d_in[11];
    const float* enc_final_ln = (const float*)d_in[12];
    const float* dec_self_w   = (const float*)d_in[13];
    const float* dec_self_b   = (const float*)d_in[14];
    const float* dec_cross_w  = (const float*)d_in[15];
    const float* dec_cross_b  = (const float*)d_in[16];
    const float* dec_ln       = (const float*)d_in[17];
    const float* dec_ff_w1    = (const float*)d_in[18];
    const float* dec_ff_b1    = (const float*)d_in[19];
    const float* dec_ff_w2    = (const float*)d_in[20];
    const float* dec_ff_b2    = (const float*)d_in[21];
    const float* dec_final_ln = (const float*)d_in[22];
    const float* pred_w       = (const float*)d_in[23];
    const float* pred_b       = (const float*)d_in[24];

    cudaFuncSetAttribute(gemm_tc<0>, cudaFuncAttributeMaxDynamicSharedMemorySize, SMEM_DYN);
    cudaFuncSetAttribute(gemm_tc<1>, cudaFuncAttributeMaxDynamicSharedMemorySize, SMEM_DYN);
    cudaFuncSetAttribute(gemm_tc<2>, cudaFuncAttributeMaxDynamicSharedMemorySize, SMEM_DYN);

    unsigned char* S = nullptr;
    cudaGetSymbolAddress((void**)&S, g_scratch);

    Ptrs P;
    P.tmph = (fp16*)(S + B_TMPH);
    P.qk   = (fp16*)(S + B_QK);   P.v   = (fp16*)(S + B_V);
    P.pkv  = (float*)(S + B_PKV); P.pks = (float*)(S + B_PKS);
    P.kv   = (float*)(S + B_KVB); P.ks  = (float*)(S + B_KSB);
    P.hh   = (fp16*)(S + B_HH);   P.zh  = (fp16*)(S + B_ZH);
    P.oh   = (fp16*)(S + B_OH);   P.ath = (fp16*)(S + B_ATH);
    P.fh   = (fp16*)(S + B_FH);
    P.wha  = (fp16*)(S + B_WHA);
    P.whf1 = (fp16*)(S + B_WHF1);
    P.whf2 = (fp16*)(S + B_WHF2);

    // ---- transpose + fp16-round all weights ----
    transpose_w16<<<dim3(16, 16, 16), 256>>>(enc_attn_w,  P.wha,                     512, 512);
    transpose_w16<<<dim3(16, 16, 16), 256>>>(dec_self_w,  P.wha + (size_t)16*262144, 512, 512);
    transpose_w16<<<dim3(16, 16, 16), 256>>>(dec_cross_w, P.wha + (size_t)32*262144, 512, 512);
    transpose_w16<<<dim3(64, 16, 4),  256>>>(enc_ff_w1, P.whf1,                      512, 2048);
    transpose_w16<<<dim3(64, 16, 4),  256>>>(dec_ff_w1, P.whf1 + (size_t)4*1048576,  512, 2048);
    transpose_w16<<<dim3(16, 64, 4),  256>>>(enc_ff_w2, P.whf2,                      2048, 512);
    transpose_w16<<<dim3(16, 64, 4),  256>>>(dec_ff_w2, P.whf2 + (size_t)4*1048576,  2048, 512);

    const size_t WT4 = (size_t)4 * DMODEL * DMODEL;
    const size_t W1S = (size_t)DFF * DMODEL;
    const size_t W2S = (size_t)DMODEL * DFF;

    // ---- embed ----
    embed_kernel<<<(NTOK * 128) / 256, 256>>>(x, pe_input, emb_w, emb_b, P.hh);

    // ---- encoder ----
    for (int l = 0; l < 4; l++) {
        const float* ln = enc_ln + (size_t)l * 2 * 2 * DMODEL;
        attention_self(P.hh, P.wha + (size_t)l * WT4,
                       enc_attn_b + (size_t)l * 4 * DMODEL, P);
        ln_kernel<<<NTOK / 4, 256>>>(P.hh, P.tmph, ln, P.hh);
        gemm1(P.hh, P.whf1 + (size_t)l * W1S,
              enc_ff_b1 + (size_t)l * DFF, P.fh, NTOK, DFF, DMODEL, DFF);
        gemm0(P.fh, P.whf2 + (size_t)l * W2S,
              enc_ff_b2 + (size_t)l * DMODEL, P.tmph, NTOK, DMODEL, DFF, DMODEL);
        ln_kernel<<<NTOK / 4, 256>>>(P.hh, P.tmph, ln + 2 * DMODEL, P.hh);
    }
    ln_kernel<<<NTOK / 4, 256>>>(P.hh, nullptr, enc_final_ln, P.zh);

    // ---- decoder ----
    dec_init_kernel<<<(NTOK * 128) / 256, 256>>>(out_pos_emb, P.oh);
    for (int l = 0; l < 4; l++) {
        const float* ln = dec_ln + (size_t)l * 3 * 2 * DMODEL;
        attention_self(P.oh, P.wha + (size_t)(16 + l * 4) * DMODEL * DMODEL,
                       dec_self_b + (size_t)l * 4 * DMODEL, P);
        ln_kernel<<<NTOK / 4, 256>>>(P.oh, P.tmph, ln, P.oh);
        attention_cross(P.oh, P.zh,
                        P.wha + (size_t)(32 + l * 4) * DMODEL * DMODEL,
                        dec_cross_b + (size_t)l * 4 * DMODEL, P);
        ln_kernel<<<NTOK / 4, 256>>>(P.oh, P.tmph, ln + 2 * DMODEL, P.oh);
        gemm1(P.oh, P.whf1 + (size_t)(4 + l) * W1S,
              dec_ff_b1 + (size_t)l * DFF, P.fh, NTOK, DFF, DMODEL, DFF);
        gemm0(P.fh, P.whf2 + (size_t)(4 + l) * W2S,
              dec_ff_b2 + (size_t)l * DMODEL, P.tmph, NTOK, DMODEL, DFF, DMODEL);
        ln_kernel<<<NTOK / 4, 256>>>(P.oh, P.tmph, ln + 4 * DMODEL, P.oh);
    }
    ln_kernel<<<NTOK / 4, 256>>>(P.oh, nullptr, dec_final_ln, P.ath);

    // ---- prediction head ----
    pred_kernel<<<(NTOK * 32) / 256, 256>>>(P.ath, pred_w, pred_b, (float*)d_out);
}

// round 14
// speedup vs baseline: 2.0348x; 1.0161x over previous
#include <cuda_runtime.h>
#include <cuda_fp16.h>
#include <cstdint>
#include <cstddef>

// ---------------------------------------------------------------------------
// TRecTransformer: linear-attention encoder/decoder.
// GEMMs: plain fp16 mma.sync m16n8k16 (fp32 accum). fp16 glue trunk.
// This round: single-buffer QKV fusion (uniform activation predicate,
// one destination) to cut GEMM launch count and wave tails.
// ---------------------------------------------------------------------------

#define NTOK   16384
#define DMODEL 512
#define DFF    2048
#define LSEQ   4096
#define SCH    16

#define SZ ((size_t)NTOK * DMODEL)        // 8,388,608 elements

// ---- scratch layout (BYTE offsets) ----
#define B_TMPH  ((size_t)0)               // fp16 sublayer output [NTOK,512]
#define B_QKV   (B_TMPH + SZ*2)           // fp16 [NTOK,1536]: Q|K|V
#define B_PKV   (B_QKV + SZ*6)
#define B_PKS   (B_PKV + (size_t)SCH*32*4096*4)
#define B_KVB   (B_PKS + (size_t)SCH*32*64*4)
#define B_KSB   (B_KVB + (size_t)32*4096*4)
#define B_HH    (B_KSB + (size_t)32*64*4) // fp16 trunk (encoder)
#define B_ZH    (B_HH  + SZ*2)
#define B_OH    (B_ZH  + SZ*2)            // fp16 trunk (decoder)
#define B_ATH   (B_OH  + SZ*2)
#define B_FH    (B_ATH + SZ*2)            // NTOK*DFF halves
#define B_WHA   (B_FH  + SZ*8)            // 48 x 512x512
#define B_WHF1  (B_WHA + (size_t)48*262144*2)
#define B_WHF2  (B_WHF1 + (size_t)8*1048576*2)
#define TOTAL_B (B_WHF2 + (size_t)8*1048576*2)

__device__ __align__(1024) unsigned char g_scratch[TOTAL_B];

typedef __half fp16;

// ---------------------------------------------------------------------------
// helpers
// ---------------------------------------------------------------------------
__device__ __forceinline__ uint32_t smem_u32(const void* p) {
    uint32_t a;
    asm("{ .reg .u64 t; cvta.to.shared.u64 t, %1; cvt.u32.u64 %0, t; }" : "=r"(a) : "l"(p));
    return a;
}
__device__ __forceinline__ void ldsm4(uint32_t* r, uint32_t addr) {
    asm volatile("ldmatrix.sync.aligned.m8n8.x4.shared.b16 {%0,%1,%2,%3}, [%4];"
        : "=r"(r[0]), "=r"(r[1]), "=r"(r[2]), "=r"(r[3]) : "r"(addr));
}
__device__ __forceinline__ void mma_f16(float* c, const uint32_t* a, const uint32_t* b) {
    asm volatile(
        "mma.sync.aligned.m16n8k16.row.col.f32.f16.f16.f32 "
        "{%0,%1,%2,%3}, {%4,%5,%6,%7}, {%8,%9}, {%0,%1,%2,%3};"
        : "+f"(c[0]), "+f"(c[1]), "+f"(c[2]), "+f"(c[3])
        : "r"(a[0]), "r"(a[1]), "r"(a[2]), "r"(a[3]), "r"(b[0]), "r"(b[1]));
}
__device__ __forceinline__ void cp16(uint32_t d, const void* s) {
    asm volatile("cp.async.cg.shared.global [%0], [%1], 16;" :: "r"(d), "l"(s));
}
__device__ __forceinline__ void cp_commit() { asm volatile("cp.async.commit_group;" ::: "memory"); }
__device__ __forceinline__ void cp_wait1()  { asm volatile("cp.async.wait_group 1;" ::: "memory"); }
__device__ __forceinline__ void cp_wait0()  { asm volatile("cp.async.wait_group 0;" ::: "memory"); }

// ---------------------------------------------------------------------------
// GEMM: Ch[M,N](ldc) = act(A[M,K] @ W[N,K]^T + bias), fp16 out.
// 128x128 tile, Kc=32, 256 threads, 3-stage cp.async pipeline.
// ACT: 0 none, 1 relu, 2 phi=elu+1, 3 phi iff col < phi_lim (uniform/warp).
// ---------------------------------------------------------------------------
#define ROWB 80
#define MATB 10240
#define STGB 20480
#define SMEM_DYN (3 * STGB)

template<int ACT>
__global__ __launch_bounds__(256) void gemm_tc(
    const fp16* __restrict__ A, const fp16* __restrict__ B,
    const float* __restrict__ bias, fp16* __restrict__ Ch,
    int M, int N, int K, int ldc, int phi_lim)
{
    extern __shared__ char smc[];
    const uint32_t smB = smem_u32(smc);

    const int tid = threadIdx.x, lane = tid & 31, wid = tid >> 5;
    const int row0 = blockIdx.y * 128, col0 = blockIdx.x * 128;
    const int wm = wid & 1, wn = wid >> 1;

    float acc[4][4][4];
    #pragma unroll
    for (int i = 0; i < 4; i++)
        #pragma unroll
        for (int j = 0; j < 4; j++)
            #pragma unroll
            for (int e = 0; e < 4; e++) acc[i][j][e] = 0.f;

    const uint32_t aoff = (uint32_t)((wm * 64 + (lane & 7) + ((lane >> 3) & 1) * 8) * ROWB
                                     + (lane >> 4) * 16);
    const uint32_t boff = (uint32_t)((wn * 32 + (lane >> 4) * 8 + (lane & 7)) * ROWB
                                     + ((lane >> 3) & 1) * 16);

    const int NC = K / 32;
    const int pr = tid >> 2;
    const int pb = (tid & 3) * 16;

    auto loadst = [&](int c, int s) {
        const int k0 = c * 32;
        const uint32_t st = smB + (uint32_t)s * STGB;
        #pragma unroll
        for (int m = 0; m < 2; m++) {
            const fp16* g = (m == 0) ? A : B;
            const int rb = (m == 0) ? row0 : col0;
            #pragma unroll
            for (int hf = 0; hf < 2; hf++) {
                const int r = hf * 64 + pr;
                cp16(st + m * MATB + r * ROWB + pb,
                     (const char*)(g + (size_t)(rb + r) * K + k0) + pb);
            }
        }
    };

    auto compute = [&](int s) {
        const uint32_t base = smB + (uint32_t)s * STGB;
        #pragma unroll
        for (int ks = 0; ks < 2; ks++) {
            uint32_t ar[4][4], br[4][2];
            #pragma unroll
            for (int mi = 0; mi < 4; mi++)
                ldsm4(ar[mi], base + aoff + mi * 1280 + ks * 32);
            #pragma unroll
            for (int j = 0; j < 2; j++) {
                uint32_t t[4];
                ldsm4(t, base + MATB + boff + j * 1280 + ks * 32);
                br[2 * j][0] = t[0]; br[2 * j][1] = t[1];
                br[2 * j + 1][0] = t[2]; br[2 * j + 1][1] = t[3];
            }
            #pragma unroll
            for (int mi = 0; mi < 4; mi++)
                #pragma unroll
                for (int ni = 0; ni < 4; ni++) mma_f16(acc[mi][ni], ar[mi], br[ni]);
        }
    };

    loadst(0, 0); cp_commit();
    loadst(1, 1); cp_commit();
    for (int c = 0; c < NC; c++) {
        if (c + 1 < NC) cp_wait1(); else cp_wait0();
        __syncthreads();
        compute(c % 3);
        if (c + 2 < NC) { loadst(c + 2, (c + 2) % 3); cp_commit(); }
    }

    const int gm0 = row0 + wm * 64;
    const int gn0 = col0 + wn * 32;
    #pragma unroll
    for (int ni = 0; ni < 4; ni++) {
        const int cn = gn0 + ni * 8 + (lane & 3) * 2;
        const float b0 = bias[cn], b1 = bias[cn + 1];
        const bool dophi = (ACT == 2) || (ACT == 3 && cn < phi_lim);
        #pragma unroll
        for (int mi = 0; mi < 4; mi++) {
            const int rm = gm0 + mi * 16 + (lane >> 2);
            float t0 = acc[mi][ni][0] + b0;
            float t1 = acc[mi][ni][1] + b1;
            float t2 = acc[mi][ni][2] + b0;
            float t3 = acc[mi][ni][3] + b1;
            if (ACT == 1) {
                t0 = fmaxf(t0, 0.f); t1 = fmaxf(t1, 0.f);
                t2 = fmaxf(t2, 0.f); t3 = fmaxf(t3, 0.f);
            }
            if (ACT == 2 || ACT == 3) {
                if (dophi) {
                    t0 = t0 > 0.f ? t0 + 1.f : __expf(t0);
                    t1 = t1 > 0.f ? t1 + 1.f : __expf(t1);
                    t2 = t2 > 0.f ? t2 + 1.f : __expf(t2);
                    t3 = t3 > 0.f ? t3 + 1.f : __expf(t3);
                }
            }
            __half2 hp;
            hp.x = __float2half_rn(t0); hp.y = __float2half_rn(t1);
            *(__half2*)&Ch[(size_t)rm * ldc + cn] = hp;
            hp.x = __float2half_rn(t2); hp.y = __float2half_rn(t3);
            *(__half2*)&Ch[(size_t)(rm + 8) * ldc + cn] = hp;
        }
    }
}

// ---------------------------------------------------------------------------
// fused weight transpose + fp16 round: W[K,N] fp32 -> Wh [N,K] fp16
// ---------------------------------------------------------------------------
__global__ __launch_bounds__(256) void transpose_w16(
    const float* __restrict__ W, fp16* __restrict__ Wh, int K, int N)
{
    __shared__ float t[32][33];
    const size_t mo = (size_t)blockIdx.z * K * N;
    const float* Wm = W + mo;
    const int n0 = blockIdx.x * 32, k0 = blockIdx.y * 32;
    const int tx = threadIdx.x & 31, ty = threadIdx.x >> 5;
    #pragma unroll
    for (int i = 0; i < 32; i += 8)
        t[ty + i][tx] = Wm[(size_t)(k0 + ty + i) * N + n0 + tx];
    __syncthreads();
    #pragma unroll
    for (int i = 0; i < 32; i += 8)
        Wh[mo + (size_t)(n0 + ty + i) * K + k0 + tx] = __float2half_rn(t[tx][ty + i]);
}

// ---------------------------------------------------------------------------
// kv partial: register-tiled 4x4 outer product per thread. K,V row strides.
// ---------------------------------------------------------------------------
__global__ __launch_bounds__(256) void kv_partial(
    const fp16* __restrict__ Kt, int ldk,
    const fp16* __restrict__ Vt, int ldv,
    float* __restrict__ pkv, float* __restrict__ pks)
{
    const int bh = blockIdx.x, ch = blockIdx.y;
    const int b = bh >> 3, h = bh & 7;
    const int tid = threadIdx.x;
    __shared__ float Ks[8][64], Vs[8][64];

    float acc[4][4];
    #pragma unroll
    for (int i = 0; i < 4; i++)
        #pragma unroll
        for (int j = 0; j < 4; j++) acc[i][j] = 0.f;
    float ksa[4] = {0.f, 0.f, 0.f, 0.f};

    const int td = tid >> 4, tm = tid & 15;
    const int s0 = ch * (LSEQ / SCH);
    const int lr = tid >> 5, lc = (tid & 31) * 2;

    for (int s = s0; s < s0 + LSEQ / SCH; s += 8) {
        const size_t row = (size_t)(b * LSEQ + s + lr);
        const float2 kf = __half22float2(*(const __half2*)(Kt + row * ldk + h * 64 + lc));
        const float2 vf = __half22float2(*(const __half2*)(Vt + row * ldv + h * 64 + lc));
        *(float2*)&Ks[lr][lc] = kf;
        *(float2*)&Vs[lr][lc] = vf;
        __syncthreads();
        #pragma unroll
        for (int rr = 0; rr < 8; rr++) {
            const float4 k4 = *(const float4*)&Ks[rr][td * 4];
            const float4 v4 = *(const float4*)&Vs[rr][tm * 4];
            acc[0][0] = fmaf(k4.x, v4.x, acc[0][0]);
            acc[0][1] = fmaf(k4.x, v4.y, acc[0][1]);
            acc[0][2] = fmaf(k4.x, v4.z, acc[0][2]);
            acc[0][3] = fmaf(k4.x, v4.w, acc[0][3]);
            acc[1][0] = fmaf(k4.y, v4.x, acc[1][0]);
            acc[1][1] = fmaf(k4.y, v4.y, acc[1][1]);
            acc[1][2] = fmaf(k4.y, v4.z, acc[1][2]);
            acc[1][3] = fmaf(k4.y, v4.w, acc[1][3]);
            acc[2][0] = fmaf(k4.z, v4.x, acc[2][0]);
            acc[2][1] = fmaf(k4.z, v4.y, acc[2][1]);
            acc[2][2] = fmaf(k4.z, v4.z, acc[2][2]);
            acc[2][3] = fmaf(k4.z, v4.w, acc[2][3]);
            acc[3][0] = fmaf(k4.w, v4.x, acc[3][0]);
            acc[3][1] = fmaf(k4.w, v4.y, acc[3][1]);
            acc[3][2] = fmaf(k4.w, v4.z, acc[3][2]);
            acc[3][3] = fmaf(k4.w, v4.w, acc[3][3]);
            if (tm == 0) {
                ksa[0] += k4.x; ksa[1] += k4.y;
                ksa[2] += k4.z; ksa[3] += k4.w;
            }
        }
        __syncthreads();
    }

    float* o = pkv + ((size_t)ch * 32 + bh) * 4096;
    #pragma unroll
    for (int i = 0; i < 4; i++) {
        float4 v;
        v.x = acc[i][0]; v.y = acc[i][1]; v.z = acc[i][2]; v.w = acc[i][3];
        *(float4*)&o[(td * 4 + i) * 64 + tm * 4] = v;
    }
    if (tm == 0) {
        float* p = pks + ((size_t)ch * 32 + bh) * 64 + td * 4;
        p[0] = ksa[0]; p[1] = ksa[1]; p[2] = ksa[2]; p[3] = ksa[3];
    }
}

__global__ __launch_bounds__(256) void kv_reduce(
    const float* __restrict__ pkv, const float* __restrict__ pks,
    float* __restrict__ kv, float* __restrict__ ks)
{
    const int bh = blockIdx.x, tid = threadIdx.x;
    const int e4 = blockIdx.y * 256 + tid;
    float4 s; s.x = s.y = s.z = s.w = 0.f;
    #pragma unroll
    for (int c = 0; c < SCH; c++) {
        const float4 v = ((const float4*)pkv)[((size_t)c * 32 + bh) * 1024 + e4];
        s.x += v.x; s.y += v.y; s.z += v.z; s.w += v.w;
    }
    ((float4*)kv)[(size_t)bh * 1024 + e4] = s;
    if (blockIdx.y == 0 && tid < 64) {
        float t = 0.f;
        #pragma unroll
        for (int c = 0; c < SCH; c++) t += pks[((size_t)c * 32 + bh) * 64 + tid];
        ks[bh * 64 + tid] = t;
    }
}

// ---------------------------------------------------------------------------
// attn out: 8-token register batches per warp. Q row stride ldq.
// ---------------------------------------------------------------------------
__global__ __launch_bounds__(256) void attn_out(
    const fp16* __restrict__ Q, int ldq, const float* __restrict__ kv,
    const float* __restrict__ ksum, fp16* __restrict__ Oh)
{
    const int bh = blockIdx.x, b = bh >> 3, h = bh & 7;
    __shared__ float kvs[64][64];
    __shared__ float kss[64];
    const int tid = threadIdx.x;
    #pragma unroll
    for (int e = 0; e < 4; e++)
        ((float4*)kvs)[e * 256 + tid] = ((const float4*)kv)[(size_t)bh * 1024 + e * 256 + tid];
    if (tid < 64) kss[tid] = ksum[bh * 64 + tid];
    __syncthreads();

    const int warp = tid >> 5, lane = tid & 31;
    const int lw = blockIdx.y * 128 + warp * 16;

    #pragma unroll
    for (int g = 0; g < 2; g++) {
        const int lt = lw + g * 8;
        float q0[8], q1[8], a0[8], a1[8], z[8];
        #pragma unroll
        for (int t = 0; t < 8; t++) {
            const fp16* q = Q + (size_t)(b * LSEQ + lt + t) * ldq + h * 64;
            q0[t] = __half2float(q[lane]);
            q1[t] = __half2float(q[lane + 32]);
            a0[t] = 0.f; a1[t] = 0.f;
        }
        const float ks0 = kss[lane], ks1 = kss[lane + 32];
        #pragma unroll
        for (int t = 0; t < 8; t++) {
            float zd = q0[t] * ks0 + q1[t] * ks1;
            #pragma unroll
            for (int o = 16; o > 0; o >>= 1) zd += __shfl_xor_sync(0xffffffffu, zd, o);
            z[t] = 1.f / (zd + 1e-6f);
        }
        #pragma unroll
        for (int dd = 0; dd < 32; dd++) {
            const float kA = kvs[dd][lane], kB = kvs[dd][lane + 32];
            #pragma unroll
            for (int t = 0; t < 8; t++) {
                const float qd = __shfl_sync(0xffffffffu, q0[t], dd);
                a0[t] = fmaf(qd, kA, a0[t]);
                a1[t] = fmaf(qd, kB, a1[t]);
            }
        }
        #pragma unroll
        for (int dd = 0; dd < 32; dd++) {
            const float kA = kvs[dd + 32][lane], kB = kvs[dd + 32][lane + 32];
            #pragma unroll
            for (int t = 0; t < 8; t++) {
                const float qd = __shfl_sync(0xffffffffu, q1[t], dd);
                a0[t] = fmaf(qd, kA, a0[t]);
                a1[t] = fmaf(qd, kB, a1[t]);
            }
        }
        #pragma unroll
        for (int t = 0; t < 8; t++) {
            const size_t op = ((size_t)(b * LSEQ + lt + t)) * DMODEL + h * 64;
            Oh[op + lane]      = __float2half_rn(a0[t] * z[t]);
            Oh[op + lane + 32] = __float2half_rn(a1[t] * z[t]);
        }
    }
}

// ---------------------------------------------------------------------------
// LayerNorm (fp16 in/out, fp32 compute): 4 tokens per 256-thread CTA.
// ---------------------------------------------------------------------------
__global__ __launch_bounds__(256) void ln_kernel(
    const fp16* __restrict__ X, const fp16* __restrict__ R,
    const float* __restrict__ gb, fp16* __restrict__ Yh)
{
    const int tid = threadIdx.x;
    const int tok = blockIdx.x * 4 + (tid >> 6);
    const int u = tid & 63;
    const size_t base8 = (size_t)tok * 64;

    const uint4 xv = ((const uint4*)X)[base8 + u];
    float v[8];
    {
        const __half2* xh = (const __half2*)&xv;
        #pragma unroll
        for (int i = 0; i < 4; i++) {
            const float2 f = __half22float2(xh[i]);
            v[2 * i] = f.x; v[2 * i + 1] = f.y;
        }
    }
    if (R) {
        const uint4 rv = ((const uint4*)R)[base8 + u];
        const __half2* rh = (const __half2*)&rv;
        #pragma unroll
        for (int i = 0; i < 4; i++) {
            const float2 f = __half22float2(rh[i]);
            v[2 * i] += f.x; v[2 * i + 1] += f.y;
        }
    }
    float s = 0.f;
    #pragma unroll
    for (int i = 0; i < 8; i++) s += v[i];

    __shared__ float redS[4][2], redQ[4][2];
    const int tk = tid >> 6, w2 = (tid >> 5) & 1;
    #pragma unroll
    for (int o = 16; o > 0; o >>= 1) s += __shfl_xor_sync(0xffffffffu, s, o);
    if ((tid & 31) == 0) redS[tk][w2] = s;
    __syncthreads();
    const float mu = (redS[tk][0] + redS[tk][1]) * (1.f / DMODEL);

    float qq = 0.f;
    #pragma unroll
    for (int i = 0; i < 8; i++) { v[i] -= mu; qq += v[i] * v[i]; }
    #pragma unroll
    for (int o = 16; o > 0; o >>= 1) qq += __shfl_xor_sync(0xffffffffu, qq, o);
    if ((tid & 31) == 0) redQ[tk][w2] = qq;
    __syncthreads();
    const float var = (redQ[tk][0] + redQ[tk][1]) * (1.f / DMODEL);
    const float rstd = rsqrtf(var + 1e-5f);

    const float4 g0 = ((const float4*)gb)[u * 2];
    const float4 g1 = ((const float4*)gb)[u * 2 + 1];
    const float4 b0 = ((const float4*)(gb + DMODEL))[u * 2];
    const float4 b1 = ((const float4*)(gb + DMODEL))[u * 2 + 1];
    float o0 = v[0] * rstd * g0.x + b0.x;
    float o1 = v[1] * rstd * g0.y + b0.y;
    float o2 = v[2] * rstd * g0.z + b0.z;
    float o3 = v[3] * rstd * g0.w + b0.w;
    float o4 = v[4] * rstd * g1.x + b1.x;
    float o5 = v[5] * rstd * g1.y + b1.y;
    float o6 = v[6] * rstd * g1.z + b1.z;
    float o7 = v[7] * rstd * g1.w + b1.w;

    uint4 out;
    __half2 hp;
    hp.x = __float2half_rn(o0); hp.y = __float2half_rn(o1); out.x = *(uint32_t*)&hp;
    hp.x = __float2half_rn(o2); hp.y = __float2half_rn(o3); out.y = *(uint32_t*)&hp;
    hp.x = __float2half_rn(o4); hp.y = __float2half_rn(o5); out.z = *(uint32_t*)&hp;
    hp.x = __float2half_rn(o6); hp.y = __float2half_rn(o7); out.w = *(uint32_t*)&hp;
    ((uint4*)Yh)[base8 + u] = out;
}

__global__ void embed_kernel(
    const float* __restrict__ x, const float* __restrict__ pe,
    const float* __restrict__ ew, const float* __restrict__ eb,
    fp16* __restrict__ hh)
{
    const size_t i4 = (size_t)blockIdx.x * blockDim.x + threadIdx.x;
    const int tok = (int)(i4 >> 7);
    const int j   = (int)(i4 & 127) * 4;
    const int l   = tok & (LSEQ - 1);
    float4 v;
    if (j < 256) {
        const float x0 = x[(size_t)tok * 2], x1 = x[(size_t)tok * 2 + 1];
        const float4 w0 = *(const float4*)(ew + j);
        const float4 w1 = *(const float4*)(ew + 256 + j);
        const float4 b  = *(const float4*)(eb + j);
        v.x = x0 * w0.x + x1 * w1.x + b.x;
        v.y = x0 * w0.y + x1 * w1.y + b.y;
        v.z = x0 * w0.z + x1 * w1.z + b.z;
        v.w = x0 * w0.w + x1 * w1.w + b.w;
    } else {
        v = *(const float4*)(pe + (size_t)l * 256 + (j - 256));
    }
    __half2 h0, h1;
    h0.x = __float2half_rn(v.x); h0.y = __float2half_rn(v.y);
    h1.x = __float2half_rn(v.z); h1.y = __float2half_rn(v.w);
    uint2 pk; pk.x = *(uint32_t*)&h0; pk.y = *(uint32_t*)&h1;
    ((uint2*)hh)[i4] = pk;
}

__global__ void dec_init_kernel(const float* __restrict__ ope, fp16* __restrict__ oh)
{
    const size_t i4 = (size_t)blockIdx.x * blockDim.x + threadIdx.x;
    const size_t tok = i4 >> 7;
    const float4 v = ((const float4*)ope)[((tok & (LSEQ - 1)) << 7) | (i4 & 127)];
    __half2 h0, h1;
    h0.x = __float2half_rn(v.x); h0.y = __float2half_rn(v.y);
    h1.x = __float2half_rn(v.z); h1.y = __float2half_rn(v.w);
    uint2 pk; pk.x = *(uint32_t*)&h0; pk.y = *(uint32_t*)&h1;
    ((uint2*)oh)[i4] = pk;
}

__global__ void pred_kernel(
    const fp16* __restrict__ Xh, const float* __restrict__ pw,
    const float* __restrict__ pb, float* __restrict__ out)
{
    const int gw = (int)(((size_t)blockIdx.x * blockDim.x + threadIdx.x) >> 5);
    const int lane = threadIdx.x & 31;
    if (gw >= NTOK) return;
    const fp16* xr = Xh + (size_t)gw * DMODEL;
    float a0 = 0.f, a1 = 0.f;
    #pragma unroll 4
    for (int j = lane; j < DMODEL; j += 32) {
        const float v = __half2float(xr[j]);
        a0 = fmaf(v, pw[2 * j],     a0);
        a1 = fmaf(v, pw[2 * j + 1], a1);
    }
    #pragma unroll
    for (int o = 16; o > 0; o >>= 1) {
        a0 += __shfl_xor_sync(0xffffffffu, a0, o);
        a1 += __shfl_xor_sync(0xffffffffu, a1, o);
    }
    if (lane == 0) { out[2 * gw] = a0 + pb[0]; out[2 * gw + 1] = a1 + pb[1]; }
}

// ---------------------------------------------------------------------------
// Host orchestration
// ---------------------------------------------------------------------------
struct Ptrs {
    float *pkv, *pks, *kv, *ks;
    fp16 *tmph, *qkv;
    fp16 *hh, *zh, *oh, *ath, *fh;
    fp16 *wha, *whf1, *whf2;
};

static void gemm0(const fp16* a, const fp16* b, const float* bias,
                  fp16* Ch, int M, int N, int K, int ldc) {
    gemm_tc<0><<<dim3(N/128, M/128), 256, SMEM_DYN>>>(a, b, bias, Ch, M, N, K, ldc, 0);
}
static void gemm1(const fp16* a, const fp16* b, const float* bias,
                  fp16* Ch, int M, int N, int K, int ldc) {
    gemm_tc<1><<<dim3(N/128, M/128), 256, SMEM_DYN>>>(a, b, bias, Ch, M, N, K, ldc, 0);
}
static void gemm2(const fp16* a, const fp16* b, const float* bias,
                  fp16* Ch, int M, int N, int K, int ldc) {
    gemm_tc<2><<<dim3(N/128, M/128), 256, SMEM_DYN>>>(a, b, bias, Ch, M, N, K, ldc, 0);
}
static void gemm3(const fp16* a, const fp16* b, const float* bias,
                  fp16* Ch, int M, int N, int K, int ldc, int phi_lim) {
    gemm_tc<3><<<dim3(N/128, M/128), 256, SMEM_DYN>>>(a, b, bias, Ch, M, N, K, ldc, phi_lim);
}

// self-attention: one fused QKV GEMM (N=1536, phi on cols < 1024).
static void attention_self(const fp16* xh, const fp16* wh, const float* b, const Ptrs& P)
{
    gemm3(xh, wh, b, P.qkv, NTOK, 1536, DMODEL, 1536, 1024);
    kv_partial<<<dim3(32, SCH), 256>>>(P.qkv + 512, 1536, P.qkv + 1024, 1536, P.pkv, P.pks);
    kv_reduce<<<dim3(32, 4), 256>>>(P.pkv, P.pks, P.kv, P.ks);
    attn_out<<<dim3(32, 32), 256>>>(P.qkv, 1536, P.kv, P.ks, P.ath);
    gemm0(P.ath, wh + (size_t)3 * DMODEL * DMODEL, b + 3 * DMODEL, P.tmph, NTOK, DMODEL, DMODEL, DMODEL);
}

// cross-attention: Q GEMM + fused K|V GEMM (N=1024, phi on cols < 512).
static void attention_cross(const fp16* xqh, const fp16* xkh,
                            const fp16* wh, const float* b, const Ptrs& P)
{
    const size_t WS = (size_t)DMODEL * DMODEL;
    gemm2(xqh, wh, b, P.qkv, NTOK, DMODEL, DMODEL, 1536);
    gemm3(xkh, wh + 1 * WS, b + 1 * DMODEL, P.qkv + 512, NTOK, 1024, DMODEL, 1536, 512);

    kv_partial<<<dim3(32, SCH), 256>>>(P.qkv + 512, 1536, P.qkv + 1024, 1536, P.pkv, P.pks);
    kv_reduce<<<dim3(32, 4), 256>>>(P.pkv, P.pks, P.kv, P.ks);
    attn_out<<<dim3(32, 32), 256>>>(P.qkv, 1536, P.kv, P.ks, P.ath);
    gemm0(P.ath, wh + 3 * WS, b + 3 * DMODEL, P.tmph, NTOK, DMODEL, DMODEL, DMODEL);
}

extern "C" void kernel_launch(void* const* d_in, const int* in_sizes, int n_in,
                              void* d_out, int out_size)
{
    const float* x            = (const float*)d_in[0];
    const float* out_pos_emb  = (const float*)d_in[1];
    const float* pe_input     = (const float*)d_in[2];
    const float* emb_w        = (const float*)d_in[3];
    const float* emb_b        = (const float*)d_in[4];
    const float* enc_attn_w   = (const float*)d_in[5];
    const float* enc_attn_b   = (const float*)d_in[6];
    const float* enc_ln       = (const float*)d_in[7];
    const float* enc_ff_w1    = (const float*)d_in[8];
    const float* enc_ff_b1    = (const float*)d_in[9];
    const float* enc_ff_w2    = (const float*)d_in[10];
    const float* enc_ff_b2    = (const float*)d_in[11];
    const float* enc_final_ln = (const float*)d_in[12];
    const float* dec_self_w   = (const float*)d_in[13];
    const float* dec_self_b   = (const float*)d_in[14];
    const float* dec_cross_w  = (const float*)d_in[15];
    const float* dec_cross_b  = (const float*)d_in[16];
    const float* dec_ln       = (const float*)d_in[17];
    const float* dec_ff_w1    = (const float*)d_in[18];
    const float* dec_ff_b1    = (const float*)d_in[19];
    const float* dec_ff_w2    = (const float*)d_in[20];
    const float* dec_ff_b2    = (const float*)d_in[21];
    const float* dec_final_ln = (const float*)d_in[22];
    const float* pred_w       = (const float*)d_in[23];
    const float* pred_b       = (const float*)d_in[24];

    cudaFuncSetAttribute(gemm_tc<0>, cudaFuncAttributeMaxDynamicSharedMemorySize, SMEM_DYN);
    cudaFuncSetAttribute(gemm_tc<1>, cudaFuncAttributeMaxDynamicSharedMemorySize, SMEM_DYN);
    cudaFuncSetAttribute(gemm_tc<2>, cudaFuncAttributeMaxDynamicSharedMemorySize, SMEM_DYN);
    cudaFuncSetAttribute(gemm_tc<3>, cudaFuncAttributeMaxDynamicSharedMemorySize, SMEM_DYN);

    unsigned char* S = nullptr;
    cudaGetSymbolAddress((void**)&S, g_scratch);

    Ptrs P;
    P.tmph = (fp16*)(S + B_TMPH);
    P.qkv  = (fp16*)(S + B_QKV);
    P.pkv  = (float*)(S + B_PKV); P.pks = (float*)(S + B_PKS);
    P.kv   = (float*)(S + B_KVB); P.ks  = (float*)(S + B_KSB);
    P.hh   = (fp16*)(S + B_HH);   P.zh  = (fp16*)(S + B_ZH);
    P.oh   = (fp16*)(S + B_OH);   P.ath = (fp16*)(S + B_ATH);
    P.fh   = (fp16*)(S + B_FH);
    P.wha  = (fp16*)(S + B_WHA);
    P.whf1 = (fp16*)(S + B_WHF1);
    P.whf2 = (fp16*)(S + B_WHF2);

    // ---- transpose + fp16-round all weights ----
    transpose_w16<<<dim3(16, 16, 16), 256>>>(enc_attn_w,  P.wha,                     512, 512);
    transpose_w16<<<dim3(16, 16, 16), 256>>>(dec_self_w,  P.wha + (size_t)16*262144, 512, 512);
    transpose_w16<<<dim3(16, 16, 16), 256>>>(dec_cross_w, P.wha + (size_t)32*262144, 512, 512);
    transpose_w16<<<dim3(64, 16, 4),  256>>>(enc_ff_w1, P.whf1,                      512, 2048);
    transpose_w16<<<dim3(64, 16, 4),  256>>>(dec_ff_w1, P.whf1 + (size_t)4*1048576,  512, 2048);
    transpose_w16<<<dim3(16, 64, 4),  256>>>(enc_ff_w2, P.whf2,                      2048, 512);
    transpose_w16<<<dim3(16, 64, 4),  256>>>(dec_ff_w2, P.whf2 + (size_t)4*1048576,  2048, 512);

    const size_t WT4 = (size_t)4 * DMODEL * DMODEL;
    const size_t W1S = (size_t)DFF * DMODEL;
    const size_t W2S = (size_t)DMODEL * DFF;

    // ---- embed ----
    embed_kernel<<<(NTOK * 128) / 256, 256>>>(x, pe_input, emb_w, emb_b, P.hh);

    // ---- encoder ----
    for (int l = 0; l < 4; l++) {
        const float* ln = enc_ln + (size_t)l * 2 * 2 * DMODEL;
        attention_self(P.hh, P.wha + (size_t)l * WT4,
                       enc_attn_b + (size_t)l * 4 * DMODEL, P);
        ln_kernel<<<NTOK / 4, 256>>>(P.hh, P.tmph, ln, P.hh);
        gemm1(P.hh, P.whf1 + (size_t)l * W1S,
              enc_ff_b1 + (size_t)l * DFF, P.fh, NTOK, DFF, DMODEL, DFF);
        gemm0(P.fh, P.whf2 + (size_t)l * W2S,
              enc_ff_b2 + (size_t)l * DMODEL, P.tmph, NTOK, DMODEL, DFF, DMODEL);
        ln_kernel<<<NTOK / 4, 256>>>(P.hh, P.tmph, ln + 2 * DMODEL, P.hh);
    }
    ln_kernel<<<NTOK / 4, 256>>>(P.hh, nullptr, enc_final_ln, P.zh);

    // ---- decoder ----
    dec_init_kernel<<<(NTOK * 128) / 256, 256>>>(out_pos_emb, P.oh);
    for (int l = 0; l < 4; l++) {
        const float* ln = dec_ln + (size_t)l * 3 * 2 * DMODEL;
        attention_self(P.oh, P.wha + (size_t)(16 + l * 4) * DMODEL * DMODEL,
                       dec_self_b + (size_t)l * 4 * DMODEL, P);
        ln_kernel<<<NTOK / 4, 256>>>(P.oh, P.tmph, ln, P.oh);
        attention_cross(P.oh, P.zh,
                        P.wha + (size_t)(32 + l * 4) * DMODEL * DMODEL,
                        dec_cross_b + (size_t)l * 4 * DMODEL, P);
        ln_kernel<<<NTOK / 4, 256>>>(P.oh, P.tmph, ln + 2 * DMODEL, P.oh);
        gemm1(P.oh, P.whf1 + (size_t)(4 + l) * W1S,
              dec_ff_b1 + (size_t)l * DFF, P.fh, NTOK, DFF, DMODEL, DFF);
        gemm0(P.fh, P.whf2 + (size_t)(4 + l) * W2S,
              dec_ff_b2 + (size_t)l * DMODEL, P.tmph, NTOK, DMODEL, DFF, DMODEL);
        ln_kernel<<<NTOK / 4, 256>>>(P.oh, P.tmph, ln + 4 * DMODEL, P.oh);
    }
    ln_kernel<<<NTOK / 4, 256>>>(P.oh, nullptr, dec_final_ln, P.ath);

    // ---- prediction head ----
    pred_kernel<<<(NTOK * 32) / 256, 256>>>(P.ath, pred_w, pred_b, (float*)d_out);
}

// round 15
// speedup vs baseline: 2.0710x; 1.0178x over previous
#include <cuda_runtime.h>
#include <cuda_fp16.h>
#include <cstdint>
#include <cstddef>

// ---------------------------------------------------------------------------
// TRecTransformer: linear-attention encoder/decoder.
// GEMMs: plain fp16 mma.sync m16n8k16 (fp32 accum). fp16 glue trunk.
// This round: kv_partial moved to tensor cores (ldmatrix.trans + mma.sync,
// fp32 accumulation -- no new rounding vs FFMA version).
// ---------------------------------------------------------------------------

#define NTOK   16384
#define DMODEL 512
#define DFF    2048
#define LSEQ   4096
#define SCH    16

#define SZ ((size_t)NTOK * DMODEL)        // 8,388,608 elements

// ---- scratch layout (BYTE offsets) ----
#define B_TMPH  ((size_t)0)               // fp16 sublayer output [NTOK,512]
#define B_QKV   (B_TMPH + SZ*2)           // fp16 [NTOK,1536]: Q|K|V
#define B_PKV   (B_QKV + SZ*6)
#define B_PKS   (B_PKV + (size_t)SCH*32*4096*4)
#define B_KVB   (B_PKS + (size_t)SCH*32*64*4)
#define B_KSB   (B_KVB + (size_t)32*4096*4)
#define B_HH    (B_KSB + (size_t)32*64*4) // fp16 trunk (encoder)
#define B_ZH    (B_HH  + SZ*2)
#define B_OH    (B_ZH  + SZ*2)            // fp16 trunk (decoder)
#define B_ATH   (B_OH  + SZ*2)
#define B_FH    (B_ATH + SZ*2)            // NTOK*DFF halves
#define B_WHA   (B_FH  + SZ*8)            // 48 x 512x512
#define B_WHF1  (B_WHA + (size_t)48*262144*2)
#define B_WHF2  (B_WHF1 + (size_t)8*1048576*2)
#define TOTAL_B (B_WHF2 + (size_t)8*1048576*2)

__device__ __align__(1024) unsigned char g_scratch[TOTAL_B];

typedef __half fp16;

// ---------------------------------------------------------------------------
// helpers
// ---------------------------------------------------------------------------
__device__ __forceinline__ uint32_t smem_u32(const void* p) {
    uint32_t a;
    asm("{ .reg .u64 t; cvta.to.shared.u64 t, %1; cvt.u32.u64 %0, t; }" : "=r"(a) : "l"(p));
    return a;
}
__device__ __forceinline__ void ldsm4(uint32_t* r, uint32_t addr) {
    asm volatile("ldmatrix.sync.aligned.m8n8.x4.shared.b16 {%0,%1,%2,%3}, [%4];"
        : "=r"(r[0]), "=r"(r[1]), "=r"(r[2]), "=r"(r[3]) : "r"(addr));
}
__device__ __forceinline__ void ldsm4t(uint32_t* r, uint32_t addr) {
    asm volatile("ldmatrix.sync.aligned.m8n8.x4.trans.shared.b16 {%0,%1,%2,%3}, [%4];"
        : "=r"(r[0]), "=r"(r[1]), "=r"(r[2]), "=r"(r[3]) : "r"(addr));
}
__device__ __forceinline__ void mma_f16(float* c, const uint32_t* a, const uint32_t* b) {
    asm volatile(
        "mma.sync.aligned.m16n8k16.row.col.f32.f16.f16.f32 "
        "{%0,%1,%2,%3}, {%4,%5,%6,%7}, {%8,%9}, {%0,%1,%2,%3};"
        : "+f"(c[0]), "+f"(c[1]), "+f"(c[2]), "+f"(c[3])
        : "r"(a[0]), "r"(a[1]), "r"(a[2]), "r"(a[3]), "r"(b[0]), "r"(b[1]));
}
__device__ __forceinline__ void cp16(uint32_t d, const void* s) {
    asm volatile("cp.async.cg.shared.global [%0], [%1], 16;" :: "r"(d), "l"(s));
}
__device__ __forceinline__ void cp_commit() { asm volatile("cp.async.commit_group;" ::: "memory"); }
__device__ __forceinline__ void cp_wait1()  { asm volatile("cp.async.wait_group 1;" ::: "memory"); }
__device__ __forceinline__ void cp_wait0()  { asm volatile("cp.async.wait_group 0;" ::: "memory"); }

// ---------------------------------------------------------------------------
// GEMM: Ch[M,N](ldc) = act(A[M,K] @ W[N,K]^T + bias), fp16 out.
// ACT: 0 none, 1 relu, 2 phi=elu+1, 3 phi iff col < phi_lim (uniform/warp).
// ---------------------------------------------------------------------------
#define ROWB 80
#define MATB 10240
#define STGB 20480
#define SMEM_DYN (3 * STGB)

template<int ACT>
__global__ __launch_bounds__(256) void gemm_tc(
    const fp16* __restrict__ A, const fp16* __restrict__ B,
    const float* __restrict__ bias, fp16* __restrict__ Ch,
    int M, int N, int K, int ldc, int phi_lim)
{
    extern __shared__ char smc[];
    const uint32_t smB = smem_u32(smc);

    const int tid = threadIdx.x, lane = tid & 31, wid = tid >> 5;
    const int row0 = blockIdx.y * 128, col0 = blockIdx.x * 128;
    const int wm = wid & 1, wn = wid >> 1;

    float acc[4][4][4];
    #pragma unroll
    for (int i = 0; i < 4; i++)
        #pragma unroll
        for (int j = 0; j < 4; j++)
            #pragma unroll
            for (int e = 0; e < 4; e++) acc[i][j][e] = 0.f;

    const uint32_t aoff = (uint32_t)((wm * 64 + (lane & 7) + ((lane >> 3) & 1) * 8) * ROWB
                                     + (lane >> 4) * 16);
    const uint32_t boff = (uint32_t)((wn * 32 + (lane >> 4) * 8 + (lane & 7)) * ROWB
                                     + ((lane >> 3) & 1) * 16);

    const int NC = K / 32;
    const int pr = tid >> 2;
    const int pb = (tid & 3) * 16;

    auto loadst = [&](int c, int s) {
        const int k0 = c * 32;
        const uint32_t st = smB + (uint32_t)s * STGB;
        #pragma unroll
        for (int m = 0; m < 2; m++) {
            const fp16* g = (m == 0) ? A : B;
            const int rb = (m == 0) ? row0 : col0;
            #pragma unroll
            for (int hf = 0; hf < 2; hf++) {
                const int r = hf * 64 + pr;
                cp16(st + m * MATB + r * ROWB + pb,
                     (const char*)(g + (size_t)(rb + r) * K + k0) + pb);
            }
        }
    };

    auto compute = [&](int s) {
        const uint32_t base = smB + (uint32_t)s * STGB;
        #pragma unroll
        for (int ks = 0; ks < 2; ks++) {
            uint32_t ar[4][4], br[4][2];
            #pragma unroll
            for (int mi = 0; mi < 4; mi++)
                ldsm4(ar[mi], base + aoff + mi * 1280 + ks * 32);
            #pragma unroll
            for (int j = 0; j < 2; j++) {
                uint32_t t[4];
                ldsm4(t, base + MATB + boff + j * 1280 + ks * 32);
                br[2 * j][0] = t[0]; br[2 * j][1] = t[1];
                br[2 * j + 1][0] = t[2]; br[2 * j + 1][1] = t[3];
            }
            #pragma unroll
            for (int mi = 0; mi < 4; mi++)
                #pragma unroll
                for (int ni = 0; ni < 4; ni++) mma_f16(acc[mi][ni], ar[mi], br[ni]);
        }
    };

    loadst(0, 0); cp_commit();
    loadst(1, 1); cp_commit();
    for (int c = 0; c < NC; c++) {
        if (c + 1 < NC) cp_wait1(); else cp_wait0();
        __syncthreads();
        compute(c % 3);
        if (c + 2 < NC) { loadst(c + 2, (c + 2) % 3); cp_commit(); }
    }

    const int gm0 = row0 + wm * 64;
    const int gn0 = col0 + wn * 32;
    #pragma unroll
    for (int ni = 0; ni < 4; ni++) {
        const int cn = gn0 + ni * 8 + (lane & 3) * 2;
        const float b0 = bias[cn], b1 = bias[cn + 1];
        const bool dophi = (ACT == 2) || (ACT == 3 && cn < phi_lim);
        #pragma unroll
        for (int mi = 0; mi < 4; mi++) {
            const int rm = gm0 + mi * 16 + (lane >> 2);
            float t0 = acc[mi][ni][0] + b0;
            float t1 = acc[mi][ni][1] + b1;
            float t2 = acc[mi][ni][2] + b0;
            float t3 = acc[mi][ni][3] + b1;
            if (ACT == 1) {
                t0 = fmaxf(t0, 0.f); t1 = fmaxf(t1, 0.f);
                t2 = fmaxf(t2, 0.f); t3 = fmaxf(t3, 0.f);
            }
            if (ACT == 2 || ACT == 3) {
                if (dophi) {
                    t0 = t0 > 0.f ? t0 + 1.f : __expf(t0);
                    t1 = t1 > 0.f ? t1 + 1.f : __expf(t1);
                    t2 = t2 > 0.f ? t2 + 1.f : __expf(t2);
                    t3 = t3 > 0.f ? t3 + 1.f : __expf(t3);
                }
            }
            __half2 hp;
            hp.x = __float2half_rn(t0); hp.y = __float2half_rn(t1);
            *(__half2*)&Ch[(size_t)rm * ldc + cn] = hp;
            hp.x = __float2half_rn(t2); hp.y = __float2half_rn(t3);
            *(__half2*)&Ch[(size_t)(rm + 8) * ldc + cn] = hp;
        }
    }
}

// ---------------------------------------------------------------------------
// fused weight transpose + fp16 round: W[K,N] fp32 -> Wh [N,K] fp16
// ---------------------------------------------------------------------------
__global__ __launch_bounds__(256) void transpose_w16(
    const float* __restrict__ W, fp16* __restrict__ Wh, int K, int N)
{
    __shared__ float t[32][33];
    const size_t mo = (size_t)blockIdx.z * K * N;
    const float* Wm = W + mo;
    const int n0 = blockIdx.x * 32, k0 = blockIdx.y * 32;
    const int tx = threadIdx.x & 31, ty = threadIdx.x >> 5;
    #pragma unroll
    for (int i = 0; i < 32; i += 8)
        t[ty + i][tx] = Wm[(size_t)(k0 + ty + i) * N + n0 + tx];
    __syncthreads();
    #pragma unroll
    for (int i = 0; i < 32; i += 8)
        Wh[mo + (size_t)(n0 + ty + i) * K + k0 + tx] = __float2half_rn(t[tx][ty + i]);
}

// ---------------------------------------------------------------------------
// kv partial (tensor-core): kv[d,m] = sum_s K[s,d]*V[s,m] via mma.sync,
// fp32 accum. 8 warps = 4(d) x 2(m); each warp 16x32 tile. 32-s smem stages.
// ksum computed alongside (4 rows per warp per stage), smem cross-warp reduce.
// ---------------------------------------------------------------------------
__global__ __launch_bounds__(256) void kv_partial(
    const fp16* __restrict__ Kt, int ldk,
    const fp16* __restrict__ Vt, int ldv,
    float* __restrict__ pkv, float* __restrict__ pks)
{
    const int bh = blockIdx.x, ch = blockIdx.y;
    const int b = bh >> 3, h = bh & 7;
    const int tid = threadIdx.x, lane = tid & 31, wid = tid >> 5;
    const int wd = wid & 3, wm = wid >> 2;

    __shared__ fp16 Ks[32][64];
    __shared__ fp16 Vs[32][64];
    __shared__ float ksm[8][64];

    const uint32_t kb = smem_u32(Ks), vb = smem_u32(Vs);

    float acc[4][4];
    #pragma unroll
    for (int i = 0; i < 4; i++)
        #pragma unroll
        for (int j = 0; j < 4; j++) acc[i][j] = 0.f;
    float ks0 = 0.f, ks1 = 0.f;

    // ldmatrix.trans lane byte offsets (within a 16-s k-step at row base rs):
    // A (K tile): row = rs + (lane&7) + ((lane>>4)&1)*8 ; col d = wd*16 + ((lane>>3)&1)*8
    const uint32_t arow = (uint32_t)((lane & 7) + ((lane >> 4) & 1) * 8);
    const uint32_t aadd = arow * 128 + (uint32_t)wd * 32 + ((lane >> 3) & 1) * 16;
    // B (V tile): row = rs + (lane&7) + ((lane>>3)&1)*8 ; col m = mb + ((lane>>4)&1)*8
    const uint32_t brow = (uint32_t)((lane & 7) + ((lane >> 3) & 1) * 8);
    const uint32_t badd = brow * 128 + (uint32_t)wm * 64 + ((lane >> 4) & 1) * 16;

    const int lrow = tid >> 3, lcol = (tid & 7) * 8;
    const int s0 = ch * (LSEQ / SCH);

    for (int st = 0; st < 8; st++) {
        const size_t row = (size_t)(b * LSEQ + s0 + st * 32 + lrow);
        *(uint4*)&Ks[lrow][lcol] = *(const uint4*)(Kt + row * ldk + h * 64 + lcol);
        *(uint4*)&Vs[lrow][lcol] = *(const uint4*)(Vt + row * ldv + h * 64 + lcol);
        __syncthreads();

        // ksum partial: warp w sums rows wid*4..+3, lane covers d = 2*lane, 2*lane+1
        #pragma unroll
        for (int r = 0; r < 4; r++) {
            const float2 kf = __half22float2(*(const __half2*)&Ks[wid * 4 + r][lane * 2]);
            ks0 += kf.x; ks1 += kf.y;
        }

        #pragma unroll
        for (int ks2 = 0; ks2 < 2; ks2++) {
            const uint32_t rb = (uint32_t)(ks2 * 16) * 128;
            uint32_t ah[4], t0[4], t1[4];
            ldsm4t(ah, kb + rb + aadd);
            ldsm4t(t0, vb + rb + badd);
            ldsm4t(t1, vb + rb + badd + 32);   // m + 16
            uint32_t br0[2] = { t0[0], t0[1] };
            uint32_t br1[2] = { t0[2], t0[3] };
            uint32_t br2[2] = { t1[0], t1[1] };
            uint32_t br3[2] = { t1[2], t1[3] };
            mma_f16(acc[0], ah, br0);
            mma_f16(acc[1], ah, br1);
            mma_f16(acc[2], ah, br2);
            mma_f16(acc[3], ah, br3);
        }
        __syncthreads();
    }

    // write pkv: warp tile rows d = wd*16 + (lane>>2) (+8), cols m = wm*32 + ni*8 + (lane&3)*2
    float* o = pkv + ((size_t)ch * 32 + bh) * 4096;
    const int d0 = wd * 16 + (lane >> 2);
    #pragma unroll
    for (int ni = 0; ni < 4; ni++) {
        const int m = wm * 32 + ni * 8 + (lane & 3) * 2;
        float2 v0; v0.x = acc[ni][0]; v0.y = acc[ni][1];
        float2 v1; v1.x = acc[ni][2]; v1.y = acc[ni][3];
        *(float2*)&o[(size_t)d0 * 64 + m]       = v0;
        *(float2*)&o[(size_t)(d0 + 8) * 64 + m] = v1;
    }

    // ksum cross-warp reduce
    ksm[wid][lane * 2]     = ks0;
    ksm[wid][lane * 2 + 1] = ks1;
    __syncthreads();
    if (tid < 64) {
        float s = 0.f;
        #pragma unroll
        for (int w = 0; w < 8; w++) s += ksm[w][tid];
        pks[((size_t)ch * 32 + bh) * 64 + tid] = s;
    }
}

__global__ __launch_bounds__(256) void kv_reduce(
    const float* __restrict__ pkv, const float* __restrict__ pks,
    float* __restrict__ kv, float* __restrict__ ks)
{
    const int bh = blockIdx.x, tid = threadIdx.x;
    const int e4 = blockIdx.y * 256 + tid;
    float4 s; s.x = s.y = s.z = s.w = 0.f;
    #pragma unroll
    for (int c = 0; c < SCH; c++) {
        const float4 v = ((const float4*)pkv)[((size_t)c * 32 + bh) * 1024 + e4];
        s.x += v.x; s.y += v.y; s.z += v.z; s.w += v.w;
    }
    ((float4*)kv)[(size_t)bh * 1024 + e4] = s;
    if (blockIdx.y == 0 && tid < 64) {
        float t = 0.f;
        #pragma unroll
        for (int c = 0; c < SCH; c++) t += pks[((size_t)c * 32 + bh) * 64 + tid];
        ks[bh * 64 + tid] = t;
    }
}

// ---------------------------------------------------------------------------
// attn out: 8-token register batches per warp. Q row stride ldq.
// ---------------------------------------------------------------------------
__global__ __launch_bounds__(256) void attn_out(
    const fp16* __restrict__ Q, int ldq, const float* __restrict__ kv,
    const float* __restrict__ ksum, fp16* __restrict__ Oh)
{
    const int bh = blockIdx.x, b = bh >> 3, h = bh & 7;
    __shared__ float kvs[64][64];
    __shared__ float kss[64];
    const int tid = threadIdx.x;
    #pragma unroll
    for (int e = 0; e < 4; e++)
        ((float4*)kvs)[e * 256 + tid] = ((const float4*)kv)[(size_t)bh * 1024 + e * 256 + tid];
    if (tid < 64) kss[tid] = ksum[bh * 64 + tid];
    __syncthreads();

    const int warp = tid >> 5, lane = tid & 31;
    const int lw = blockIdx.y * 128 + warp * 16;

    #pragma unroll
    for (int g = 0; g < 2; g++) {
        const int lt = lw + g * 8;
        float q0[8], q1[8], a0[8], a1[8], z[8];
        #pragma unroll
        for (int t = 0; t < 8; t++) {
            const fp16* q = Q + (size_t)(b * LSEQ + lt + t) * ldq + h * 64;
            q0[t] = __half2float(q[lane]);
            q1[t] = __half2float(q[lane + 32]);
            a0[t] = 0.f; a1[t] = 0.f;
        }
        const float ks0 = kss[lane], ks1 = kss[lane + 32];
        #pragma unroll
        for (int t = 0; t < 8; t++) {
            float zd = q0[t] * ks0 + q1[t] * ks1;
            #pragma unroll
            for (int o = 16; o > 0; o >>= 1) zd += __shfl_xor_sync(0xffffffffu, zd, o);
            z[t] = 1.f / (zd + 1e-6f);
        }
        #pragma unroll
        for (int dd = 0; dd < 32; dd++) {
            const float kA = kvs[dd][lane], kB = kvs[dd][lane + 32];
            #pragma unroll
            for (int t = 0; t < 8; t++) {
                const float qd = __shfl_sync(0xffffffffu, q0[t], dd);
                a0[t] = fmaf(qd, kA, a0[t]);
                a1[t] = fmaf(qd, kB, a1[t]);
            }
        }
        #pragma unroll
        for (int dd = 0; dd < 32; dd++) {
            const float kA = kvs[dd + 32][lane], kB = kvs[dd + 32][lane + 32];
            #pragma unroll
            for (int t = 0; t < 8; t++) {
                const float qd = __shfl_sync(0xffffffffu, q1[t], dd);
                a0[t] = fmaf(qd, kA, a0[t]);
                a1[t] = fmaf(qd, kB, a1[t]);
            }
        }
        #pragma unroll
        for (int t = 0; t < 8; t++) {
            const size_t op = ((size_t)(b * LSEQ + lt + t)) * DMODEL + h * 64;
            Oh[op + lane]      = __float2half_rn(a0[t] * z[t]);
            Oh[op + lane + 32] = __float2half_rn(a1[t] * z[t]);
        }
    }
}

// ---------------------------------------------------------------------------
// LayerNorm (fp16 in/out, fp32 compute): 4 tokens per 256-thread CTA.
// ---------------------------------------------------------------------------
__global__ __launch_bounds__(256) void ln_kernel(
    const fp16* __restrict__ X, const fp16* __restrict__ R,
    const float* __restrict__ gb, fp16* __restrict__ Yh)
{
    const int tid = threadIdx.x;
    const int tok = blockIdx.x * 4 + (tid >> 6);
    const int u = tid & 63;
    const size_t base8 = (size_t)tok * 64;

    const uint4 xv = ((const uint4*)X)[base8 + u];
    float v[8];
    {
        const __half2* xh = (const __half2*)&xv;
        #pragma unroll
        for (int i = 0; i < 4; i++) {
            const float2 f = __half22float2(xh[i]);
            v[2 * i] = f.x; v[2 * i + 1] = f.y;
        }
    }
    if (R) {
        const uint4 rv = ((const uint4*)R)[base8 + u];
        const __half2* rh = (const __half2*)&rv;
        #pragma unroll
        for (int i = 0; i < 4; i++) {
            const float2 f = __half22float2(rh[i]);
            v[2 * i] += f.x; v[2 * i + 1] += f.y;
        }
    }
    float s = 0.f;
    #pragma unroll
    for (int i = 0; i < 8; i++) s += v[i];

    __shared__ float redS[4][2], redQ[4][2];
    const int tk = tid >> 6, w2 = (tid >> 5) & 1;
    #pragma unroll
    for (int o = 16; o > 0; o >>= 1) s += __shfl_xor_sync(0xffffffffu, s, o);
    if ((tid & 31) == 0) redS[tk][w2] = s;
    __syncthreads();
    const float mu = (redS[tk][0] + redS[tk][1]) * (1.f / DMODEL);

    float qq = 0.f;
    #pragma unroll
    for (int i = 0; i < 8; i++) { v[i] -= mu; qq += v[i] * v[i]; }
    #pragma unroll
    for (int o = 16; o > 0; o >>= 1) qq += __shfl_xor_sync(0xffffffffu, qq, o);
    if ((tid & 31) == 0) redQ[tk][w2] = qq;
    __syncthreads();
    const float var = (redQ[tk][0] + redQ[tk][1]) * (1.f / DMODEL);
    const float rstd = rsqrtf(var + 1e-5f);

    const float4 g0 = ((const float4*)gb)[u * 2];
    const float4 g1 = ((const float4*)gb)[u * 2 + 1];
    const float4 b0 = ((const float4*)(gb + DMODEL))[u * 2];
    const float4 b1 = ((const float4*)(gb + DMODEL))[u * 2 + 1];
    float o0 = v[0] * rstd * g0.x + b0.x;
    float o1 = v[1] * rstd * g0.y + b0.y;
    float o2 = v[2] * rstd * g0.z + b0.z;
    float o3 = v[3] * rstd * g0.w + b0.w;
    float o4 = v[4] * rstd * g1.x + b1.x;
    float o5 = v[5] * rstd * g1.y + b1.y;
    float o6 = v[6] * rstd * g1.z + b1.z;
    float o7 = v[7] * rstd * g1.w + b1.w;

    uint4 out;
    __half2 hp;
    hp.x = __float2half_rn(o0); hp.y = __float2half_rn(o1); out.x = *(uint32_t*)&hp;
    hp.x = __float2half_rn(o2); hp.y = __float2half_rn(o3); out.y = *(uint32_t*)&hp;
    hp.x = __float2half_rn(o4); hp.y = __float2half_rn(o5); out.z = *(uint32_t*)&hp;
    hp.x = __float2half_rn(o6); hp.y = __float2half_rn(o7); out.w = *(uint32_t*)&hp;
    ((uint4*)Yh)[base8 + u] = out;
}

__global__ void embed_kernel(
    const float* __restrict__ x, const float* __restrict__ pe,
    const float* __restrict__ ew, const float* __restrict__ eb,
    fp16* __restrict__ hh)
{
    const size_t i4 = (size_t)blockIdx.x * blockDim.x + threadIdx.x;
    const int tok = (int)(i4 >> 7);
    const int j   = (int)(i4 & 127) * 4;
    const int l   = tok & (LSEQ - 1);
    float4 v;
    if (j < 256) {
        const float x0 = x[(size_t)tok * 2], x1 = x[(size_t)tok * 2 + 1];
        const float4 w0 = *(const float4*)(ew + j);
        const float4 w1 = *(const float4*)(ew + 256 + j);
        const float4 b  = *(const float4*)(eb + j);
        v.x = x0 * w0.x + x1 * w1.x + b.x;
        v.y = x0 * w0.y + x1 * w1.y + b.y;
        v.z = x0 * w0.z + x1 * w1.z + b.z;
        v.w = x0 * w0.w + x1 * w1.w + b.w;
    } else {
        v = *(const float4*)(pe + (size_t)l * 256 + (j - 256));
    }
    __half2 h0, h1;
    h0.x = __float2half_rn(v.x); h0.y = __float2half_rn(v.y);
    h1.x = __float2half_rn(v.z); h1.y = __float2half_rn(v.w);
    uint2 pk; pk.x = *(uint32_t*)&h0; pk.y = *(uint32_t*)&h1;
    ((uint2*)hh)[i4] = pk;
}

__global__ void dec_init_kernel(const float* __restrict__ ope, fp16* __restrict__ oh)
{
    const size_t i4 = (size_t)blockIdx.x * blockDim.x + threadIdx.x;
    const size_t tok = i4 >> 7;
    const float4 v = ((const float4*)ope)[((tok & (LSEQ - 1)) << 7) | (i4 & 127)];
    __half2 h0, h1;
    h0.x = __float2half_rn(v.x); h0.y = __float2half_rn(v.y);
    h1.x = __float2half_rn(v.z); h1.y = __float2half_rn(v.w);
    uint2 pk; pk.x = *(uint32_t*)&h0; pk.y = *(uint32_t*)&h1;
    ((uint2*)oh)[i4] = pk;
}

__global__ void pred_kernel(
    const fp16* __restrict__ Xh, const float* __restrict__ pw,
    const float* __restrict__ pb, float* __restrict__ out)
{
    const int gw = (int)(((size_t)blockIdx.x * blockDim.x + threadIdx.x) >> 5);
    const int lane = threadIdx.x & 31;
    if (gw >= NTOK) return;
    const fp16* xr = Xh + (size_t)gw * DMODEL;
    float a0 = 0.f, a1 = 0.f;
    #pragma unroll 4
    for (int j = lane; j < DMODEL; j += 32) {
        const float v = __half2float(xr[j]);
        a0 = fmaf(v, pw[2 * j],     a0);
        a1 = fmaf(v, pw[2 * j + 1], a1);
    }
    #pragma unroll
    for (int o = 16; o > 0; o >>= 1) {
        a0 += __shfl_xor_sync(0xffffffffu, a0, o);
        a1 += __shfl_xor_sync(0xffffffffu, a1, o);
    }
    if (lane == 0) { out[2 * gw] = a0 + pb[0]; out[2 * gw + 1] = a1 + pb[1]; }
}

// ---------------------------------------------------------------------------
// Host orchestration
// ---------------------------------------------------------------------------
struct Ptrs {
    float *pkv, *pks, *kv, *ks;
    fp16 *tmph, *qkv;
    fp16 *hh, *zh, *oh, *ath, *fh;
    fp16 *wha, *whf1, *whf2;
};

static void gemm0(const fp16* a, const fp16* b, const float* bias,
                  fp16* Ch, int M, int N, int K, int ldc) {
    gemm_tc<0><<<dim3(N/128, M/128), 256, SMEM_DYN>>>(a, b, bias, Ch, M, N, K, ldc, 0);
}
static void gemm1(const fp16* a, const fp16* b, const float* bias,
                  fp16* Ch, int M, int N, int K, int ldc) {
    gemm_tc<1><<<dim3(N/128, M/128), 256, SMEM_DYN>>>(a, b, bias, Ch, M, N, K, ldc, 0);
}
static void gemm2(const fp16* a, const fp16* b, const float* bias,
                  fp16* Ch, int M, int N, int K, int ldc) {
    gemm_tc<2><<<dim3(N/128, M/128), 256, SMEM_DYN>>>(a, b, bias, Ch, M, N, K, ldc, 0);
}
static void gemm3(const fp16* a, const fp16* b, const float* bias,
                  fp16* Ch, int M, int N, int K, int ldc, int phi_lim) {
    gemm_tc<3><<<dim3(N/128, M/128), 256, SMEM_DYN>>>(a, b, bias, Ch, M, N, K, ldc, phi_lim);
}

// self-attention: one fused QKV GEMM (N=1536, phi on cols < 1024).
static void attention_self(const fp16* xh, const fp16* wh, const float* b, const Ptrs& P)
{
    gemm3(xh, wh, b, P.qkv, NTOK, 1536, DMODEL, 1536, 1024);
    kv_partial<<<dim3(32, SCH), 256>>>(P.qkv + 512, 1536, P.qkv + 1024, 1536, P.pkv, P.pks);
    kv_reduce<<<dim3(32, 4), 256>>>(P.pkv, P.pks, P.kv, P.ks);
    attn_out<<<dim3(32, 32), 256>>>(P.qkv, 1536, P.kv, P.ks, P.ath);
    gemm0(P.ath, wh + (size_t)3 * DMODEL * DMODEL, b + 3 * DMODEL, P.tmph, NTOK, DMODEL, DMODEL, DMODEL);
}

// cross-attention: Q GEMM + fused K|V GEMM (N=1024, phi on cols < 512).
static void attention_cross(const fp16* xqh, const fp16* xkh,
                            const fp16* wh, const float* b, const Ptrs& P)
{
    const size_t WS = (size_t)DMODEL * DMODEL;
    gemm2(xqh, wh, b, P.qkv, NTOK, DMODEL, DMODEL, 1536);
    gemm3(xkh, wh + 1 * WS, b + 1 * DMODEL, P.qkv + 512, NTOK, 1024, DMODEL, 1536, 512);

    kv_partial<<<dim3(32, SCH), 256>>>(P.qkv + 512, 1536, P.qkv + 1024, 1536, P.pkv, P.pks);
    kv_reduce<<<dim3(32, 4), 256>>>(P.pkv, P.pks, P.kv, P.ks);
    attn_out<<<dim3(32, 32), 256>>>(P.qkv, 1536, P.kv, P.ks, P.ath);
    gemm0(P.ath, wh + 3 * WS, b + 3 * DMODEL, P.tmph, NTOK, DMODEL, DMODEL, DMODEL);
}

extern "C" void kernel_launch(void* const* d_in, const int* in_sizes, int n_in,
                              void* d_out, int out_size)
{
    const float* x            = (const float*)d_in[0];
    const float* out_pos_emb  = (const float*)d_in[1];
    const float* pe_input     = (const float*)d_in[2];
    const float* emb_w        = (const float*)d_in[3];
    const float* emb_b        = (const float*)d_in[4];
    const float* enc_attn_w   = (const float*)d_in[5];
    const float* enc_attn_b   = (const float*)d_in[6];
    const float* enc_ln       = (const float*)d_in[7];
    const float* enc_ff_w1    = (const float*)d_in[8];
    const float* enc_ff_b1    = (const float*)d_in[9];
    const float* enc_ff_w2    = (const float*)d_in[10];
    const float* enc_ff_b2    = (const float*)d_in[11];
    const float* enc_final_ln = (const float*)d_in[12];
    const float* dec_self_w   = (const float*)d_in[13];
    const float* dec_self_b   = (const float*)d_in[14];
    const float* dec_cross_w  = (const float*)d_in[15];
    const float* dec_cross_b  = (const float*)d_in[16];
    const float* dec_ln       = (const float*)d_in[17];
    const float* dec_ff_w1    = (const float*)d_in[18];
    const float* dec_ff_b1    = (const float*)d_in[19];
    const float* dec_ff_w2    = (const float*)d_in[20];
    const float* dec_ff_b2    = (const float*)d_in[21];
    const float* dec_final_ln = (const float*)d_in[22];
    const float* pred_w       = (const float*)d_in[23];
    const float* pred_b       = (const float*)d_in[24];

    cudaFuncSetAttribute(gemm_tc<0>, cudaFuncAttributeMaxDynamicSharedMemorySize, SMEM_DYN);
    cudaFuncSetAttribute(gemm_tc<1>, cudaFuncAttributeMaxDynamicSharedMemorySize, SMEM_DYN);
    cudaFuncSetAttribute(gemm_tc<2>, cudaFuncAttributeMaxDynamicSharedMemorySize, SMEM_DYN);
    cudaFuncSetAttribute(gemm_tc<3>, cudaFuncAttributeMaxDynamicSharedMemorySize, SMEM_DYN);

    unsigned char* S = nullptr;
    cudaGetSymbolAddress((void**)&S, g_scratch);

    Ptrs P;
    P.tmph = (fp16*)(S + B_TMPH);
    P.qkv  = (fp16*)(S + B_QKV);
    P.pkv  = (float*)(S + B_PKV); P.pks = (float*)(S + B_PKS);
    P.kv   = (float*)(S + B_KVB); P.ks  = (float*)(S + B_KSB);
    P.hh   = (fp16*)(S + B_HH);   P.zh  = (fp16*)(S + B_ZH);
    P.oh   = (fp16*)(S + B_OH);   P.ath = (fp16*)(S + B_ATH);
    P.fh   = (fp16*)(S + B_FH);
    P.wha  = (fp16*)(S + B_WHA);
    P.whf1 = (fp16*)(S + B_WHF1);
    P.whf2 = (fp16*)(S + B_WHF2);

    // ---- transpose + fp16-round all weights ----
    transpose_w16<<<dim3(16, 16, 16), 256>>>(enc_attn_w,  P.wha,                     512, 512);
    transpose_w16<<<dim3(16, 16, 16), 256>>>(dec_self_w,  P.wha + (size_t)16*262144, 512, 512);
    transpose_w16<<<dim3(16, 16, 16), 256>>>(dec_cross_w, P.wha + (size_t)32*262144, 512, 512);
    transpose_w16<<<dim3(64, 16, 4),  256>>>(enc_ff_w1, P.whf1,                      512, 2048);
    transpose_w16<<<dim3(64, 16, 4),  256>>>(dec_ff_w1, P.whf1 + (size_t)4*1048576,  512, 2048);
    transpose_w16<<<dim3(16, 64, 4),  256>>>(enc_ff_w2, P.whf2,                      2048, 512);
    transpose_w16<<<dim3(16, 64, 4),  256>>>(dec_ff_w2, P.whf2 + (size_t)4*1048576,  2048, 512);

    const size_t WT4 = (size_t)4 * DMODEL * DMODEL;
    const size_t W1S = (size_t)DFF * DMODEL;
    const size_t W2S = (size_t)DMODEL * DFF;

    // ---- embed ----
    embed_kernel<<<(NTOK * 128) / 256, 256>>>(x, pe_input, emb_w, emb_b, P.hh);

    // ---- encoder ----
    for (int l = 0; l < 4; l++) {
        const float* ln = enc_ln + (size_t)l * 2 * 2 * DMODEL;
        attention_self(P.hh, P.wha + (size_t)l * WT4,
                       enc_attn_b + (size_t)l * 4 * DMODEL, P);
        ln_kernel<<<NTOK / 4, 256>>>(P.hh, P.tmph, ln, P.hh);
        gemm1(P.hh, P.whf1 + (size_t)l * W1S,
              enc_ff_b1 + (size_t)l * DFF, P.fh, NTOK, DFF, DMODEL, DFF);
        gemm0(P.fh, P.whf2 + (size_t)l * W2S,
              enc_ff_b2 + (size_t)l * DMODEL, P.tmph, NTOK, DMODEL, DFF, DMODEL);
        ln_kernel<<<NTOK / 4, 256>>>(P.hh, P.tmph, ln + 2 * DMODEL, P.hh);
    }
    ln_kernel<<<NTOK / 4, 256>>>(P.hh, nullptr, enc_final_ln, P.zh);

    // ---- decoder ----
    dec_init_kernel<<<(NTOK * 128) / 256, 256>>>(out_pos_emb, P.oh);
    for (int l = 0; l < 4; l++) {
        const float* ln = dec_ln + (size_t)l * 3 * 2 * DMODEL;
        attention_self(P.oh, P.wha + (size_t)(16 + l * 4) * DMODEL * DMODEL,
                       dec_self_b + (size_t)l * 4 * DMODEL, P);
        ln_kernel<<<NTOK / 4, 256>>>(P.oh, P.tmph, ln, P.oh);
        attention_cross(P.oh, P.zh,
                        P.wha + (size_t)(32 + l * 4) * DMODEL * DMODEL,
                        dec_cross_b + (size_t)l * 4 * DMODEL, P);
        ln_kernel<<<NTOK / 4, 256>>>(P.oh, P.tmph, ln + 2 * DMODEL, P.oh);
        gemm1(P.oh, P.whf1 + (size_t)(4 + l) * W1S,
              dec_ff_b1 + (size_t)l * DFF, P.fh, NTOK, DFF, DMODEL, DFF);
        gemm0(P.fh, P.whf2 + (size_t)(4 + l) * W2S,
              dec_ff_b2 + (size_t)l * DMODEL, P.tmph, NTOK, DMODEL, DFF, DMODEL);
        ln_kernel<<<NTOK / 4, 256>>>(P.oh, P.tmph, ln + 4 * DMODEL, P.oh);
    }
    ln_kernel<<<NTOK / 4, 256>>>(P.oh, nullptr, dec_final_ln, P.ath);

    // ---- prediction head ----
    pred_kernel<<<(NTOK * 32) / 256, 256>>>(P.ath, pred_w, pred_b, (float*)d_out);
}

// round 17
// speedup vs baseline: 2.1308x; 1.0289x over previous
#include <cuda_runtime.h>
#include <cuda_fp16.h>
#include <cstdint>
#include <cstddef>

// ---------------------------------------------------------------------------
// TRecTransformer: linear-attention encoder/decoder.
// GEMMs: plain fp16 mma.sync m16n8k16 (fp32 accum). fp16 glue trunk.
// Round 17: round-16 attn_out tensorization with the Q-tile loader fixed
// (4 iterations -- 1024 uint4, all 128 token rows initialized).
// ---------------------------------------------------------------------------

#define NTOK   16384
#define DMODEL 512
#define DFF    2048
#define LSEQ   4096
#define SCH    16

#define SZ ((size_t)NTOK * DMODEL)        // 8,388,608 elements

// ---- scratch layout (BYTE offsets) ----
#define B_TMPH  ((size_t)0)               // fp16 sublayer output [NTOK,512]
#define B_QKV   (B_TMPH + SZ*2)           // fp16 [NTOK,1536]: Q|K|V
#define B_PKV   (B_QKV + SZ*6)
#define B_PKS   (B_PKV + (size_t)SCH*32*4096*4)
#define B_KVH   (B_PKS + (size_t)SCH*32*64*4)   // fp16 hi [32][64][64]
#define B_KVL   (B_KVH + (size_t)32*4096*2)     // fp16 lo
#define B_KSB   (B_KVL + (size_t)32*4096*2)
#define B_HH    (B_KSB + (size_t)32*64*4) // fp16 trunk (encoder)
#define B_ZH    (B_HH  + SZ*2)
#define B_OH    (B_ZH  + SZ*2)            // fp16 trunk (decoder)
#define B_ATH   (B_OH  + SZ*2)
#define B_FH    (B_ATH + SZ*2)            // NTOK*DFF halves
#define B_WHA   (B_FH  + SZ*8)            // 48 x 512x512
#define B_WHF1  (B_WHA + (size_t)48*262144*2)
#define B_WHF2  (B_WHF1 + (size_t)8*1048576*2)
#define TOTAL_B (B_WHF2 + (size_t)8*1048576*2)

__device__ __align__(1024) unsigned char g_scratch[TOTAL_B];

typedef __half fp16;

// ---------------------------------------------------------------------------
// helpers
// ---------------------------------------------------------------------------
__device__ __forceinline__ uint32_t smem_u32(const void* p) {
    uint32_t a;
    asm("{ .reg .u64 t; cvta.to.shared.u64 t, %1; cvt.u32.u64 %0, t; }" : "=r"(a) : "l"(p));
    return a;
}
__device__ __forceinline__ void ldsm4(uint32_t* r, uint32_t addr) {
    asm volatile("ldmatrix.sync.aligned.m8n8.x4.shared.b16 {%0,%1,%2,%3}, [%4];"
        : "=r"(r[0]), "=r"(r[1]), "=r"(r[2]), "=r"(r[3]) : "r"(addr));
}
__device__ __forceinline__ void ldsm4t(uint32_t* r, uint32_t addr) {
    asm volatile("ldmatrix.sync.aligned.m8n8.x4.trans.shared.b16 {%0,%1,%2,%3}, [%4];"
        : "=r"(r[0]), "=r"(r[1]), "=r"(r[2]), "=r"(r[3]) : "r"(addr));
}
__device__ __forceinline__ void mma_f16(float* c, const uint32_t* a, const uint32_t* b) {
    asm volatile(
        "mma.sync.aligned.m16n8k16.row.col.f32.f16.f16.f32 "
        "{%0,%1,%2,%3}, {%4,%5,%6,%7}, {%8,%9}, {%0,%1,%2,%3};"
        : "+f"(c[0]), "+f"(c[1]), "+f"(c[2]), "+f"(c[3])
        : "r"(a[0]), "r"(a[1]), "r"(a[2]), "r"(a[3]), "r"(b[0]), "r"(b[1]));
}
__device__ __forceinline__ void cp16(uint32_t d, const void* s) {
    asm volatile("cp.async.cg.shared.global [%0], [%1], 16;" :: "r"(d), "l"(s));
}
__device__ __forceinline__ void cp_commit() { asm volatile("cp.async.commit_group;" ::: "memory"); }
__device__ __forceinline__ void cp_wait1()  { asm volatile("cp.async.wait_group 1;" ::: "memory"); }
__device__ __forceinline__ void cp_wait0()  { asm volatile("cp.async.wait_group 0;" ::: "memory"); }

// ---------------------------------------------------------------------------
// GEMM: Ch[M,N](ldc) = act(A[M,K] @ W[N,K]^T + bias), fp16 out.
// ACT: 0 none, 1 relu, 2 phi=elu+1, 3 phi iff col < phi_lim (uniform/warp).
// ---------------------------------------------------------------------------
#define ROWB 80
#define MATB 10240
#define STGB 20480
#define SMEM_DYN (3 * STGB)

template<int ACT>
__global__ __launch_bounds__(256) void gemm_tc(
    const fp16* __restrict__ A, const fp16* __restrict__ B,
    const float* __restrict__ bias, fp16* __restrict__ Ch,
    int M, int N, int K, int ldc, int phi_lim)
{
    extern __shared__ char smc[];
    const uint32_t smB = smem_u32(smc);

    const int tid = threadIdx.x, lane = tid & 31, wid = tid >> 5;
    const int row0 = blockIdx.y * 128, col0 = blockIdx.x * 128;
    const int wm = wid & 1, wn = wid >> 1;

    float acc[4][4][4];
    #pragma unroll
    for (int i = 0; i < 4; i++)
        #pragma unroll
        for (int j = 0; j < 4; j++)
            #pragma unroll
            for (int e = 0; e < 4; e++) acc[i][j][e] = 0.f;

    const uint32_t aoff = (uint32_t)((wm * 64 + (lane & 7) + ((lane >> 3) & 1) * 8) * ROWB
                                     + (lane >> 4) * 16);
    const uint32_t boff = (uint32_t)((wn * 32 + (lane >> 4) * 8 + (lane & 7)) * ROWB
                                     + ((lane >> 3) & 1) * 16);

    const int NC = K / 32;
    const int pr = tid >> 2;
    const int pb = (tid & 3) * 16;

    auto loadst = [&](int c, int s) {
        const int k0 = c * 32;
        const uint32_t st = smB + (uint32_t)s * STGB;
        #pragma unroll
        for (int m = 0; m < 2; m++) {
            const fp16* g = (m == 0) ? A : B;
            const int rb = (m == 0) ? row0 : col0;
            #pragma unroll
            for (int hf = 0; hf < 2; hf++) {
                const int r = hf * 64 + pr;
                cp16(st + m * MATB + r * ROWB + pb,
                     (const char*)(g + (size_t)(rb + r) * K + k0) + pb);
            }
        }
    };

    auto compute = [&](int s) {
        const uint32_t base = smB + (uint32_t)s * STGB;
        #pragma unroll
        for (int ks = 0; ks < 2; ks++) {
            uint32_t ar[4][4], br[4][2];
            #pragma unroll
            for (int mi = 0; mi < 4; mi++)
                ldsm4(ar[mi], base + aoff + mi * 1280 + ks * 32);
            #pragma unroll
            for (int j = 0; j < 2; j++) {
                uint32_t t[4];
                ldsm4(t, base + MATB + boff + j * 1280 + ks * 32);
                br[2 * j][0] = t[0]; br[2 * j][1] = t[1];
                br[2 * j + 1][0] = t[2]; br[2 * j + 1][1] = t[3];
            }
            #pragma unroll
            for (int mi = 0; mi < 4; mi++)
                #pragma unroll
                for (int ni = 0; ni < 4; ni++) mma_f16(acc[mi][ni], ar[mi], br[ni]);
        }
    };

    loadst(0, 0); cp_commit();
    loadst(1, 1); cp_commit();
    for (int c = 0; c < NC; c++) {
        if (c + 1 < NC) cp_wait1(); else cp_wait0();
        __syncthreads();
        compute(c % 3);
        if (c + 2 < NC) { loadst(c + 2, (c + 2) % 3); cp_commit(); }
    }

    const int gm0 = row0 + wm * 64;
    const int gn0 = col0 + wn * 32;
    #pragma unroll
    for (int ni = 0; ni < 4; ni++) {
        const int cn = gn0 + ni * 8 + (lane & 3) * 2;
        const float b0 = bias[cn], b1 = bias[cn + 1];
        const bool dophi = (ACT == 2) || (ACT == 3 && cn < phi_lim);
        #pragma unroll
        for (int mi = 0; mi < 4; mi++) {
            const int rm = gm0 + mi * 16 + (lane >> 2);
            float t0 = acc[mi][ni][0] + b0;
            float t1 = acc[mi][ni][1] + b1;
            float t2 = acc[mi][ni][2] + b0;
            float t3 = acc[mi][ni][3] + b1;
            if (ACT == 1) {
                t0 = fmaxf(t0, 0.f); t1 = fmaxf(t1, 0.f);
                t2 = fmaxf(t2, 0.f); t3 = fmaxf(t3, 0.f);
            }
            if (ACT == 2 || ACT == 3) {
                if (dophi) {
                    t0 = t0 > 0.f ? t0 + 1.f : __expf(t0);
                    t1 = t1 > 0.f ? t1 + 1.f : __expf(t1);
                    t2 = t2 > 0.f ? t2 + 1.f : __expf(t2);
                    t3 = t3 > 0.f ? t3 + 1.f : __expf(t3);
                }
            }
            __half2 hp;
            hp.x = __float2half_rn(t0); hp.y = __float2half_rn(t1);
            *(__half2*)&Ch[(size_t)rm * ldc + cn] = hp;
            hp.x = __float2half_rn(t2); hp.y = __float2half_rn(t3);
            *(__half2*)&Ch[(size_t)(rm + 8) * ldc + cn] = hp;
        }
    }
}

// ---------------------------------------------------------------------------
// fused weight transpose + fp16 round: W[K,N] fp32 -> Wh [N,K] fp16
// ---------------------------------------------------------------------------
__global__ __launch_bounds__(256) void transpose_w16(
    const float* __restrict__ W, fp16* __restrict__ Wh, int K, int N)
{
    __shared__ float t[32][33];
    const size_t mo = (size_t)blockIdx.z * K * N;
    const float* Wm = W + mo;
    const int n0 = blockIdx.x * 32, k0 = blockIdx.y * 32;
    const int tx = threadIdx.x & 31, ty = threadIdx.x >> 5;
    #pragma unroll
    for (int i = 0; i < 32; i += 8)
        t[ty + i][tx] = Wm[(size_t)(k0 + ty + i) * N + n0 + tx];
    __syncthreads();
    #pragma unroll
    for (int i = 0; i < 32; i += 8)
        Wh[mo + (size_t)(n0 + ty + i) * K + k0 + tx] = __float2half_rn(t[tx][ty + i]);
}

// ---------------------------------------------------------------------------
// kv partial (tensor-core): unchanged from round 15 (verified mappings).
// ---------------------------------------------------------------------------
__global__ __launch_bounds__(256) void kv_partial(
    const fp16* __restrict__ Kt, int ldk,
    const fp16* __restrict__ Vt, int ldv,
    float* __restrict__ pkv, float* __restrict__ pks)
{
    const int bh = blockIdx.x, ch = blockIdx.y;
    const int b = bh >> 3, h = bh & 7;
    const int tid = threadIdx.x, lane = tid & 31, wid = tid >> 5;
    const int wd = wid & 3, wm = wid >> 2;

    __shared__ fp16 Ks[32][64];
    __shared__ fp16 Vs[32][64];
    __shared__ float ksm[8][64];

    const uint32_t kb = smem_u32(Ks), vb = smem_u32(Vs);

    float acc[4][4];
    #pragma unroll
    for (int i = 0; i < 4; i++)
        #pragma unroll
        for (int j = 0; j < 4; j++) acc[i][j] = 0.f;
    float ks0 = 0.f, ks1 = 0.f;

    const uint32_t arow = (uint32_t)((lane & 7) + ((lane >> 4) & 1) * 8);
    const uint32_t aadd = arow * 128 + (uint32_t)wd * 32 + ((lane >> 3) & 1) * 16;
    const uint32_t brow = (uint32_t)((lane & 7) + ((lane >> 3) & 1) * 8);
    const uint32_t badd = brow * 128 + (uint32_t)wm * 64 + ((lane >> 4) & 1) * 16;

    const int lrow = tid >> 3, lcol = (tid & 7) * 8;
    const int s0 = ch * (LSEQ / SCH);

    for (int st = 0; st < 8; st++) {
        const size_t row = (size_t)(b * LSEQ + s0 + st * 32 + lrow);
        *(uint4*)&Ks[lrow][lcol] = *(const uint4*)(Kt + row * ldk + h * 64 + lcol);
        *(uint4*)&Vs[lrow][lcol] = *(const uint4*)(Vt + row * ldv + h * 64 + lcol);
        __syncthreads();

        #pragma unroll
        for (int r = 0; r < 4; r++) {
            const float2 kf = __half22float2(*(const __half2*)&Ks[wid * 4 + r][lane * 2]);
            ks0 += kf.x; ks1 += kf.y;
        }

        #pragma unroll
        for (int ks2 = 0; ks2 < 2; ks2++) {
            const uint32_t rb = (uint32_t)(ks2 * 16) * 128;
            uint32_t ah[4], t0[4], t1[4];
            ldsm4t(ah, kb + rb + aadd);
            ldsm4t(t0, vb + rb + badd);
            ldsm4t(t1, vb + rb + badd + 32);
            uint32_t br0[2] = { t0[0], t0[1] };
            uint32_t br1[2] = { t0[2], t0[3] };
            uint32_t br2[2] = { t1[0], t1[1] };
            uint32_t br3[2] = { t1[2], t1[3] };
            mma_f16(acc[0], ah, br0);
            mma_f16(acc[1], ah, br1);
            mma_f16(acc[2], ah, br2);
            mma_f16(acc[3], ah, br3);
        }
        __syncthreads();
    }

    float* o = pkv + ((size_t)ch * 32 + bh) * 4096;
    const int d0 = wd * 16 + (lane >> 2);
    #pragma unroll
    for (int ni = 0; ni < 4; ni++) {
        const int m = wm * 32 + ni * 8 + (lane & 3) * 2;
        float2 v0; v0.x = acc[ni][0]; v0.y = acc[ni][1];
        float2 v1; v1.x = acc[ni][2]; v1.y = acc[ni][3];
        *(float2*)&o[(size_t)d0 * 64 + m]       = v0;
        *(float2*)&o[(size_t)(d0 + 8) * 64 + m] = v1;
    }

    ksm[wid][lane * 2]     = ks0;
    ksm[wid][lane * 2 + 1] = ks1;
    __syncthreads();
    if (tid < 64) {
        float s = 0.f;
        #pragma unroll
        for (int w = 0; w < 8; w++) s += ksm[w][tid];
        pks[((size_t)ch * 32 + bh) * 64 + tid] = s;
    }
}

// kv_reduce: sum partials; emit kv as fp16 hi/lo pair + fp32 ksum.
__global__ __launch_bounds__(256) void kv_reduce(
    const float* __restrict__ pkv, const float* __restrict__ pks,
    fp16* __restrict__ kvh, fp16* __restrict__ kvl, float* __restrict__ ks)
{
    const int bh = blockIdx.x, tid = threadIdx.x;
    const int e4 = blockIdx.y * 256 + tid;
    float4 s; s.x = s.y = s.z = s.w = 0.f;
    #pragma unroll
    for (int c = 0; c < SCH; c++) {
        const float4 v = ((const float4*)pkv)[((size_t)c * 32 + bh) * 1024 + e4];
        s.x += v.x; s.y += v.y; s.z += v.z; s.w += v.w;
    }
    fp16 hx = __float2half_rn(s.x), hy = __float2half_rn(s.y);
    fp16 hz = __float2half_rn(s.z), hw = __float2half_rn(s.w);
    __half2 h0, h1, l0, l1;
    h0.x = hx; h0.y = hy; h1.x = hz; h1.y = hw;
    l0.x = __float2half_rn(s.x - __half2float(hx));
    l0.y = __float2half_rn(s.y - __half2float(hy));
    l1.x = __float2half_rn(s.z - __half2float(hz));
    l1.y = __float2half_rn(s.w - __half2float(hw));
    uint2 ph, pl;
    ph.x = *(uint32_t*)&h0; ph.y = *(uint32_t*)&h1;
    pl.x = *(uint32_t*)&l0; pl.y = *(uint32_t*)&l1;
    ((uint2*)kvh)[(size_t)bh * 1024 + e4] = ph;
    ((uint2*)kvl)[(size_t)bh * 1024 + e4] = pl;
    if (blockIdx.y == 0 && tid < 64) {
        float t = 0.f;
        #pragma unroll
        for (int c = 0; c < SCH; c++) t += pks[((size_t)c * 32 + bh) * 64 + tid];
        ks[bh * 64 + tid] = t;
    }
}

// ---------------------------------------------------------------------------
// attn out (tensor-core): O = (Q @ kv) / (Q . ksum + eps), kv = kvh + kvl.
// grid (32 bh, 32); 128 tokens per CTA; 8 warps x 16 tokens.
// ---------------------------------------------------------------------------
__global__ __launch_bounds__(256) void attn_out(
    const fp16* __restrict__ Q, int ldq,
    const fp16* __restrict__ kvh, const fp16* __restrict__ kvl,
    const float* __restrict__ ksum, fp16* __restrict__ Oh)
{
    const int bh = blockIdx.x, b = bh >> 3, h = bh & 7;
    const int tid = threadIdx.x, lane = tid & 31, w = tid >> 5;

    __shared__ fp16 qs[128][64];
    __shared__ fp16 kh[64][64];
    __shared__ fp16 kl[64][64];
    __shared__ float kss[64];
    __shared__ float zs[128];

    // load kv hi/lo (512 uint4 each) and ksum
    #pragma unroll
    for (int i = 0; i < 2; i++) {
        ((uint4*)kh)[tid + i * 256] = ((const uint4*)(kvh + (size_t)bh * 4096))[tid + i * 256];
        ((uint4*)kl)[tid + i * 256] = ((const uint4*)(kvl + (size_t)bh * 4096))[tid + i * 256];
    }
    if (tid < 64) kss[tid] = ksum[bh * 64 + tid];

    // load Q tile: 128 tokens x 64 halves = 1024 uint4 (4 iterations!)
    const int tok0 = blockIdx.y * 128;
    #pragma unroll
    for (int i = 0; i < 4; i++) {
        const int idx = tid + i * 256;
        const int row = idx >> 3, col = (idx & 7) * 8;
        *(uint4*)&qs[row][col] =
            *(const uint4*)(Q + (size_t)(b * LSEQ + tok0 + row) * ldq + h * 64 + col);
    }
    __syncthreads();

    // z denominators: 2 threads per token
    {
        const int t = tid >> 1, hf = tid & 1;
        float s = 0.f;
        #pragma unroll
        for (int j = 0; j < 16; j++) {
            const float2 qf = __half22float2(*(const __half2*)&qs[t][hf * 32 + j * 2]);
            s = fmaf(qf.x, kss[hf * 32 + j * 2],     s);
            s = fmaf(qf.y, kss[hf * 32 + j * 2 + 1], s);
        }
        s += __shfl_xor_sync(0xffffffffu, s, 1);
        if (hf == 0) zs[t] = 1.f / (s + 1e-6f);
    }
    __syncthreads();

    const uint32_t qb = smem_u32(qs), khb = smem_u32(kh), klb = smem_u32(kl);

    float acc[8][4];
    #pragma unroll
    for (int i = 0; i < 8; i++)
        #pragma unroll
        for (int e = 0; e < 4; e++) acc[i][e] = 0.f;

    const uint32_t aadd = (uint32_t)(w * 16 + (lane & 7) + ((lane >> 3) & 1) * 8) * 128
                          + (lane >> 4) * 16;
    const uint32_t badd = (uint32_t)((lane & 7) + ((lane >> 3) & 1) * 8) * 128
                          + ((lane >> 4) & 1) * 16;

    #pragma unroll
    for (int ks2 = 0; ks2 < 4; ks2++) {
        uint32_t a[4];
        ldsm4(a, qb + aadd + ks2 * 32);
        const uint32_t rb = (uint32_t)(ks2 * 16) * 128;
        #pragma unroll
        for (int part = 0; part < 2; part++) {
            const uint32_t base = (part == 0 ? khb : klb) + rb;
            #pragma unroll
            for (int nb = 0; nb < 4; nb++) {
                uint32_t t[4];
                ldsm4t(t, base + badd + nb * 32);
                uint32_t br0[2] = { t[0], t[1] };
                uint32_t br1[2] = { t[2], t[3] };
                mma_f16(acc[nb * 2],     a, br0);
                mma_f16(acc[nb * 2 + 1], a, br1);
            }
        }
    }

    // epilogue
    const int r = lane >> 2, c2 = (lane & 3) * 2;
    const int lt0 = w * 16 + r;
    const float z0 = zs[lt0], z1 = zs[lt0 + 8];
    #pragma unroll
    for (int ni = 0; ni < 8; ni++) {
        const int m = ni * 8 + c2;
        __half2 hp;
        hp.x = __float2half_rn(acc[ni][0] * z0);
        hp.y = __float2half_rn(acc[ni][1] * z0);
        *(__half2*)&Oh[(size_t)(b * LSEQ + tok0 + lt0) * DMODEL + h * 64 + m] = hp;
        hp.x = __float2half_rn(acc[ni][2] * z1);
        hp.y = __float2half_rn(acc[ni][3] * z1);
        *(__half2*)&Oh[(size_t)(b * LSEQ + tok0 + lt0 + 8) * DMODEL + h * 64 + m] = hp;
    }
}

// ---------------------------------------------------------------------------
// LayerNorm (fp16 in/out, fp32 compute): 4 tokens per 256-thread CTA.
// ---------------------------------------------------------------------------
__global__ __launch_bounds__(256) void ln_kernel(
    const fp16* __restrict__ X, const fp16* __restrict__ R,
    const float* __restrict__ gb, fp16* __restrict__ Yh)
{
    const int tid = threadIdx.x;
    const int tok = blockIdx.x * 4 + (tid >> 6);
    const int u = tid & 63;
    const size_t base8 = (size_t)tok * 64;

    const uint4 xv = ((const uint4*)X)[base8 + u];
    float v[8];
    {
        const __half2* xh = (const __half2*)&xv;
        #pragma unroll
        for (int i = 0; i < 4; i++) {
            const float2 f = __half22float2(xh[i]);
            v[2 * i] = f.x; v[2 * i + 1] = f.y;
        }
    }
    if (R) {
        const uint4 rv = ((const uint4*)R)[base8 + u];
        const __half2* rh = (const __half2*)&rv;
        #pragma unroll
        for (int i = 0; i < 4; i++) {
            const float2 f = __half22float2(rh[i]);
            v[2 * i] += f.x; v[2 * i + 1] += f.y;
        }
    }
    float s = 0.f;
    #pragma unroll
    for (int i = 0; i < 8; i++) s += v[i];

    __shared__ float redS[4][2], redQ[4][2];
    const int tk = tid >> 6, w2 = (tid >> 5) & 1;
    #pragma unroll
    for (int o = 16; o > 0; o >>= 1) s += __shfl_xor_sync(0xffffffffu, s, o);
    if ((tid & 31) == 0) redS[tk][w2] = s;
    __syncthreads();
    const float mu = (redS[tk][0] + redS[tk][1]) * (1.f / DMODEL);

    float qq = 0.f;
    #pragma unroll
    for (int i = 0; i < 8; i++) { v[i] -= mu; qq += v[i] * v[i]; }
    #pragma unroll
    for (int o = 16; o > 0; o >>= 1) qq += __shfl_xor_sync(0xffffffffu, qq, o);
    if ((tid & 31) == 0) redQ[tk][w2] = qq;
    __syncthreads();
    const float var = (redQ[tk][0] + redQ[tk][1]) * (1.f / DMODEL);
    const float rstd = rsqrtf(var + 1e-5f);

    const float4 g0 = ((const float4*)gb)[u * 2];
    const float4 g1 = ((const float4*)gb)[u * 2 + 1];
    const float4 b0 = ((const float4*)(gb + DMODEL))[u * 2];
    const float4 b1 = ((const float4*)(gb + DMODEL))[u * 2 + 1];
    float o0 = v[0] * rstd * g0.x + b0.x;
    float o1 = v[1] * rstd * g0.y + b0.y;
    float o2 = v[2] * rstd * g0.z + b0.z;
    float o3 = v[3] * rstd * g0.w + b0.w;
    float o4 = v[4] * rstd * g1.x + b1.x;
    float o5 = v[5] * rstd * g1.y + b1.y;
    float o6 = v[6] * rstd * g1.z + b1.z;
    float o7 = v[7] * rstd * g1.w + b1.w;

    uint4 out;
    __half2 hp;
    hp.x = __float2half_rn(o0); hp.y = __float2half_rn(o1); out.x = *(uint32_t*)&hp;
    hp.x = __float2half_rn(o2); hp.y = __float2half_rn(o3); out.y = *(uint32_t*)&hp;
    hp.x = __float2half_rn(o4); hp.y = __float2half_rn(o5); out.z = *(uint32_t*)&hp;
    hp.x = __float2half_rn(o6); hp.y = __float2half_rn(o7); out.w = *(uint32_t*)&hp;
    ((uint4*)Yh)[base8 + u] = out;
}

__global__ void embed_kernel(
    const float* __restrict__ x, const float* __restrict__ pe,
    const float* __restrict__ ew, const float* __restrict__ eb,
    fp16* __restrict__ hh)
{
    const size_t i4 = (size_t)blockIdx.x * blockDim.x + threadIdx.x;
    const int tok = (int)(i4 >> 7);
    const int j   = (int)(i4 & 127) * 4;
    const int l   = tok & (LSEQ - 1);
    float4 v;
    if (j < 256) {
        const float x0 = x[(size_t)tok * 2], x1 = x[(size_t)tok * 2 + 1];
        const float4 w0 = *(const float4*)(ew + j);
        const float4 w1 = *(const float4*)(ew + 256 + j);
        const float4 b  = *(const float4*)(eb + j);
        v.x = x0 * w0.x + x1 * w1.x + b.x;
        v.y = x0 * w0.y + x1 * w1.y + b.y;
        v.z = x0 * w0.z + x1 * w1.z + b.z;
        v.w = x0 * w0.w + x1 * w1.w + b.w;
    } else {
        v = *(const float4*)(pe + (size_t)l * 256 + (j - 256));
    }
    __half2 h0, h1;
    h0.x = __float2half_rn(v.x); h0.y = __float2half_rn(v.y);
    h1.x = __float2half_rn(v.z); h1.y = __float2half_rn(v.w);
    uint2 pk; pk.x = *(uint32_t*)&h0; pk.y = *(uint32_t*)&h1;
    ((uint2*)hh)[i4] = pk;
}

__global__ void dec_init_kernel(const float* __restrict__ ope, fp16* __restrict__ oh)
{
    const size_t i4 = (size_t)blockIdx.x * blockDim.x + threadIdx.x;
    const size_t tok = i4 >> 7;
    const float4 v = ((const float4*)ope)[((tok & (LSEQ - 1)) << 7) | (i4 & 127)];
    __half2 h0, h1;
    h0.x = __float2half_rn(v.x); h0.y = __float2half_rn(v.y);
    h1.x = __float2half_rn(v.z); h1.y = __float2half_rn(v.w);
    uint2 pk; pk.x = *(uint32_t*)&h0; pk.y = *(uint32_t*)&h1;
    ((uint2*)oh)[i4] = pk;
}

__global__ void pred_kernel(
    const fp16* __restrict__ Xh, const float* __restrict__ pw,
    const float* __restrict__ pb, float* __restrict__ out)
{
    const int gw = (int)(((size_t)blockIdx.x * blockDim.x + threadIdx.x) >> 5);
    const int lane = threadIdx.x & 31;
    if (gw >= NTOK) return;
    const fp16* xr = Xh + (size_t)gw * DMODEL;
    float a0 = 0.f, a1 = 0.f;
    #pragma unroll 4
    for (int j = lane; j < DMODEL; j += 32) {
        const float v = __half2float(xr[j]);
        a0 = fmaf(v, pw[2 * j],     a0);
        a1 = fmaf(v, pw[2 * j + 1], a1);
    }
    #pragma unroll
    for (int o = 16; o > 0; o >>= 1) {
        a0 += __shfl_xor_sync(0xffffffffu, a0, o);
        a1 += __shfl_xor_sync(0xffffffffu, a1, o);
    }
    if (lane == 0) { out[2 * gw] = a0 + pb[0]; out[2 * gw + 1] = a1 + pb[1]; }
}

// ---------------------------------------------------------------------------
// Host orchestration
// ---------------------------------------------------------------------------
struct Ptrs {
    float *pkv, *pks, *ks;
    fp16 *kvh, *kvl;
    fp16 *tmph, *qkv;
    fp16 *hh, *zh, *oh, *ath, *fh;
    fp16 *wha, *whf1, *whf2;
};

static void gemm0(const fp16* a, const fp16* b, const float* bias,
                  fp16* Ch, int M, int N, int K, int ldc) {
    gemm_tc<0><<<dim3(N/128, M/128), 256, SMEM_DYN>>>(a, b, bias, Ch, M, N, K, ldc, 0);
}
static void gemm1(const fp16* a, const fp16* b, const float* bias,
                  fp16* Ch, int M, int N, int K, int ldc) {
    gemm_tc<1><<<dim3(N/128, M/128), 256, SMEM_DYN>>>(a, b, bias, Ch, M, N, K, ldc, 0);
}
static void gemm2(const fp16* a, const fp16* b, const float* bias,
                  fp16* Ch, int M, int N, int K, int ldc) {
    gemm_tc<2><<<dim3(N/128, M/128), 256, SMEM_DYN>>>(a, b, bias, Ch, M, N, K, ldc, 0);
}
static void gemm3(const fp16* a, const fp16* b, const float* bias,
                  fp16* Ch, int M, int N, int K, int ldc, int phi_lim) {
    gemm_tc<3><<<dim3(N/128, M/128), 256, SMEM_DYN>>>(a, b, bias, Ch, M, N, K, ldc, phi_lim);
}

static void attn_chain(const Ptrs& P) {
    kv_partial<<<dim3(32, SCH), 256>>>(P.qkv + 512, 1536, P.qkv + 1024, 1536, P.pkv, P.pks);
    kv_reduce<<<dim3(32, 4), 256>>>(P.pkv, P.pks, P.kvh, P.kvl, P.ks);
    attn_out<<<dim3(32, 32), 256>>>(P.qkv, 1536, P.kvh, P.kvl, P.ks, P.ath);
}

static void attention_self(const fp16* xh, const fp16* wh, const float* b, const Ptrs& P)
{
    gemm3(xh, wh, b, P.qkv, NTOK, 1536, DMODEL, 1536, 1024);
    attn_chain(P);
    gemm0(P.ath, wh + (size_t)3 * DMODEL * DMODEL, b + 3 * DMODEL, P.tmph, NTOK, DMODEL, DMODEL, DMODEL);
}

static void attention_cross(const fp16* xqh, const fp16* xkh,
                            const fp16* wh, const float* b, const Ptrs& P)
{
    const size_t WS = (size_t)DMODEL * DMODEL;
    gemm2(xqh, wh, b, P.qkv, NTOK, DMODEL, DMODEL, 1536);
    gemm3(xkh, wh + 1 * WS, b + 1 * DMODEL, P.qkv + 512, NTOK, 1024, DMODEL, 1536, 512);
    attn_chain(P);
    gemm0(P.ath, wh + 3 * WS, b + 3 * DMODEL, P.tmph, NTOK, DMODEL, DMODEL, DMODEL);
}

extern "C" void kernel_launch(void* const* d_in, const int* in_sizes, int n_in,
                              void* d_out, int out_size)
{
    const float* x            = (const float*)d_in[0];
    const float* out_pos_emb  = (const float*)d_in[1];
    const float* pe_input     = (const float*)d_in[2];
    const float* emb_w        = (const float*)d_in[3];
    const float* emb_b        = (const float*)d_in[4];
    const float* enc_attn_w   = (const float*)d_in[5];
    const float* enc_attn_b   = (const float*)d_in[6];
    const float* enc_ln       = (const float*)d_in[7];
    const float* enc_ff_w1    = (const float*)d_in[8];
    const float* enc_ff_b1    = (const float*)d_in[9];
    const float* enc_ff_w2    = (const float*)d_in[10];
    const float* enc_ff_b2    = (const float*)d_in[11];
    const float* enc_final_ln = (const float*)d_in[12];
    const float* dec_self_w   = (const float*)d_in[13];
    const float* dec_self_b   = (const float*)d_in[14];
    const float* dec_cross_w  = (const float*)d_in[15];
    const float* dec_cross_b  = (const float*)d_in[16];
    const float* dec_ln       = (const float*)d_in[17];
    const float* dec_ff_w1    = (const float*)d_in[18];
    const float* dec_ff_b1    = (const float*)d_in[19];
    const float* dec_ff_w2    = (const float*)d_in[20];
    const float* dec_ff_b2    = (const float*)d_in[21];
    const float* dec_final_ln = (const float*)d_in[22];
    const float* pred_w       = (const float*)d_in[23];
    const float* pred_b       = (const float*)d_in[24];

    cudaFuncSetAttribute(gemm_tc<0>, cudaFuncAttributeMaxDynamicSharedMemorySize, SMEM_DYN);
    cudaFuncSetAttribute(gemm_tc<1>, cudaFuncAttributeMaxDynamicSharedMemorySize, SMEM_DYN);
    cudaFuncSetAttribute(gemm_tc<2>, cudaFuncAttributeMaxDynamicSharedMemorySize, SMEM_DYN);
    cudaFuncSetAttribute(gemm_tc<3>, cudaFuncAttributeMaxDynamicSharedMemorySize, SMEM_DYN);

    unsigned char* S = nullptr;
    cudaGetSymbolAddress((void**)&S, g_scratch);

    Ptrs P;
    P.tmph = (fp16*)(S + B_TMPH);
    P.qkv  = (fp16*)(S + B_QKV);
    P.pkv  = (float*)(S + B_PKV); P.pks = (float*)(S + B_PKS);
    P.kvh  = (fp16*)(S + B_KVH);  P.kvl = (fp16*)(S + B_KVL);
    P.ks   = (float*)(S + B_KSB);
    P.hh   = (fp16*)(S + B_HH);   P.zh  = (fp16*)(S + B_ZH);
    P.oh   = (fp16*)(S + B_OH);   P.ath = (fp16*)(S + B_ATH);
    P.fh   = (fp16*)(S + B_FH);
    P.wha  = (fp16*)(S + B_WHA);
    P.whf1 = (fp16*)(S + B_WHF1);
    P.whf2 = (fp16*)(S + B_WHF2);

    // ---- transpose + fp16-round all weights ----
    transpose_w16<<<dim3(16, 16, 16), 256>>>(enc_attn_w,  P.wha,                     512, 512);
    transpose_w16<<<dim3(16, 16, 16), 256>>>(dec_self_w,  P.wha + (size_t)16*262144, 512, 512);
    transpose_w16<<<dim3(16, 16, 16), 256>>>(dec_cross_w, P.wha + (size_t)32*262144, 512, 512);
    transpose_w16<<<dim3(64, 16, 4),  256>>>(enc_ff_w1, P.whf1,                      512, 2048);
    transpose_w16<<<dim3(64, 16, 4),  256>>>(dec_ff_w1, P.whf1 + (size_t)4*1048576,  512, 2048);
    transpose_w16<<<dim3(16, 64, 4),  256>>>(enc_ff_w2, P.whf2,                      2048, 512);
    transpose_w16<<<dim3(16, 64, 4),  256>>>(dec_ff_w2, P.whf2 + (size_t)4*1048576,  2048, 512);

    const size_t WT4 = (size_t)4 * DMODEL * DMODEL;
    const size_t W1S = (size_t)DFF * DMODEL;
    const size_t W2S = (size_t)DMODEL * DFF;

    // ---- embed ----
    embed_kernel<<<(NTOK * 128) / 256, 256>>>(x, pe_input, emb_w, emb_b, P.hh);

    // ---- encoder ----
    for (int l = 0; l < 4; l++) {
        const float* ln = enc_ln + (size_t)l * 2 * 2 * DMODEL;
        attention_self(P.hh, P.wha + (size_t)l * WT4,
                       enc_attn_b + (size_t)l * 4 * DMODEL, P);
        ln_kernel<<<NTOK / 4, 256>>>(P.hh, P.tmph, ln, P.hh);
        gemm1(P.hh, P.whf1 + (size_t)l * W1S,
              enc_ff_b1 + (size_t)l * DFF, P.fh, NTOK, DFF, DMODEL, DFF);
        gemm0(P.fh, P.whf2 + (size_t)l * W2S,
              enc_ff_b2 + (size_t)l * DMODEL, P.tmph, NTOK, DMODEL, DFF, DMODEL);
        ln_kernel<<<NTOK / 4, 256>>>(P.hh, P.tmph, ln + 2 * DMODEL, P.hh);
    }
    ln_kernel<<<NTOK / 4, 256>>>(P.hh, nullptr, enc_final_ln, P.zh);

    // ---- decoder ----
    dec_init_kernel<<<(NTOK * 128) / 256, 256>>>(out_pos_emb, P.oh);
    for (int l = 0; l < 4; l++) {
        const float* ln = dec_ln + (size_t)l * 3 * 2 * DMODEL;
        attention_self(P.oh, P.wha + (size_t)(16 + l * 4) * DMODEL * DMODEL,
                       dec_self_b + (size_t)l * 4 * DMODEL, P);
        ln_kernel<<<NTOK / 4, 256>>>(P.oh, P.tmph, ln, P.oh);
        attention_cross(P.oh, P.zh,
                        P.wha + (size_t)(32 + l * 4) * DMODEL * DMODEL,
                        dec_cross_b + (size_t)l * 4 * DMODEL, P);
        ln_kernel<<<NTOK / 4, 256>>>(P.oh, P.tmph, ln + 2 * DMODEL, P.oh);
        gemm1(P.oh, P.whf1 + (size_t)(4 + l) * W1S,
              dec_ff_b1 + (size_t)l * DFF, P.fh, NTOK, DFF, DMODEL, DFF);
        gemm0(P.fh, P.whf2 + (size_t)(4 + l) * W2S,
              dec_ff_b2 + (size_t)l * DMODEL, P.tmph, NTOK, DMODEL, DFF, DMODEL);
        ln_kernel<<<NTOK / 4, 256>>>(P.oh, P.tmph, ln + 4 * DMODEL, P.oh);
    }
    ln_kernel<<<NTOK / 4, 256>>>(P.oh, nullptr, dec_final_ln, P.ath);

    // ---- prediction head ----
    pred_kernel<<<(NTOK * 32) / 256, 256>>>(P.ath, pred_w, pred_b, (float*)d_out);
}